// round 6
// baseline (speedup 1.0000x reference)
#include <cuda_runtime.h>
#include <cstdint>
#include <math.h>

#define Bdim 4
#define Cdim 256
#define Ndim 2304      // 48*48
#define PLANE (Bdim*Cdim*Ndim)
#define CN   (Cdim*Ndim)
#define NN   ((size_t)Ndim*Ndim)

#define BM 128
#define BN 128
#define BK 16
#define BMP 136        // padded smem stride (narrow kernels)
#define BNP 264        // padded smem stride for 256-wide B tiles

// ---- scratch ----
__device__ float g_P[9][PLANE];                      // Q0..2, K0..2, V0..2
__device__ float g_S3[(size_t)3 * Bdim * NN];        // scores for all 3 attends
__device__ float g_W[3][PLANE];                      // attention outputs
__device__ float g_F3[3][PLANE];                     // gated outputs

// ---- tf32 helpers ----
__device__ __forceinline__ float f2tf32f(float x) {
    uint32_t u;
    asm("cvt.rna.tf32.f32 %0, %1;" : "=r"(u) : "f"(x));
    return __uint_as_float(u);
}

__device__ __forceinline__ void mma_tf32(float c[4], const uint32_t a[4], const uint32_t b[2]) {
    asm volatile(
        "mma.sync.aligned.m16n8k8.row.col.f32.tf32.tf32.f32 "
        "{%0,%1,%2,%3}, {%4,%5,%6,%7}, {%8,%9}, {%0,%1,%2,%3};"
        : "+f"(c[0]), "+f"(c[1]), "+f"(c[2]), "+f"(c[3])
        : "r"(a[0]), "r"(a[1]), "r"(a[2]), "r"(a[3]), "r"(b[0]), "r"(b[1]));
}

// narrow: warp tile 64x32 over 128x128 block (8 warps)
__device__ __forceinline__ void tile_mma(
    const float (*As)[BMP], const float (*Bs)[BMP],
    int wm, int wn, int g, int t, float acc[4][4][4])
{
#pragma unroll
    for (int ks = 0; ks < BK; ks += 8) {
        uint32_t af[4][4], bf[4][2];
#pragma unroll
        for (int mi = 0; mi < 4; mi++) {
            int m = wm + mi * 16 + g;
            af[mi][0] = __float_as_uint(As[ks + t][m]);
            af[mi][1] = __float_as_uint(As[ks + t][m + 8]);
            af[mi][2] = __float_as_uint(As[ks + t + 4][m]);
            af[mi][3] = __float_as_uint(As[ks + t + 4][m + 8]);
        }
#pragma unroll
        for (int ni = 0; ni < 4; ni++) {
            int n = wn + ni * 8 + g;
            bf[ni][0] = __float_as_uint(Bs[ks + t][n]);
            bf[ni][1] = __float_as_uint(Bs[ks + t + 4][n]);
        }
#pragma unroll
        for (int mi = 0; mi < 4; mi++)
#pragma unroll
            for (int ni = 0; ni < 4; ni++)
                mma_tf32(acc[mi][ni], af[mi], bf[ni]);
    }
}

// wide: warp tile 64x64 over 128x256 block (8 warps)
__device__ __forceinline__ void tile_mma_w(
    const float (*As)[BMP], const float (*Bs)[BNP],
    int wm, int wn, int g, int t, float acc[4][8][4])
{
#pragma unroll
    for (int ks = 0; ks < BK; ks += 8) {
        uint32_t af[4][4], bf[8][2];
#pragma unroll
        for (int mi = 0; mi < 4; mi++) {
            int m = wm + mi * 16 + g;
            af[mi][0] = __float_as_uint(As[ks + t][m]);
            af[mi][1] = __float_as_uint(As[ks + t][m + 8]);
            af[mi][2] = __float_as_uint(As[ks + t + 4][m]);
            af[mi][3] = __float_as_uint(As[ks + t + 4][m + 8]);
        }
#pragma unroll
        for (int ni = 0; ni < 8; ni++) {
            int n = wn + ni * 8 + g;
            bf[ni][0] = __float_as_uint(Bs[ks + t][n]);
            bf[ni][1] = __float_as_uint(Bs[ks + t + 4][n]);
        }
#pragma unroll
        for (int mi = 0; mi < 4; mi++)
#pragma unroll
            for (int ni = 0; ni < 8; ni++)
                mma_tf32(acc[mi][ni], af[mi], bf[ni]);
    }
}

#define DECL_ACC float acc[4][4][4]; \
    _Pragma("unroll") for (int mi = 0; mi < 4; mi++) \
    _Pragma("unroll") for (int ni = 0; ni < 4; ni++) \
    _Pragma("unroll") for (int r = 0; r < 4; r++) acc[mi][ni][r] = 0.f;

#define DECL_ACC_W float acc[4][8][4]; \
    _Pragma("unroll") for (int mi = 0; mi < 4; mi++) \
    _Pragma("unroll") for (int ni = 0; ni < 8; ni++) \
    _Pragma("unroll") for (int r = 0; r < 4; r++) acc[mi][ni][r] = 0.f;

// ---- batched arg structs ----
struct Proj9 {
    const float* X[9]; const float* W[9]; const float* B[9];
    float* D[9]; int sidx[9];
};
struct Att3 {
    const float* Q[3]; const float* Ka[3]; const float* Kb[3];
    const float* V[3]; float* O[3];
};

// wide-kernel dynamic smem: As[2][16][136] then Bs[2][16][264]
#define WIDE_SMEM_FLOATS (2 * BK * BMP + 2 * BK * BNP)
#define WIDE_SMEM_BYTES  (WIDE_SMEM_FLOATS * 4)

// =====================================================================
// batched proj (64x32 warps), z = job*4 + b (grid z = 36)
// =====================================================================
__global__ void __launch_bounds__(256, 2) proj_mma9(Proj9 P, const float* __restrict__ s)
{
    __shared__ float As[2][BK][BMP];
    __shared__ float Bs[2][BK][BMP];
    const int z = blockIdx.z, job = z >> 2, b = z & 3;
    const int o0 = blockIdx.y * BM;
    const int n0 = blockIdx.x * BN;
    const int tid = threadIdx.x;
    const int warp = tid >> 5, lane = tid & 31;
    const int g = lane >> 2, t = lane & 3;
    const int wm = (warp & 1) * 64, wn = (warp >> 1) * 32;

    const float* Xb   = P.X[job] + (size_t)b * CN;
    const float* Wt   = P.W[job];
    const float* bias = P.B[job];
    float*       dst  = P.D[job] + (size_t)b * CN;
    const int   sidx  = P.sidx[job];

    const int arow = tid >> 1;
    const int akk0 = (tid & 1) * 8;
    const int bn4 = (tid & 31) * 4;
    const int bk0 = tid >> 5;

    DECL_ACC;

    float4 a_st[2], b_st[2];
    auto loadg = [&](int k0) {
#pragma unroll
        for (int r = 0; r < 2; r++)
            a_st[r] = *(const float4*)(Wt + (size_t)(o0 + arow) * Cdim + k0 + akk0 + r * 4);
#pragma unroll
        for (int r = 0; r < 2; r++)
            b_st[r] = *(const float4*)(Xb + (size_t)(k0 + bk0 + r * 8) * Ndim + n0 + bn4);
    };
    auto storeg = [&](int buf) {
#pragma unroll
        for (int r = 0; r < 2; r++) {
            int kk = akk0 + r * 4;
            As[buf][kk + 0][arow] = f2tf32f(a_st[r].x);
            As[buf][kk + 1][arow] = f2tf32f(a_st[r].y);
            As[buf][kk + 2][arow] = f2tf32f(a_st[r].z);
            As[buf][kk + 3][arow] = f2tf32f(a_st[r].w);
        }
#pragma unroll
        for (int r = 0; r < 2; r++) {
            float4 v = b_st[r];
            v.x = f2tf32f(v.x); v.y = f2tf32f(v.y);
            v.z = f2tf32f(v.z); v.w = f2tf32f(v.w);
            *(float4*)(&Bs[buf][bk0 + r * 8][bn4]) = v;
        }
    };

    loadg(0); storeg(0); __syncthreads();
    int buf = 0;
    for (int k0 = 0; k0 < Cdim; k0 += BK) {
        bool more = (k0 + BK) < Cdim;
        if (more) loadg(k0 + BK);
        tile_mma(As[buf], Bs[buf], wm, wn, g, t, acc);
        if (more) storeg(buf ^ 1);
        __syncthreads();
        buf ^= 1;
    }

    const float scale = (sidx >= 0) ? s[sidx] : 1.f;
#pragma unroll
    for (int mi = 0; mi < 4; mi++)
#pragma unroll
        for (int r2 = 0; r2 < 2; r2++) {
            int m = o0 + wm + mi * 16 + g + r2 * 8;
            float bi = bias[m];
#pragma unroll
            for (int ni = 0; ni < 4; ni++) {
                int n = n0 + wn + ni * 8 + t * 2;
                size_t idx = (size_t)m * Ndim + n;
                dst[idx]     = (acc[mi][ni][r2 * 2 + 0] + bi) * scale;
                dst[idx + 1] = (acc[mi][ni][r2 * 2 + 1] + bi) * scale;
            }
        }
}

// =====================================================================
// batched scores, wide 128(y) x 256(z) tiles, z = attend*4 + b (grid z=12)
// S3[z][y][m] = (1/16) sum_c Q[c][y]*(Ka[c][m]+Kb[c][m])
// =====================================================================
__global__ void __launch_bounds__(256, 1) scores_w(Att3 A)
{
    extern __shared__ float dyn[];
    float (*As)[BK][BMP] = (float(*)[BK][BMP])dyn;
    float (*Bs)[BK][BNP] = (float(*)[BK][BNP])(dyn + 2 * BK * BMP);

    const int zb = blockIdx.z, a = zb >> 2, b = zb & 3;
    const int y0 = blockIdx.y * 128;
    const int z0 = blockIdx.x * 256;
    const int tid = threadIdx.x;
    const int warp = tid >> 5, lane = tid & 31;
    const int g = lane >> 2, t = lane & 3;
    const int wm = (warp & 1) * 64, wn = (warp >> 1) * 64;
    const float* Qb  = A.Q[a]  + (size_t)b * CN;
    const float* Kab = A.Ka[a] + (size_t)b * CN;
    const float* Kbb = A.Kb[a] + (size_t)b * CN;

    // A loader: 16 threads/row, 8 floats each
    const int akr = tid >> 4;             // k row 0..15
    const int ac8 = (tid & 15) * 8;       // col in [0,128)
    // B loader: 16 threads/row, 16 floats each
    const int bkr = tid >> 4;
    const int bc16 = (tid & 15) * 16;     // col in [0,256)

    DECL_ACC_W;

    float4 a_st[2], b_st[4];
    auto loadg = [&](int k0) {
        size_t ka = (size_t)(k0 + akr) * Ndim + y0 + ac8;
#pragma unroll
        for (int r = 0; r < 2; r++)
            a_st[r] = *(const float4*)(Qb + ka + r * 4);
        size_t kb = (size_t)(k0 + bkr) * Ndim + z0 + bc16;
#pragma unroll
        for (int r = 0; r < 4; r++) {
            float4 v1 = *(const float4*)(Kab + kb + r * 4);
            float4 v2 = *(const float4*)(Kbb + kb + r * 4);
            v1.x += v2.x; v1.y += v2.y; v1.z += v2.z; v1.w += v2.w;
            b_st[r] = v1;
        }
    };
    auto storeg = [&](int buf) {
#pragma unroll
        for (int r = 0; r < 2; r++) {
            float4 v = a_st[r];
            v.x = f2tf32f(v.x); v.y = f2tf32f(v.y);
            v.z = f2tf32f(v.z); v.w = f2tf32f(v.w);
            *(float4*)(&As[buf][akr][ac8 + r * 4]) = v;
        }
#pragma unroll
        for (int r = 0; r < 4; r++) {
            float4 v = b_st[r];
            v.x = f2tf32f(v.x); v.y = f2tf32f(v.y);
            v.z = f2tf32f(v.z); v.w = f2tf32f(v.w);
            *(float4*)(&Bs[buf][bkr][bc16 + r * 4]) = v;
        }
    };

    loadg(0); storeg(0); __syncthreads();
    int buf = 0;
    for (int k0 = 0; k0 < Cdim; k0 += BK) {
        bool more = (k0 + BK) < Cdim;
        if (more) loadg(k0 + BK);
        tile_mma_w(As[buf], Bs[buf], wm, wn, g, t, acc);
        if (more) storeg(buf ^ 1);
        __syncthreads();
        buf ^= 1;
    }

    float* Sb = g_S3 + (size_t)zb * NN;
#pragma unroll
    for (int mi = 0; mi < 4; mi++)
#pragma unroll
        for (int r2 = 0; r2 < 2; r2++) {
            int y = y0 + wm + mi * 16 + g + r2 * 8;
#pragma unroll
            for (int ni = 0; ni < 8; ni++) {
                int zz = z0 + wn + ni * 8 + t * 2;
                size_t idx = (size_t)y * Ndim + zz;
                Sb[idx]     = acc[mi][ni][r2 * 2 + 0] * 0.0625f;
                Sb[idx + 1] = acc[mi][ni][r2 * 2 + 1] * 0.0625f;
            }
        }
}

// =====================================================================
// softmax (one block per row)
// =====================================================================
__global__ void __launch_bounds__(256) softmax_kernel()
{
    const size_t row = blockIdx.x;
    float* p = g_S3 + row * Ndim;
    const int tid = threadIdx.x;
    const int warp = tid >> 5, lane = tid & 31;
    __shared__ float red[8];

    float v[9];
#pragma unroll
    for (int i = 0; i < 9; i++) v[i] = p[tid + i * 256];

    float mx = v[0];
#pragma unroll
    for (int i = 1; i < 9; i++) mx = fmaxf(mx, v[i]);
#pragma unroll
    for (int off = 16; off > 0; off >>= 1)
        mx = fmaxf(mx, __shfl_xor_sync(0xffffffffu, mx, off));
    if (lane == 0) red[warp] = mx;
    __syncthreads();
    if (warp == 0) {
        float m2 = red[lane & 7];
#pragma unroll
        for (int off = 4; off > 0; off >>= 1)
            m2 = fmaxf(m2, __shfl_xor_sync(0xffffffffu, m2, off));
        if (lane == 0) red[0] = m2;
    }
    __syncthreads();
    mx = red[0];

    float sum = 0.f;
#pragma unroll
    for (int i = 0; i < 9; i++) { v[i] = __expf(v[i] - mx); sum += v[i]; }
#pragma unroll
    for (int off = 16; off > 0; off >>= 1)
        sum += __shfl_xor_sync(0xffffffffu, sum, off);
    __syncthreads();
    if (lane == 0) red[warp] = sum;
    __syncthreads();
    if (warp == 0) {
        float s2 = red[lane & 7];
#pragma unroll
        for (int off = 4; off > 0; off >>= 1)
            s2 += __shfl_xor_sync(0xffffffffu, s2, off);
        if (lane == 0) red[0] = s2;
    }
    __syncthreads();
    const float inv = 1.f / red[0];
#pragma unroll
    for (int i = 0; i < 9; i++) p[tid + i * 256] = v[i] * inv;
}

// =====================================================================
// batched AV, wide 128(c) x 256(n) tiles, z = attend*4 + b (grid z=12)
// dst[c][n] = sum_m V[c][m] * P[n][m]
// =====================================================================
__global__ void __launch_bounds__(256, 1) av_w(Att3 A)
{
    extern __shared__ float dyn[];
    float (*As)[BK][BMP] = (float(*)[BK][BMP])dyn;
    float (*Bs)[BK][BNP] = (float(*)[BK][BNP])(dyn + 2 * BK * BMP);

    const int zb = blockIdx.z, a = zb >> 2, b = zb & 3;
    const int c0 = blockIdx.y * 128;
    const int n0 = blockIdx.x * 256;
    const int tid = threadIdx.x;
    const int warp = tid >> 5, lane = tid & 31;
    const int g = lane >> 2, t = lane & 3;
    const int wm = (warp & 1) * 64, wn = (warp >> 1) * 64;
    const float* Vb = A.V[a] + (size_t)b * CN;
    const float* Sb = g_S3 + (size_t)zb * NN;
    float*      dst = A.O[a] + (size_t)b * CN;

    // A loader (transpose): 2 threads/row, 8 k-values each
    const int arow = tid >> 1;            // c row 0..127
    const int akk0 = (tid & 1) * 8;
    // B loader (transpose): 1 thread/row, 16 k-values
    const int brow = tid;                 // n row 0..255

    DECL_ACC_W;

    float4 a_st[2], b_st[4];
    auto loadg = [&](int k0) {
#pragma unroll
        for (int r = 0; r < 2; r++)
            a_st[r] = *(const float4*)(Vb + (size_t)(c0 + arow) * Ndim + k0 + akk0 + r * 4);
        const float* srow = Sb + (size_t)(n0 + brow) * Ndim + k0;
#pragma unroll
        for (int r = 0; r < 4; r++)
            b_st[r] = *(const float4*)(srow + r * 4);
    };
    auto storeg = [&](int buf) {
#pragma unroll
        for (int r = 0; r < 2; r++) {
            int kk = akk0 + r * 4;
            As[buf][kk + 0][arow] = f2tf32f(a_st[r].x);
            As[buf][kk + 1][arow] = f2tf32f(a_st[r].y);
            As[buf][kk + 2][arow] = f2tf32f(a_st[r].z);
            As[buf][kk + 3][arow] = f2tf32f(a_st[r].w);
        }
#pragma unroll
        for (int r = 0; r < 4; r++) {
            int kk = r * 4;
            Bs[buf][kk + 0][brow] = f2tf32f(b_st[r].x);
            Bs[buf][kk + 1][brow] = f2tf32f(b_st[r].y);
            Bs[buf][kk + 2][brow] = f2tf32f(b_st[r].z);
            Bs[buf][kk + 3][brow] = f2tf32f(b_st[r].w);
        }
    };

    loadg(0); storeg(0); __syncthreads();
    int buf = 0;
    for (int k0 = 0; k0 < Ndim; k0 += BK) {
        bool more = (k0 + BK) < Ndim;
        if (more) loadg(k0 + BK);
        tile_mma_w(As[buf], Bs[buf], wm, wn, g, t, acc);
        if (more) storeg(buf ^ 1);
        __syncthreads();
        buf ^= 1;
    }

#pragma unroll
    for (int mi = 0; mi < 4; mi++)
#pragma unroll
        for (int r2 = 0; r2 < 2; r2++) {
            int c = c0 + wm + mi * 16 + g + r2 * 8;
#pragma unroll
            for (int ni = 0; ni < 8; ni++) {
                int n = n0 + wn + ni * 8 + t * 2;
                size_t idx = (size_t)c * Ndim + n;
                dst[idx]     = acc[mi][ni][r2 * 2 + 0];
                dst[idx + 1] = acc[mi][ni][r2 * 2 + 1];
            }
        }
}

// =====================================================================
// batched gate (64x32 warps), z = m*4 + b (grid z = 12)
// =====================================================================
__global__ void __launch_bounds__(256, 2) gate_mma3(
    const float* __restrict__ Wg, const float* __restrict__ bg)
{
    __shared__ float As[2][BK][BMP];
    __shared__ float Bs[2][BK][BMP];
    const int z = blockIdx.z, a = z >> 2, b = z & 3;
    const int o0 = blockIdx.y * BM;
    const int n0 = blockIdx.x * BN;
    const int tid = threadIdx.x;
    const int warp = tid >> 5, lane = tid & 31;
    const int g = lane >> 2, t = lane & 3;
    const int wm = (warp & 1) * 64, wn = (warp >> 1) * 32;
    const float* Xb = g_W[a] + (size_t)b * CN;
    float*       F  = g_F3[a] + (size_t)b * CN;

    const int arow = tid >> 1;
    const int akk0 = (tid & 1) * 8;
    const int bn4 = (tid & 31) * 4;
    const int bk0 = tid >> 5;

    DECL_ACC;

    float4 a_st[2], b_st[2];
    auto loadg = [&](int k0) {
#pragma unroll
        for (int r = 0; r < 2; r++)
            a_st[r] = *(const float4*)(Wg + (size_t)(o0 + arow) * Cdim + k0 + akk0 + r * 4);
#pragma unroll
        for (int r = 0; r < 2; r++)
            b_st[r] = *(const float4*)(Xb + (size_t)(k0 + bk0 + r * 8) * Ndim + n0 + bn4);
    };
    auto storeg = [&](int buf) {
#pragma unroll
        for (int r = 0; r < 2; r++) {
            int kk = akk0 + r * 4;
            As[buf][kk + 0][arow] = f2tf32f(a_st[r].x);
            As[buf][kk + 1][arow] = f2tf32f(a_st[r].y);
            As[buf][kk + 2][arow] = f2tf32f(a_st[r].z);
            As[buf][kk + 3][arow] = f2tf32f(a_st[r].w);
        }
#pragma unroll
        for (int r = 0; r < 2; r++) {
            float4 v = b_st[r];
            v.x = f2tf32f(v.x); v.y = f2tf32f(v.y);
            v.z = f2tf32f(v.z); v.w = f2tf32f(v.w);
            *(float4*)(&Bs[buf][bk0 + r * 8][bn4]) = v;
        }
    };

    loadg(0); storeg(0); __syncthreads();
    int buf = 0;
    for (int k0 = 0; k0 < Cdim; k0 += BK) {
        bool more = (k0 + BK) < Cdim;
        if (more) loadg(k0 + BK);
        tile_mma(As[buf], Bs[buf], wm, wn, g, t, acc);
        if (more) storeg(buf ^ 1);
        __syncthreads();
        buf ^= 1;
    }

#pragma unroll
    for (int mi = 0; mi < 4; mi++)
#pragma unroll
        for (int r2 = 0; r2 < 2; r2++) {
            int o = o0 + wm + mi * 16 + g + r2 * 8;
            float bi = bg[o];
#pragma unroll
            for (int ni = 0; ni < 4; ni++) {
                int n = n0 + wn + ni * 8 + t * 2;
                size_t idx = (size_t)o * Ndim + n;
#pragma unroll
                for (int e = 0; e < 2; e++) {
                    float gv  = acc[mi][ni][r2 * 2 + e] + bi;
                    float sig = 1.f / (1.f + __expf(-gv));
                    F[idx + e] = sig * Xb[idx + e];
                }
            }
        }
}

// =====================================================================
// final conv (64x32 warps): out = Wo @ (F0+F1+F2) + bo (grid z = 4)
// =====================================================================
__global__ void __launch_bounds__(256, 2) final_mma(
    const float* __restrict__ Wo, const float* __restrict__ bo,
    float* __restrict__ out)
{
    __shared__ float As[2][BK][BMP];
    __shared__ float Bs[2][BK][BMP];
    const int b  = blockIdx.z;
    const int o0 = blockIdx.y * BM;
    const int n0 = blockIdx.x * BN;
    const int tid = threadIdx.x;
    const int warp = tid >> 5, lane = tid & 31;
    const int g = lane >> 2, t = lane & 3;
    const int wm = (warp & 1) * 64, wn = (warp >> 1) * 32;
    const float* F0 = g_F3[0] + (size_t)b * CN;
    const float* F1 = g_F3[1] + (size_t)b * CN;
    const float* F2 = g_F3[2] + (size_t)b * CN;
    float* dst = out + (size_t)b * CN;

    const int arow = tid >> 1;
    const int akk0 = (tid & 1) * 8;
    const int bn4 = (tid & 31) * 4;
    const int bk0 = tid >> 5;

    DECL_ACC;

    float4 a_st[2], b_st[2];
    auto loadg = [&](int k0) {
#pragma unroll
        for (int r = 0; r < 2; r++)
            a_st[r] = *(const float4*)(Wo + (size_t)(o0 + arow) * Cdim + k0 + akk0 + r * 4);
#pragma unroll
        for (int r = 0; r < 2; r++) {
            size_t off = (size_t)(k0 + bk0 + r * 8) * Ndim + n0 + bn4;
            float4 v0 = *(const float4*)(F0 + off);
            float4 v1 = *(const float4*)(F1 + off);
            float4 v2 = *(const float4*)(F2 + off);
            v0.x += v1.x + v2.x; v0.y += v1.y + v2.y;
            v0.z += v1.z + v2.z; v0.w += v1.w + v2.w;
            b_st[r] = v0;
        }
    };
    auto storeg = [&](int buf) {
#pragma unroll
        for (int r = 0; r < 2; r++) {
            int kk = akk0 + r * 4;
            As[buf][kk + 0][arow] = f2tf32f(a_st[r].x);
            As[buf][kk + 1][arow] = f2tf32f(a_st[r].y);
            As[buf][kk + 2][arow] = f2tf32f(a_st[r].z);
            As[buf][kk + 3][arow] = f2tf32f(a_st[r].w);
        }
#pragma unroll
        for (int r = 0; r < 2; r++) {
            float4 v = b_st[r];
            v.x = f2tf32f(v.x); v.y = f2tf32f(v.y);
            v.z = f2tf32f(v.z); v.w = f2tf32f(v.w);
            *(float4*)(&Bs[buf][bk0 + r * 8][bn4]) = v;
        }
    };

    loadg(0); storeg(0); __syncthreads();
    int buf = 0;
    for (int k0 = 0; k0 < Cdim; k0 += BK) {
        bool more = (k0 + BK) < Cdim;
        if (more) loadg(k0 + BK);
        tile_mma(As[buf], Bs[buf], wm, wn, g, t, acc);
        if (more) storeg(buf ^ 1);
        __syncthreads();
        buf ^= 1;
    }

#pragma unroll
    for (int mi = 0; mi < 4; mi++)
#pragma unroll
        for (int r2 = 0; r2 < 2; r2++) {
            int o = o0 + wm + mi * 16 + g + r2 * 8;
            float bi = bo[o];
#pragma unroll
            for (int ni = 0; ni < 4; ni++) {
                int n = n0 + wn + ni * 8 + t * 2;
                size_t idx = (size_t)o * Ndim + n;
                dst[idx]     = acc[mi][ni][r2 * 2 + 0] + bi;
                dst[idx + 1] = acc[mi][ni][r2 * 2 + 1] + bi;
            }
        }
}

// =====================================================================
// launch
// =====================================================================
extern "C" void kernel_launch(void* const* d_in, const int* in_sizes, int n_in,
                              void* d_out, int out_size)
{
    const float* x[3] = { (const float*)d_in[0], (const float*)d_in[1], (const float*)d_in[2] };
    const float* s = (const float*)d_in[3];
    const float *wq[3], *bq[3], *wk[3], *bk[3], *wv[3], *bv[3];
    for (int m = 0; m < 3; m++) {
        wq[m] = (const float*)d_in[4 + 6 * m];
        bq[m] = (const float*)d_in[5 + 6 * m];
        wk[m] = (const float*)d_in[6 + 6 * m];
        bk[m] = (const float*)d_in[7 + 6 * m];
        wv[m] = (const float*)d_in[8 + 6 * m];
        bv[m] = (const float*)d_in[9 + 6 * m];
    }
    const float* wg = (const float*)d_in[22];
    const float* bg = (const float*)d_in[23];
    const float* wo = (const float*)d_in[24];
    const float* bo = (const float*)d_in[25];
    float* out = (float*)d_out;

    float *gP, *gW;
    cudaGetSymbolAddress((void**)&gP, g_P);
    cudaGetSymbolAddress((void**)&gW, g_W);

    float* Q[3]; float* K[3]; float* V[3]; float* Wout[3];
    for (int m = 0; m < 3; m++) {
        Q[m]    = gP + (size_t)(0 + m) * PLANE;
        K[m]    = gP + (size_t)(3 + m) * PLANE;
        V[m]    = gP + (size_t)(6 + m) * PLANE;
        Wout[m] = gW + (size_t)m * PLANE;
    }

    Proj9 P;
    for (int m = 0; m < 3; m++) {
        P.X[3 * m + 0] = x[m]; P.W[3 * m + 0] = wq[m]; P.B[3 * m + 0] = bq[m];
        P.D[3 * m + 0] = Q[m]; P.sidx[3 * m + 0] = m;
        P.X[3 * m + 1] = x[m]; P.W[3 * m + 1] = wk[m]; P.B[3 * m + 1] = bk[m];
        P.D[3 * m + 1] = K[m]; P.sidx[3 * m + 1] = m;
        P.X[3 * m + 2] = x[m]; P.W[3 * m + 2] = wv[m]; P.B[3 * m + 2] = bv[m];
        P.D[3 * m + 2] = V[m]; P.sidx[3 * m + 2] = -1;
    }

    // attends: w_rgb(Q0; K2+K1; V0), w_depth(Q2; K0+K1; V2), w_thermal(Q1; K0+K2; V1)
    Att3 A;
    const int qi[3]  = { 0, 2, 1 };
    const int kai[3] = { 2, 0, 0 };
    const int kbi[3] = { 1, 1, 2 };
    for (int a = 0; a < 3; a++) {
        A.Q[a]  = Q[qi[a]];
        A.Ka[a] = K[kai[a]];
        A.Kb[a] = K[kbi[a]];
        A.V[a]  = V[qi[a]];
        A.O[a]  = Wout[a];
    }

    cudaFuncSetAttribute(scores_w, cudaFuncAttributeMaxDynamicSharedMemorySize, WIDE_SMEM_BYTES);
    cudaFuncSetAttribute(av_w,     cudaFuncAttributeMaxDynamicSharedMemorySize, WIDE_SMEM_BYTES);

    dim3 blk(256);
    proj_mma9 <<<dim3(Ndim / BN, Cdim / BM, 36), blk>>>(P, s);
    scores_w  <<<dim3(Ndim / 256, Ndim / 128, 12), blk, WIDE_SMEM_BYTES>>>(A);
    softmax_kernel<<<dim3(3 * Bdim * Ndim), blk>>>();
    av_w      <<<dim3(Ndim / 256, Cdim / 128, 12), blk, WIDE_SMEM_BYTES>>>(A);
    gate_mma3 <<<dim3(Ndim / BN, Cdim / BM, 12), blk>>>(wg, bg);
    final_mma <<<dim3(Ndim / BN, Cdim / BM, 4), blk>>>(wo, bo, out);
}

// round 7
// speedup vs baseline: 1.1140x; 1.1140x over previous
#include <cuda_runtime.h>
#include <cstdint>
#include <math.h>

#define Bdim 4
#define Cdim 256
#define Ndim 2304      // 48*48
#define PLANE (Bdim*Cdim*Ndim)
#define CN   (Cdim*Ndim)
#define NN   ((size_t)Ndim*Ndim)

#define BM 128
#define BN 128
#define BK 16
#define BMP 136        // padded smem stride

// ---- scratch ----
__device__ float g_P[9][PLANE];                      // Q0..2, K0..2, V0..2
__device__ float g_S3[(size_t)3 * Bdim * NN];        // scores for all 3 attends
__device__ float g_W[3][PLANE];                      // attention outputs
__device__ float g_F3[3][PLANE];                     // gated outputs

// ---- tf32 helpers ----
__device__ __forceinline__ float f2tf32f(float x) {
    uint32_t u;
    asm("cvt.rna.tf32.f32 %0, %1;" : "=r"(u) : "f"(x));
    return __uint_as_float(u);
}

__device__ __forceinline__ void mma_tf32(float c[4], const uint32_t a[4], const uint32_t b[2]) {
    asm volatile(
        "mma.sync.aligned.m16n8k8.row.col.f32.tf32.tf32.f32 "
        "{%0,%1,%2,%3}, {%4,%5,%6,%7}, {%8,%9}, {%0,%1,%2,%3};"
        : "+f"(c[0]), "+f"(c[1]), "+f"(c[2]), "+f"(c[3])
        : "r"(a[0]), "r"(a[1]), "r"(a[2]), "r"(a[3]), "r"(b[0]), "r"(b[1]));
}

// narrow: warp tile 64x32 over 128x128 block (8 warps of 256)
__device__ __forceinline__ void tile_mma(
    const float (*As)[BMP], const float (*Bs)[BMP],
    int wm, int wn, int g, int t, float acc[4][4][4])
{
#pragma unroll
    for (int ks = 0; ks < BK; ks += 8) {
        uint32_t af[4][4], bf[4][2];
#pragma unroll
        for (int mi = 0; mi < 4; mi++) {
            int m = wm + mi * 16 + g;
            af[mi][0] = __float_as_uint(As[ks + t][m]);
            af[mi][1] = __float_as_uint(As[ks + t][m + 8]);
            af[mi][2] = __float_as_uint(As[ks + t + 4][m]);
            af[mi][3] = __float_as_uint(As[ks + t + 4][m + 8]);
        }
#pragma unroll
        for (int ni = 0; ni < 4; ni++) {
            int n = wn + ni * 8 + g;
            bf[ni][0] = __float_as_uint(Bs[ks + t][n]);
            bf[ni][1] = __float_as_uint(Bs[ks + t + 4][n]);
        }
#pragma unroll
        for (int mi = 0; mi < 4; mi++)
#pragma unroll
            for (int ni = 0; ni < 4; ni++)
                mma_tf32(acc[mi][ni], af[mi], bf[ni]);
    }
}

// wide warp: 64x64 warp tile over 128x128 block (4 warps of 128 threads)
__device__ __forceinline__ void tile_mma_w64(
    const float (*As)[BMP], const float (*Bs)[BMP],
    int wm, int wn, int g, int t, float acc[4][8][4])
{
#pragma unroll
    for (int ks = 0; ks < BK; ks += 8) {
        uint32_t af[4][4], bf[8][2];
#pragma unroll
        for (int mi = 0; mi < 4; mi++) {
            int m = wm + mi * 16 + g;
            af[mi][0] = __float_as_uint(As[ks + t][m]);
            af[mi][1] = __float_as_uint(As[ks + t][m + 8]);
            af[mi][2] = __float_as_uint(As[ks + t + 4][m]);
            af[mi][3] = __float_as_uint(As[ks + t + 4][m + 8]);
        }
#pragma unroll
        for (int ni = 0; ni < 8; ni++) {
            int n = wn + ni * 8 + g;
            bf[ni][0] = __float_as_uint(Bs[ks + t][n]);
            bf[ni][1] = __float_as_uint(Bs[ks + t + 4][n]);
        }
#pragma unroll
        for (int mi = 0; mi < 4; mi++)
#pragma unroll
            for (int ni = 0; ni < 8; ni++)
                mma_tf32(acc[mi][ni], af[mi], bf[ni]);
    }
}

#define DECL_ACC float acc[4][4][4]; \
    _Pragma("unroll") for (int mi = 0; mi < 4; mi++) \
    _Pragma("unroll") for (int ni = 0; ni < 4; ni++) \
    _Pragma("unroll") for (int r = 0; r < 4; r++) acc[mi][ni][r] = 0.f;

#define DECL_ACC_W float acc[4][8][4]; \
    _Pragma("unroll") for (int mi = 0; mi < 4; mi++) \
    _Pragma("unroll") for (int ni = 0; ni < 8; ni++) \
    _Pragma("unroll") for (int r = 0; r < 4; r++) acc[mi][ni][r] = 0.f;

// ---- batched arg structs ----
struct Proj9 {
    const float* X[9]; const float* W[9]; const float* B[9];
    float* D[9]; int sidx[9];
};
struct Att3 {
    const float* Q[3]; const float* Ka[3]; const float* Kb[3];
    const float* V[3]; float* O[3];
};

// =====================================================================
// batched proj (64x32 warps, 256 thr), z = job*4 + b (grid z = 36)
// =====================================================================
__global__ void __launch_bounds__(256, 2) proj_mma9(Proj9 P, const float* __restrict__ s)
{
    __shared__ float As[2][BK][BMP];
    __shared__ float Bs[2][BK][BMP];
    const int z = blockIdx.z, job = z >> 2, b = z & 3;
    const int o0 = blockIdx.y * BM;
    const int n0 = blockIdx.x * BN;
    const int tid = threadIdx.x;
    const int warp = tid >> 5, lane = tid & 31;
    const int g = lane >> 2, t = lane & 3;
    const int wm = (warp & 1) * 64, wn = (warp >> 1) * 32;

    const float* Xb   = P.X[job] + (size_t)b * CN;
    const float* Wt   = P.W[job];
    const float* bias = P.B[job];
    float*       dst  = P.D[job] + (size_t)b * CN;
    const int   sidx  = P.sidx[job];

    const int arow = tid >> 1;
    const int akk0 = (tid & 1) * 8;
    const int bn4 = (tid & 31) * 4;
    const int bk0 = tid >> 5;

    DECL_ACC;

    float4 a_st[2], b_st[2];
    auto loadg = [&](int k0) {
#pragma unroll
        for (int r = 0; r < 2; r++)
            a_st[r] = *(const float4*)(Wt + (size_t)(o0 + arow) * Cdim + k0 + akk0 + r * 4);
#pragma unroll
        for (int r = 0; r < 2; r++)
            b_st[r] = *(const float4*)(Xb + (size_t)(k0 + bk0 + r * 8) * Ndim + n0 + bn4);
    };
    auto storeg = [&](int buf) {
#pragma unroll
        for (int r = 0; r < 2; r++) {
            int kk = akk0 + r * 4;
            As[buf][kk + 0][arow] = f2tf32f(a_st[r].x);
            As[buf][kk + 1][arow] = f2tf32f(a_st[r].y);
            As[buf][kk + 2][arow] = f2tf32f(a_st[r].z);
            As[buf][kk + 3][arow] = f2tf32f(a_st[r].w);
        }
#pragma unroll
        for (int r = 0; r < 2; r++) {
            float4 v = b_st[r];
            v.x = f2tf32f(v.x); v.y = f2tf32f(v.y);
            v.z = f2tf32f(v.z); v.w = f2tf32f(v.w);
            *(float4*)(&Bs[buf][bk0 + r * 8][bn4]) = v;
        }
    };

    loadg(0); storeg(0); __syncthreads();
    int buf = 0;
    for (int k0 = 0; k0 < Cdim; k0 += BK) {
        bool more = (k0 + BK) < Cdim;
        if (more) loadg(k0 + BK);
        tile_mma(As[buf], Bs[buf], wm, wn, g, t, acc);
        if (more) storeg(buf ^ 1);
        __syncthreads();
        buf ^= 1;
    }

    const float scale = (sidx >= 0) ? s[sidx] : 1.f;
#pragma unroll
    for (int mi = 0; mi < 4; mi++)
#pragma unroll
        for (int r2 = 0; r2 < 2; r2++) {
            int m = o0 + wm + mi * 16 + g + r2 * 8;
            float bi = bias[m];
#pragma unroll
            for (int ni = 0; ni < 4; ni++) {
                int n = n0 + wn + ni * 8 + t * 2;
                size_t idx = (size_t)m * Ndim + n;
                dst[idx]     = (acc[mi][ni][r2 * 2 + 0] + bi) * scale;
                dst[idx + 1] = (acc[mi][ni][r2 * 2 + 1] + bi) * scale;
            }
        }
}

// =====================================================================
// batched scores, 128 threads / 4 warps, 64x64 warp tiles, block 128x128
// z = attend*4 + b (grid z = 12)
// S3[z][y][m] = (1/16) sum_c Q[c][y]*(Ka[c][m]+Kb[c][m])
// =====================================================================
__global__ void __launch_bounds__(128, 2) scores_w64(Att3 A)
{
    __shared__ float As[2][BK][BMP];
    __shared__ float Bs[2][BK][BMP];
    const int zb = blockIdx.z, a = zb >> 2, b = zb & 3;
    const int y0 = blockIdx.y * 128;
    const int z0 = blockIdx.x * 128;
    const int tid = threadIdx.x;
    const int warp = tid >> 5, lane = tid & 31;
    const int g = lane >> 2, t = lane & 3;
    const int wm = (warp & 1) * 64, wn = (warp >> 1) * 64;
    const float* Qb  = A.Q[a]  + (size_t)b * CN;
    const float* Kab = A.Ka[a] + (size_t)b * CN;
    const float* Kbb = A.Kb[a] + (size_t)b * CN;

    // loaders: 8 threads per k-row, each 4 strided float4 (stride 32 floats)
    const int kr = tid >> 3;          // k row 0..15
    const int q4 = (tid & 7) * 4;     // float col base

    DECL_ACC_W;

    float4 a_st[4], b_st[4];
    auto loadg = [&](int k0) {
        size_t ka = (size_t)(k0 + kr) * Ndim;
#pragma unroll
        for (int r = 0; r < 4; r++) {
            a_st[r] = *(const float4*)(Qb + ka + y0 + q4 + r * 32);
            float4 v1 = *(const float4*)(Kab + ka + z0 + q4 + r * 32);
            float4 v2 = *(const float4*)(Kbb + ka + z0 + q4 + r * 32);
            v1.x += v2.x; v1.y += v2.y; v1.z += v2.z; v1.w += v2.w;
            b_st[r] = v1;
        }
    };
    auto storeg = [&](int buf) {
#pragma unroll
        for (int r = 0; r < 4; r++) {
            float4 v = a_st[r];
            v.x = f2tf32f(v.x); v.y = f2tf32f(v.y);
            v.z = f2tf32f(v.z); v.w = f2tf32f(v.w);
            *(float4*)(&As[buf][kr][q4 + r * 32]) = v;
            float4 w = b_st[r];
            w.x = f2tf32f(w.x); w.y = f2tf32f(w.y);
            w.z = f2tf32f(w.z); w.w = f2tf32f(w.w);
            *(float4*)(&Bs[buf][kr][q4 + r * 32]) = w;
        }
    };

    loadg(0); storeg(0); __syncthreads();
    int buf = 0;
    for (int k0 = 0; k0 < Cdim; k0 += BK) {
        bool more = (k0 + BK) < Cdim;
        if (more) loadg(k0 + BK);
        tile_mma_w64(As[buf], Bs[buf], wm, wn, g, t, acc);
        if (more) storeg(buf ^ 1);
        __syncthreads();
        buf ^= 1;
    }

    float* Sb = g_S3 + (size_t)zb * NN;
#pragma unroll
    for (int mi = 0; mi < 4; mi++)
#pragma unroll
        for (int r2 = 0; r2 < 2; r2++) {
            int y = y0 + wm + mi * 16 + g + r2 * 8;
#pragma unroll
            for (int ni = 0; ni < 8; ni++) {
                int zz = z0 + wn + ni * 8 + t * 2;
                size_t idx = (size_t)y * Ndim + zz;
                Sb[idx]     = acc[mi][ni][r2 * 2 + 0] * 0.0625f;
                Sb[idx + 1] = acc[mi][ni][r2 * 2 + 1] * 0.0625f;
            }
        }
}

// =====================================================================
// softmax (one block per row)
// =====================================================================
__global__ void __launch_bounds__(256) softmax_kernel()
{
    const size_t row = blockIdx.x;
    float* p = g_S3 + row * Ndim;
    const int tid = threadIdx.x;
    const int warp = tid >> 5, lane = tid & 31;
    __shared__ float red[8];

    float v[9];
#pragma unroll
    for (int i = 0; i < 9; i++) v[i] = p[tid + i * 256];

    float mx = v[0];
#pragma unroll
    for (int i = 1; i < 9; i++) mx = fmaxf(mx, v[i]);
#pragma unroll
    for (int off = 16; off > 0; off >>= 1)
        mx = fmaxf(mx, __shfl_xor_sync(0xffffffffu, mx, off));
    if (lane == 0) red[warp] = mx;
    __syncthreads();
    if (warp == 0) {
        float m2 = red[lane & 7];
#pragma unroll
        for (int off = 4; off > 0; off >>= 1)
            m2 = fmaxf(m2, __shfl_xor_sync(0xffffffffu, m2, off));
        if (lane == 0) red[0] = m2;
    }
    __syncthreads();
    mx = red[0];

    float sum = 0.f;
#pragma unroll
    for (int i = 0; i < 9; i++) { v[i] = __expf(v[i] - mx); sum += v[i]; }
#pragma unroll
    for (int off = 16; off > 0; off >>= 1)
        sum += __shfl_xor_sync(0xffffffffu, sum, off);
    __syncthreads();
    if (lane == 0) red[warp] = sum;
    __syncthreads();
    if (warp == 0) {
        float s2 = red[lane & 7];
#pragma unroll
        for (int off = 4; off > 0; off >>= 1)
            s2 += __shfl_xor_sync(0xffffffffu, s2, off);
        if (lane == 0) red[0] = s2;
    }
    __syncthreads();
    const float inv = 1.f / red[0];
#pragma unroll
    for (int i = 0; i < 9; i++) p[tid + i * 256] = v[i] * inv;
}

// =====================================================================
// batched AV, 128 threads / 4 warps, 64x64 warp tiles, block 128x128
// z = attend*4 + b (grid z = 12); dst[c][n] = sum_m V[c][m] * P[n][m]
// =====================================================================
__global__ void __launch_bounds__(128, 2) av_w64(Att3 A)
{
    __shared__ float As[2][BK][BMP];
    __shared__ float Bs[2][BK][BMP];
    const int zb = blockIdx.z, a = zb >> 2, b = zb & 3;
    const int c0 = blockIdx.y * 128;
    const int n0 = blockIdx.x * 128;
    const int tid = threadIdx.x;
    const int warp = tid >> 5, lane = tid & 31;
    const int g = lane >> 2, t = lane & 3;
    const int wm = (warp & 1) * 64, wn = (warp >> 1) * 64;
    const float* Vb = A.V[a] + (size_t)b * CN;
    const float* Sb = g_S3 + (size_t)zb * NN;
    float*      dst = A.O[a] + (size_t)b * CN;

    // loaders: 1 thread per row (128 rows), 16 k-values (4 float4) each,
    // transposed scalar stores into [k][row] — conflict-free (bank = 8k+row).
    DECL_ACC_W;

    float4 a_st[4], b_st[4];
    auto loadg = [&](int k0) {
        const float* ga = Vb + (size_t)(c0 + tid) * Ndim + k0;
        const float* gb = Sb + (size_t)(n0 + tid) * Ndim + k0;
#pragma unroll
        for (int r = 0; r < 4; r++) {
            a_st[r] = *(const float4*)(ga + r * 4);
            b_st[r] = *(const float4*)(gb + r * 4);
        }
    };
    auto storeg = [&](int buf) {
#pragma unroll
        for (int r = 0; r < 4; r++) {
            int kk = r * 4;
            As[buf][kk + 0][tid] = f2tf32f(a_st[r].x);
            As[buf][kk + 1][tid] = f2tf32f(a_st[r].y);
            As[buf][kk + 2][tid] = f2tf32f(a_st[r].z);
            As[buf][kk + 3][tid] = f2tf32f(a_st[r].w);
            Bs[buf][kk + 0][tid] = f2tf32f(b_st[r].x);
            Bs[buf][kk + 1][tid] = f2tf32f(b_st[r].y);
            Bs[buf][kk + 2][tid] = f2tf32f(b_st[r].z);
            Bs[buf][kk + 3][tid] = f2tf32f(b_st[r].w);
        }
    };

    loadg(0); storeg(0); __syncthreads();
    int buf = 0;
    for (int k0 = 0; k0 < Ndim; k0 += BK) {
        bool more = (k0 + BK) < Ndim;
        if (more) loadg(k0 + BK);
        tile_mma_w64(As[buf], Bs[buf], wm, wn, g, t, acc);
        if (more) storeg(buf ^ 1);
        __syncthreads();
        buf ^= 1;
    }

#pragma unroll
    for (int mi = 0; mi < 4; mi++)
#pragma unroll
        for (int r2 = 0; r2 < 2; r2++) {
            int c = c0 + wm + mi * 16 + g + r2 * 8;
#pragma unroll
            for (int ni = 0; ni < 8; ni++) {
                int n = n0 + wn + ni * 8 + t * 2;
                size_t idx = (size_t)c * Ndim + n;
                dst[idx]     = acc[mi][ni][r2 * 2 + 0];
                dst[idx + 1] = acc[mi][ni][r2 * 2 + 1];
            }
        }
}

// =====================================================================
// batched gate (64x32 warps, 256 thr), z = m*4 + b (grid z = 12)
// =====================================================================
__global__ void __launch_bounds__(256, 2) gate_mma3(
    const float* __restrict__ Wg, const float* __restrict__ bg)
{
    __shared__ float As[2][BK][BMP];
    __shared__ float Bs[2][BK][BMP];
    const int z = blockIdx.z, a = z >> 2, b = z & 3;
    const int o0 = blockIdx.y * BM;
    const int n0 = blockIdx.x * BN;
    const int tid = threadIdx.x;
    const int warp = tid >> 5, lane = tid & 31;
    const int g = lane >> 2, t = lane & 3;
    const int wm = (warp & 1) * 64, wn = (warp >> 1) * 32;
    const float* Xb = g_W[a] + (size_t)b * CN;
    float*       F  = g_F3[a] + (size_t)b * CN;

    const int arow = tid >> 1;
    const int akk0 = (tid & 1) * 8;
    const int bn4 = (tid & 31) * 4;
    const int bk0 = tid >> 5;

    DECL_ACC;

    float4 a_st[2], b_st[2];
    auto loadg = [&](int k0) {
#pragma unroll
        for (int r = 0; r < 2; r++)
            a_st[r] = *(const float4*)(Wg + (size_t)(o0 + arow) * Cdim + k0 + akk0 + r * 4);
#pragma unroll
        for (int r = 0; r < 2; r++)
            b_st[r] = *(const float4*)(Xb + (size_t)(k0 + bk0 + r * 8) * Ndim + n0 + bn4);
    };
    auto storeg = [&](int buf) {
#pragma unroll
        for (int r = 0; r < 2; r++) {
            int kk = akk0 + r * 4;
            As[buf][kk + 0][arow] = f2tf32f(a_st[r].x);
            As[buf][kk + 1][arow] = f2tf32f(a_st[r].y);
            As[buf][kk + 2][arow] = f2tf32f(a_st[r].z);
            As[buf][kk + 3][arow] = f2tf32f(a_st[r].w);
        }
#pragma unroll
        for (int r = 0; r < 2; r++) {
            float4 v = b_st[r];
            v.x = f2tf32f(v.x); v.y = f2tf32f(v.y);
            v.z = f2tf32f(v.z); v.w = f2tf32f(v.w);
            *(float4*)(&Bs[buf][bk0 + r * 8][bn4]) = v;
        }
    };

    loadg(0); storeg(0); __syncthreads();
    int buf = 0;
    for (int k0 = 0; k0 < Cdim; k0 += BK) {
        bool more = (k0 + BK) < Cdim;
        if (more) loadg(k0 + BK);
        tile_mma(As[buf], Bs[buf], wm, wn, g, t, acc);
        if (more) storeg(buf ^ 1);
        __syncthreads();
        buf ^= 1;
    }

#pragma unroll
    for (int mi = 0; mi < 4; mi++)
#pragma unroll
        for (int r2 = 0; r2 < 2; r2++) {
            int o = o0 + wm + mi * 16 + g + r2 * 8;
            float bi = bg[o];
#pragma unroll
            for (int ni = 0; ni < 4; ni++) {
                int n = n0 + wn + ni * 8 + t * 2;
                size_t idx = (size_t)o * Ndim + n;
#pragma unroll
                for (int e = 0; e < 2; e++) {
                    float gv  = acc[mi][ni][r2 * 2 + e] + bi;
                    float sig = 1.f / (1.f + __expf(-gv));
                    F[idx + e] = sig * Xb[idx + e];
                }
            }
        }
}

// =====================================================================
// final conv (64x32 warps, 256 thr): out = Wo @ (F0+F1+F2) + bo (grid z=4)
// =====================================================================
__global__ void __launch_bounds__(256, 2) final_mma(
    const float* __restrict__ Wo, const float* __restrict__ bo,
    float* __restrict__ out)
{
    __shared__ float As[2][BK][BMP];
    __shared__ float Bs[2][BK][BMP];
    const int b  = blockIdx.z;
    const int o0 = blockIdx.y * BM;
    const int n0 = blockIdx.x * BN;
    const int tid = threadIdx.x;
    const int warp = tid >> 5, lane = tid & 31;
    const int g = lane >> 2, t = lane & 3;
    const int wm = (warp & 1) * 64, wn = (warp >> 1) * 32;
    const float* F0 = g_F3[0] + (size_t)b * CN;
    const float* F1 = g_F3[1] + (size_t)b * CN;
    const float* F2 = g_F3[2] + (size_t)b * CN;
    float* dst = out + (size_t)b * CN;

    const int arow = tid >> 1;
    const int akk0 = (tid & 1) * 8;
    const int bn4 = (tid & 31) * 4;
    const int bk0 = tid >> 5;

    DECL_ACC;

    float4 a_st[2], b_st[2];
    auto loadg = [&](int k0) {
#pragma unroll
        for (int r = 0; r < 2; r++)
            a_st[r] = *(const float4*)(Wo + (size_t)(o0 + arow) * Cdim + k0 + akk0 + r * 4);
#pragma unroll
        for (int r = 0; r < 2; r++) {
            size_t off = (size_t)(k0 + bk0 + r * 8) * Ndim + n0 + bn4;
            float4 v0 = *(const float4*)(F0 + off);
            float4 v1 = *(const float4*)(F1 + off);
            float4 v2 = *(const float4*)(F2 + off);
            v0.x += v1.x + v2.x; v0.y += v1.y + v2.y;
            v0.z += v1.z + v2.z; v0.w += v1.w + v2.w;
            b_st[r] = v0;
        }
    };
    auto storeg = [&](int buf) {
#pragma unroll
        for (int r = 0; r < 2; r++) {
            int kk = akk0 + r * 4;
            As[buf][kk + 0][arow] = f2tf32f(a_st[r].x);
            As[buf][kk + 1][arow] = f2tf32f(a_st[r].y);
            As[buf][kk + 2][arow] = f2tf32f(a_st[r].z);
            As[buf][kk + 3][arow] = f2tf32f(a_st[r].w);
        }
#pragma unroll
        for (int r = 0; r < 2; r++) {
            float4 v = b_st[r];
            v.x = f2tf32f(v.x); v.y = f2tf32f(v.y);
            v.z = f2tf32f(v.z); v.w = f2tf32f(v.w);
            *(float4*)(&Bs[buf][bk0 + r * 8][bn4]) = v;
        }
    };

    loadg(0); storeg(0); __syncthreads();
    int buf = 0;
    for (int k0 = 0; k0 < Cdim; k0 += BK) {
        bool more = (k0 + BK) < Cdim;
        if (more) loadg(k0 + BK);
        tile_mma(As[buf], Bs[buf], wm, wn, g, t, acc);
        if (more) storeg(buf ^ 1);
        __syncthreads();
        buf ^= 1;
    }

#pragma unroll
    for (int mi = 0; mi < 4; mi++)
#pragma unroll
        for (int r2 = 0; r2 < 2; r2++) {
            int o = o0 + wm + mi * 16 + g + r2 * 8;
            float bi = bo[o];
#pragma unroll
            for (int ni = 0; ni < 4; ni++) {
                int n = n0 + wn + ni * 8 + t * 2;
                size_t idx = (size_t)o * Ndim + n;
                dst[idx]     = acc[mi][ni][r2 * 2 + 0] + bi;
                dst[idx + 1] = acc[mi][ni][r2 * 2 + 1] + bi;
            }
        }
}

// =====================================================================
// launch
// =====================================================================
extern "C" void kernel_launch(void* const* d_in, const int* in_sizes, int n_in,
                              void* d_out, int out_size)
{
    const float* x[3] = { (const float*)d_in[0], (const float*)d_in[1], (const float*)d_in[2] };
    const float* s = (const float*)d_in[3];
    const float *wq[3], *bq[3], *wk[3], *bk[3], *wv[3], *bv[3];
    for (int m = 0; m < 3; m++) {
        wq[m] = (const float*)d_in[4 + 6 * m];
        bq[m] = (const float*)d_in[5 + 6 * m];
        wk[m] = (const float*)d_in[6 + 6 * m];
        bk[m] = (const float*)d_in[7 + 6 * m];
        wv[m] = (const float*)d_in[8 + 6 * m];
        bv[m] = (const float*)d_in[9 + 6 * m];
    }
    const float* wg = (const float*)d_in[22];
    const float* bg = (const float*)d_in[23];
    const float* wo = (const float*)d_in[24];
    const float* bo = (const float*)d_in[25];
    float* out = (float*)d_out;

    float *gP, *gW;
    cudaGetSymbolAddress((void**)&gP, g_P);
    cudaGetSymbolAddress((void**)&gW, g_W);

    float* Q[3]; float* K[3]; float* V[3]; float* Wout[3];
    for (int m = 0; m < 3; m++) {
        Q[m]    = gP + (size_t)(0 + m) * PLANE;
        K[m]    = gP + (size_t)(3 + m) * PLANE;
        V[m]    = gP + (size_t)(6 + m) * PLANE;
        Wout[m] = gW + (size_t)m * PLANE;
    }

    Proj9 P;
    for (int m = 0; m < 3; m++) {
        P.X[3 * m + 0] = x[m]; P.W[3 * m + 0] = wq[m]; P.B[3 * m + 0] = bq[m];
        P.D[3 * m + 0] = Q[m]; P.sidx[3 * m + 0] = m;
        P.X[3 * m + 1] = x[m]; P.W[3 * m + 1] = wk[m]; P.B[3 * m + 1] = bk[m];
        P.D[3 * m + 1] = K[m]; P.sidx[3 * m + 1] = m;
        P.X[3 * m + 2] = x[m]; P.W[3 * m + 2] = wv[m]; P.B[3 * m + 2] = bv[m];
        P.D[3 * m + 2] = V[m]; P.sidx[3 * m + 2] = -1;
    }

    // attends: w_rgb(Q0; K2+K1; V0), w_depth(Q2; K0+K1; V2), w_thermal(Q1; K0+K2; V1)
    Att3 A;
    const int qi[3]  = { 0, 2, 1 };
    const int kai[3] = { 2, 0, 0 };
    const int kbi[3] = { 1, 1, 2 };
    for (int a = 0; a < 3; a++) {
        A.Q[a]  = Q[qi[a]];
        A.Ka[a] = K[kai[a]];
        A.Kb[a] = K[kbi[a]];
        A.V[a]  = V[qi[a]];
        A.O[a]  = Wout[a];
    }

    dim3 blk(256);
    dim3 blk128(128);
    proj_mma9 <<<dim3(Ndim / BN, Cdim / BM, 36), blk>>>(P, s);
    scores_w64<<<dim3(Ndim / 128, Ndim / 128, 12), blk128>>>(A);
    softmax_kernel<<<dim3(3 * Bdim * Ndim), blk>>>();
    av_w64    <<<dim3(Ndim / 128, Cdim / 128, 12), blk128>>>(A);
    gate_mma3 <<<dim3(Ndim / BN, Cdim / BM, 12), blk>>>(wg, bg);
    final_mma <<<dim3(Ndim / BN, Cdim / BM, 4), blk>>>(wo, bo, out);
}

// round 8
// speedup vs baseline: 1.1143x; 1.0002x over previous
#include <cuda_runtime.h>
#include <cstdint>
#include <math.h>

#define Bdim 4
#define Cdim 256
#define Ndim 2304      // 48*48
#define PLANE (Bdim*Cdim*Ndim)
#define CN   (Cdim*Ndim)
#define NN   ((size_t)Ndim*Ndim)

#define BM 128
#define BN 128
#define BK 16
#define BMP 136        // [k][*] layout stride
#define AKP 20         // [m][k] / [n][k] layout stride (bank = 4m+k)

// ---- scratch ----
__device__ float g_P[9][PLANE];                      // Q0..2, K0..2, V0..2
__device__ float g_S3[(size_t)3 * Bdim * NN];        // scores for all 3 attends
__device__ float g_W[3][PLANE];                      // attention outputs
__device__ float g_F3[3][PLANE];                     // gated outputs

// ---- tf32 helpers ----
__device__ __forceinline__ float f2tf32f(float x) {
    uint32_t u;
    asm("cvt.rna.tf32.f32 %0, %1;" : "=r"(u) : "f"(x));
    return __uint_as_float(u);
}
__device__ __forceinline__ float4 cvt4(float4 v) {
    v.x = f2tf32f(v.x); v.y = f2tf32f(v.y);
    v.z = f2tf32f(v.z); v.w = f2tf32f(v.w);
    return v;
}

__device__ __forceinline__ void mma_tf32(float c[4], const uint32_t a[4], const uint32_t b[2]) {
    asm volatile(
        "mma.sync.aligned.m16n8k8.row.col.f32.tf32.tf32.f32 "
        "{%0,%1,%2,%3}, {%4,%5,%6,%7}, {%8,%9}, {%0,%1,%2,%3};"
        : "+f"(c[0]), "+f"(c[1]), "+f"(c[2]), "+f"(c[3])
        : "r"(a[0]), "r"(a[1]), "r"(a[2]), "r"(a[3]), "r"(b[0]), "r"(b[1]));
}

// A [k][m]136, B [k][n]136  (scores)
__device__ __forceinline__ void tile_mma_kk(
    const float (*As)[BMP], const float (*Bs)[BMP],
    int wm, int wn, int g, int t, float acc[4][4][4])
{
#pragma unroll
    for (int ks = 0; ks < BK; ks += 8) {
        uint32_t af[4][4], bf[4][2];
#pragma unroll
        for (int mi = 0; mi < 4; mi++) {
            int m = wm + mi * 16 + g;
            af[mi][0] = __float_as_uint(As[ks + t][m]);
            af[mi][1] = __float_as_uint(As[ks + t][m + 8]);
            af[mi][2] = __float_as_uint(As[ks + t + 4][m]);
            af[mi][3] = __float_as_uint(As[ks + t + 4][m + 8]);
        }
#pragma unroll
        for (int ni = 0; ni < 4; ni++) {
            int n = wn + ni * 8 + g;
            bf[ni][0] = __float_as_uint(Bs[ks + t][n]);
            bf[ni][1] = __float_as_uint(Bs[ks + t + 4][n]);
        }
#pragma unroll
        for (int mi = 0; mi < 4; mi++)
#pragma unroll
            for (int ni = 0; ni < 4; ni++)
                mma_tf32(acc[mi][ni], af[mi], bf[ni]);
    }
}

// A [m][k]20, B [k][n]136  (proj/gate/final)
__device__ __forceinline__ void tile_mma_mk_kn(
    const float (*As)[AKP], const float (*Bs)[BMP],
    int wm, int wn, int g, int t, float acc[4][4][4])
{
#pragma unroll
    for (int ks = 0; ks < BK; ks += 8) {
        uint32_t af[4][4], bf[4][2];
#pragma unroll
        for (int mi = 0; mi < 4; mi++) {
            int m = wm + mi * 16 + g;
            af[mi][0] = __float_as_uint(As[m][ks + t]);
            af[mi][1] = __float_as_uint(As[m + 8][ks + t]);
            af[mi][2] = __float_as_uint(As[m][ks + t + 4]);
            af[mi][3] = __float_as_uint(As[m + 8][ks + t + 4]);
        }
#pragma unroll
        for (int ni = 0; ni < 4; ni++) {
            int n = wn + ni * 8 + g;
            bf[ni][0] = __float_as_uint(Bs[ks + t][n]);
            bf[ni][1] = __float_as_uint(Bs[ks + t + 4][n]);
        }
#pragma unroll
        for (int mi = 0; mi < 4; mi++)
#pragma unroll
            for (int ni = 0; ni < 4; ni++)
                mma_tf32(acc[mi][ni], af[mi], bf[ni]);
    }
}

// A [m][k]20, B [n][k]20  (av)
__device__ __forceinline__ void tile_mma_mk_nk(
    const float (*As)[AKP], const float (*Bs)[AKP],
    int wm, int wn, int g, int t, float acc[4][4][4])
{
#pragma unroll
    for (int ks = 0; ks < BK; ks += 8) {
        uint32_t af[4][4], bf[4][2];
#pragma unroll
        for (int mi = 0; mi < 4; mi++) {
            int m = wm + mi * 16 + g;
            af[mi][0] = __float_as_uint(As[m][ks + t]);
            af[mi][1] = __float_as_uint(As[m + 8][ks + t]);
            af[mi][2] = __float_as_uint(As[m][ks + t + 4]);
            af[mi][3] = __float_as_uint(As[m + 8][ks + t + 4]);
        }
#pragma unroll
        for (int ni = 0; ni < 4; ni++) {
            int n = wn + ni * 8 + g;
            bf[ni][0] = __float_as_uint(Bs[n][ks + t]);
            bf[ni][1] = __float_as_uint(Bs[n][ks + t + 4]);
        }
#pragma unroll
        for (int mi = 0; mi < 4; mi++)
#pragma unroll
            for (int ni = 0; ni < 4; ni++)
                mma_tf32(acc[mi][ni], af[mi], bf[ni]);
    }
}

#define DECL_ACC float acc[4][4][4]; \
    _Pragma("unroll") for (int mi = 0; mi < 4; mi++) \
    _Pragma("unroll") for (int ni = 0; ni < 4; ni++) \
    _Pragma("unroll") for (int r = 0; r < 4; r++) acc[mi][ni][r] = 0.f;

// ---- batched arg structs ----
struct Proj9 {
    const float* X[9]; const float* W[9]; const float* B[9];
    float* D[9]; int sidx[9];
};
struct Att3 {
    const float* Q[3]; const float* Ka[3]; const float* Kb[3];
    const float* V[3]; float* O[3];
};

// =====================================================================
// batched proj: A=W [m][k], B=X [k][n].  z = job*4 + b (grid z = 36)
// threads 0-127 load A (1 row each), threads 128-255 load B.
// =====================================================================
__global__ void __launch_bounds__(256, 2) proj_mma9(Proj9 P, const float* __restrict__ s)
{
    __shared__ float As[2][BM][AKP];
    __shared__ float Bs[2][BK][BMP];
    const int z = blockIdx.z, job = z >> 2, b = z & 3;
    const int o0 = blockIdx.y * BM;
    const int n0 = blockIdx.x * BN;
    const int tid = threadIdx.x;
    const int warp = tid >> 5, lane = tid & 31;
    const int g = lane >> 2, t = lane & 3;
    const int wm = (warp & 1) * 64, wn = (warp >> 1) * 32;

    const float* Xb   = P.X[job] + (size_t)b * CN;
    const float* Wt   = P.W[job];
    const float* bias = P.B[job];
    float*       dst  = P.D[job] + (size_t)b * CN;
    const int   sidx  = P.sidx[job];

    const int u = tid & 127;
    const int kr = u >> 3, c4 = (u & 7) * 4;   // B loader coords

    DECL_ACC;

    float4 st[4];
    auto loadg = [&](int k0) {
        if (tid < 128) {
#pragma unroll
            for (int r = 0; r < 4; r++)
                st[r] = *(const float4*)(Wt + (size_t)(o0 + u) * Cdim + k0 + r * 4);
        } else {
#pragma unroll
            for (int r = 0; r < 4; r++)
                st[r] = *(const float4*)(Xb + (size_t)(k0 + kr) * Ndim + n0 + c4 + r * 32);
        }
    };
    auto storeg = [&](int buf) {
        if (tid < 128) {
#pragma unroll
            for (int r = 0; r < 4; r++)
                *(float4*)(&As[buf][u][r * 4]) = cvt4(st[r]);
        } else {
#pragma unroll
            for (int r = 0; r < 4; r++)
                *(float4*)(&Bs[buf][kr][c4 + r * 32]) = cvt4(st[r]);
        }
    };

    loadg(0); storeg(0); __syncthreads();
    int buf = 0;
    for (int k0 = 0; k0 < Cdim; k0 += BK) {
        bool more = (k0 + BK) < Cdim;
        if (more) loadg(k0 + BK);
        tile_mma_mk_kn(As[buf], Bs[buf], wm, wn, g, t, acc);
        if (more) storeg(buf ^ 1);
        __syncthreads();
        buf ^= 1;
    }

    const float scale = (sidx >= 0) ? s[sidx] : 1.f;
#pragma unroll
    for (int mi = 0; mi < 4; mi++)
#pragma unroll
        for (int r2 = 0; r2 < 2; r2++) {
            int m = o0 + wm + mi * 16 + g + r2 * 8;
            float bi = bias[m];
#pragma unroll
            for (int ni = 0; ni < 4; ni++) {
                int n = n0 + wn + ni * 8 + t * 2;
                size_t idx = (size_t)m * Ndim + n;
                dst[idx]     = (acc[mi][ni][r2 * 2 + 0] + bi) * scale;
                dst[idx + 1] = (acc[mi][ni][r2 * 2 + 1] + bi) * scale;
            }
        }
}

// =====================================================================
// batched scores (R4 form): A=Q [k][m], B=Ka+Kb [k][n]. grid z = 12
// =====================================================================
__global__ void __launch_bounds__(256, 2) scores_mma3(Att3 A)
{
    __shared__ float As[2][BK][BMP];
    __shared__ float Bs[2][BK][BMP];
    const int z = blockIdx.z, a = z >> 2, b = z & 3;
    const int y0 = blockIdx.y * BM;
    const int z0 = blockIdx.x * BN;
    const int tid = threadIdx.x;
    const int warp = tid >> 5, lane = tid & 31;
    const int g = lane >> 2, t = lane & 3;
    const int wm = (warp & 1) * 64, wn = (warp >> 1) * 32;
    const float* Qb  = A.Q[a]  + (size_t)b * CN;
    const float* Kab = A.Ka[a] + (size_t)b * CN;
    const float* Kbb = A.Kb[a] + (size_t)b * CN;

    const int n4 = (tid & 31) * 4;
    const int k0r = tid >> 5;

    DECL_ACC;

    float4 a_st[2], b_st[2];
    auto loadg = [&](int k0) {
#pragma unroll
        for (int r = 0; r < 2; r++) {
            size_t koff = (size_t)(k0 + k0r + r * 8) * Ndim;
            a_st[r] = *(const float4*)(Qb + koff + y0 + n4);
            float4 v1 = *(const float4*)(Kab + koff + z0 + n4);
            float4 v2 = *(const float4*)(Kbb + koff + z0 + n4);
            v1.x += v2.x; v1.y += v2.y; v1.z += v2.z; v1.w += v2.w;
            b_st[r] = v1;
        }
    };
    auto storeg = [&](int buf) {
#pragma unroll
        for (int r = 0; r < 2; r++) {
            *(float4*)(&As[buf][k0r + r * 8][n4]) = cvt4(a_st[r]);
            *(float4*)(&Bs[buf][k0r + r * 8][n4]) = cvt4(b_st[r]);
        }
    };

    loadg(0); storeg(0); __syncthreads();
    int buf = 0;
    for (int k0 = 0; k0 < Cdim; k0 += BK) {
        bool more = (k0 + BK) < Cdim;
        if (more) loadg(k0 + BK);
        tile_mma_kk(As[buf], Bs[buf], wm, wn, g, t, acc);
        if (more) storeg(buf ^ 1);
        __syncthreads();
        buf ^= 1;
    }

    float* Sb = g_S3 + (size_t)z * NN;
#pragma unroll
    for (int mi = 0; mi < 4; mi++)
#pragma unroll
        for (int r2 = 0; r2 < 2; r2++) {
            int y = y0 + wm + mi * 16 + g + r2 * 8;
#pragma unroll
            for (int ni = 0; ni < 4; ni++) {
                int zz = z0 + wn + ni * 8 + t * 2;
                size_t idx = (size_t)y * Ndim + zz;
                Sb[idx]     = acc[mi][ni][r2 * 2 + 0] * 0.0625f;
                Sb[idx + 1] = acc[mi][ni][r2 * 2 + 1] * 0.0625f;
            }
        }
}

// =====================================================================
// softmax (one block per row)
// =====================================================================
__global__ void __launch_bounds__(256) softmax_kernel()
{
    const size_t row = blockIdx.x;
    float* p = g_S3 + row * Ndim;
    const int tid = threadIdx.x;
    const int warp = tid >> 5, lane = tid & 31;
    __shared__ float red[8];

    float v[9];
#pragma unroll
    for (int i = 0; i < 9; i++) v[i] = p[tid + i * 256];

    float mx = v[0];
#pragma unroll
    for (int i = 1; i < 9; i++) mx = fmaxf(mx, v[i]);
#pragma unroll
    for (int off = 16; off > 0; off >>= 1)
        mx = fmaxf(mx, __shfl_xor_sync(0xffffffffu, mx, off));
    if (lane == 0) red[warp] = mx;
    __syncthreads();
    if (warp == 0) {
        float m2 = red[lane & 7];
#pragma unroll
        for (int off = 4; off > 0; off >>= 1)
            m2 = fmaxf(m2, __shfl_xor_sync(0xffffffffu, m2, off));
        if (lane == 0) red[0] = m2;
    }
    __syncthreads();
    mx = red[0];

    float sum = 0.f;
#pragma unroll
    for (int i = 0; i < 9; i++) { v[i] = __expf(v[i] - mx); sum += v[i]; }
#pragma unroll
    for (int off = 16; off > 0; off >>= 1)
        sum += __shfl_xor_sync(0xffffffffu, sum, off);
    __syncthreads();
    if (lane == 0) red[warp] = sum;
    __syncthreads();
    if (warp == 0) {
        float s2 = red[lane & 7];
#pragma unroll
        for (int off = 4; off > 0; off >>= 1)
            s2 += __shfl_xor_sync(0xffffffffu, s2, off);
        if (lane == 0) red[0] = s2;
    }
    __syncthreads();
    const float inv = 1.f / red[0];
#pragma unroll
    for (int i = 0; i < 9; i++) p[tid + i * 256] = v[i] * inv;
}

// =====================================================================
// batched AV: A=V [c][k], B=S [n][k], both stride-20, conflict-free.
// threads 0-127 load A rows, 128-255 load B rows. grid z = 12
// dst[c][n] = sum_m V[c][m] * S[n][m]
// =====================================================================
__global__ void __launch_bounds__(256, 2) av_mma3(Att3 A)
{
    __shared__ float As[2][BM][AKP];
    __shared__ float Bs[2][BN][AKP];
    const int z = blockIdx.z, a = z >> 2, b = z & 3;
    const int c0 = blockIdx.y * BM;
    const int n0 = blockIdx.x * BN;
    const int tid = threadIdx.x;
    const int warp = tid >> 5, lane = tid & 31;
    const int g = lane >> 2, t = lane & 3;
    const int wm = (warp & 1) * 64, wn = (warp >> 1) * 32;
    const float* Vb = A.V[a] + (size_t)b * CN;
    const float* Sb = g_S3 + (size_t)z * NN;
    float*      dst = A.O[a] + (size_t)b * CN;

    const int u = tid & 127;   // row within tile

    DECL_ACC;

    float4 st[4];
    auto loadg = [&](int k0) {
        const float* gsrc = (tid < 128)
            ? (Vb + (size_t)(c0 + u) * Ndim + k0)
            : (Sb + (size_t)(n0 + u) * Ndim + k0);
#pragma unroll
        for (int r = 0; r < 4; r++)
            st[r] = *(const float4*)(gsrc + r * 4);
    };
    auto storeg = [&](int buf) {
        float* srow = (tid < 128) ? &As[buf][u][0] : &Bs[buf][u][0];
#pragma unroll
        for (int r = 0; r < 4; r++)
            *(float4*)(srow + r * 4) = cvt4(st[r]);
    };

    loadg(0); storeg(0); __syncthreads();
    int buf = 0;
    for (int k0 = 0; k0 < Ndim; k0 += BK) {
        bool more = (k0 + BK) < Ndim;
        if (more) loadg(k0 + BK);
        tile_mma_mk_nk(As[buf], Bs[buf], wm, wn, g, t, acc);
        if (more) storeg(buf ^ 1);
        __syncthreads();
        buf ^= 1;
    }

#pragma unroll
    for (int mi = 0; mi < 4; mi++)
#pragma unroll
        for (int r2 = 0; r2 < 2; r2++) {
            int c = c0 + wm + mi * 16 + g + r2 * 8;
#pragma unroll
            for (int ni = 0; ni < 4; ni++) {
                int n = n0 + wn + ni * 8 + t * 2;
                size_t idx = (size_t)c * Ndim + n;
                dst[idx]     = acc[mi][ni][r2 * 2 + 0];
                dst[idx + 1] = acc[mi][ni][r2 * 2 + 1];
            }
        }
}

// =====================================================================
// batched gate: A=Wg [m][k], B=g_W[a] [k][n]. grid z = 12
// =====================================================================
__global__ void __launch_bounds__(256, 2) gate_mma3(
    const float* __restrict__ Wg, const float* __restrict__ bg)
{
    __shared__ float As[2][BM][AKP];
    __shared__ float Bs[2][BK][BMP];
    const int z = blockIdx.z, a = z >> 2, b = z & 3;
    const int o0 = blockIdx.y * BM;
    const int n0 = blockIdx.x * BN;
    const int tid = threadIdx.x;
    const int warp = tid >> 5, lane = tid & 31;
    const int g = lane >> 2, t = lane & 3;
    const int wm = (warp & 1) * 64, wn = (warp >> 1) * 32;
    const float* Xb = g_W[a] + (size_t)b * CN;
    float*       F  = g_F3[a] + (size_t)b * CN;

    const int u = tid & 127;
    const int kr = u >> 3, c4 = (u & 7) * 4;

    DECL_ACC;

    float4 st[4];
    auto loadg = [&](int k0) {
        if (tid < 128) {
#pragma unroll
            for (int r = 0; r < 4; r++)
                st[r] = *(const float4*)(Wg + (size_t)(o0 + u) * Cdim + k0 + r * 4);
        } else {
#pragma unroll
            for (int r = 0; r < 4; r++)
                st[r] = *(const float4*)(Xb + (size_t)(k0 + kr) * Ndim + n0 + c4 + r * 32);
        }
    };
    auto storeg = [&](int buf) {
        if (tid < 128) {
#pragma unroll
            for (int r = 0; r < 4; r++)
                *(float4*)(&As[buf][u][r * 4]) = cvt4(st[r]);
        } else {
#pragma unroll
            for (int r = 0; r < 4; r++)
                *(float4*)(&Bs[buf][kr][c4 + r * 32]) = cvt4(st[r]);
        }
    };

    loadg(0); storeg(0); __syncthreads();
    int buf = 0;
    for (int k0 = 0; k0 < Cdim; k0 += BK) {
        bool more = (k0 + BK) < Cdim;
        if (more) loadg(k0 + BK);
        tile_mma_mk_kn(As[buf], Bs[buf], wm, wn, g, t, acc);
        if (more) storeg(buf ^ 1);
        __syncthreads();
        buf ^= 1;
    }

#pragma unroll
    for (int mi = 0; mi < 4; mi++)
#pragma unroll
        for (int r2 = 0; r2 < 2; r2++) {
            int o = o0 + wm + mi * 16 + g + r2 * 8;
            float bi = bg[o];
#pragma unroll
            for (int ni = 0; ni < 4; ni++) {
                int n = n0 + wn + ni * 8 + t * 2;
                size_t idx = (size_t)o * Ndim + n;
#pragma unroll
                for (int e = 0; e < 2; e++) {
                    float gv  = acc[mi][ni][r2 * 2 + e] + bi;
                    float sig = 1.f / (1.f + __expf(-gv));
                    F[idx + e] = sig * Xb[idx + e];
                }
            }
        }
}

// =====================================================================
// final conv: A=Wo [m][k], B=(F0+F1+F2) [k][n]. grid z = 4
// =====================================================================
__global__ void __launch_bounds__(256, 2) final_mma(
    const float* __restrict__ Wo, const float* __restrict__ bo,
    float* __restrict__ out)
{
    __shared__ float As[2][BM][AKP];
    __shared__ float Bs[2][BK][BMP];
    const int b  = blockIdx.z;
    const int o0 = blockIdx.y * BM;
    const int n0 = blockIdx.x * BN;
    const int tid = threadIdx.x;
    const int warp = tid >> 5, lane = tid & 31;
    const int g = lane >> 2, t = lane & 3;
    const int wm = (warp & 1) * 64, wn = (warp >> 1) * 32;
    const float* F0 = g_F3[0] + (size_t)b * CN;
    const float* F1 = g_F3[1] + (size_t)b * CN;
    const float* F2 = g_F3[2] + (size_t)b * CN;
    float* dst = out + (size_t)b * CN;

    const int u = tid & 127;
    const int kr = u >> 3, c4 = (u & 7) * 4;

    DECL_ACC;

    float4 st[4];
    auto loadg = [&](int k0) {
        if (tid < 128) {
#pragma unroll
            for (int r = 0; r < 4; r++)
                st[r] = *(const float4*)(Wo + (size_t)(o0 + u) * Cdim + k0 + r * 4);
        } else {
#pragma unroll
            for (int r = 0; r < 4; r++) {
                size_t off = (size_t)(k0 + kr) * Ndim + n0 + c4 + r * 32;
                float4 v0 = *(const float4*)(F0 + off);
                float4 v1 = *(const float4*)(F1 + off);
                float4 v2 = *(const float4*)(F2 + off);
                v0.x += v1.x + v2.x; v0.y += v1.y + v2.y;
                v0.z += v1.z + v2.z; v0.w += v1.w + v2.w;
                st[r] = v0;
            }
        }
    };
    auto storeg = [&](int buf) {
        if (tid < 128) {
#pragma unroll
            for (int r = 0; r < 4; r++)
                *(float4*)(&As[buf][u][r * 4]) = cvt4(st[r]);
        } else {
#pragma unroll
            for (int r = 0; r < 4; r++)
                *(float4*)(&Bs[buf][kr][c4 + r * 32]) = cvt4(st[r]);
        }
    };

    loadg(0); storeg(0); __syncthreads();
    int buf = 0;
    for (int k0 = 0; k0 < Cdim; k0 += BK) {
        bool more = (k0 + BK) < Cdim;
        if (more) loadg(k0 + BK);
        tile_mma_mk_kn(As[buf], Bs[buf], wm, wn, g, t, acc);
        if (more) storeg(buf ^ 1);
        __syncthreads();
        buf ^= 1;
    }

#pragma unroll
    for (int mi = 0; mi < 4; mi++)
#pragma unroll
        for (int r2 = 0; r2 < 2; r2++) {
            int o = o0 + wm + mi * 16 + g + r2 * 8;
            float bi = bo[o];
#pragma unroll
            for (int ni = 0; ni < 4; ni++) {
                int n = n0 + wn + ni * 8 + t * 2;
                size_t idx = (size_t)o * Ndim + n;
                dst[idx]     = acc[mi][ni][r2 * 2 + 0] + bi;
                dst[idx + 1] = acc[mi][ni][r2 * 2 + 1] + bi;
            }
        }
}

// =====================================================================
// launch
// =====================================================================
extern "C" void kernel_launch(void* const* d_in, const int* in_sizes, int n_in,
                              void* d_out, int out_size)
{
    const float* x[3] = { (const float*)d_in[0], (const float*)d_in[1], (const float*)d_in[2] };
    const float* s = (const float*)d_in[3];
    const float *wq[3], *bq[3], *wk[3], *bk[3], *wv[3], *bv[3];
    for (int m = 0; m < 3; m++) {
        wq[m] = (const float*)d_in[4 + 6 * m];
        bq[m] = (const float*)d_in[5 + 6 * m];
        wk[m] = (const float*)d_in[6 + 6 * m];
        bk[m] = (const float*)d_in[7 + 6 * m];
        wv[m] = (const float*)d_in[8 + 6 * m];
        bv[m] = (const float*)d_in[9 + 6 * m];
    }
    const float* wg = (const float*)d_in[22];
    const float* bg = (const float*)d_in[23];
    const float* wo = (const float*)d_in[24];
    const float* bo = (const float*)d_in[25];
    float* out = (float*)d_out;

    float *gP, *gW;
    cudaGetSymbolAddress((void**)&gP, g_P);
    cudaGetSymbolAddress((void**)&gW, g_W);

    float* Q[3]; float* K[3]; float* V[3]; float* Wout[3];
    for (int m = 0; m < 3; m++) {
        Q[m]    = gP + (size_t)(0 + m) * PLANE;
        K[m]    = gP + (size_t)(3 + m) * PLANE;
        V[m]    = gP + (size_t)(6 + m) * PLANE;
        Wout[m] = gW + (size_t)m * PLANE;
    }

    Proj9 P;
    for (int m = 0; m < 3; m++) {
        P.X[3 * m + 0] = x[m]; P.W[3 * m + 0] = wq[m]; P.B[3 * m + 0] = bq[m];
        P.D[3 * m + 0] = Q[m]; P.sidx[3 * m + 0] = m;
        P.X[3 * m + 1] = x[m]; P.W[3 * m + 1] = wk[m]; P.B[3 * m + 1] = bk[m];
        P.D[3 * m + 1] = K[m]; P.sidx[3 * m + 1] = m;
        P.X[3 * m + 2] = x[m]; P.W[3 * m + 2] = wv[m]; P.B[3 * m + 2] = bv[m];
        P.D[3 * m + 2] = V[m]; P.sidx[3 * m + 2] = -1;
    }

    // attends: w_rgb(Q0; K2+K1; V0), w_depth(Q2; K0+K1; V2), w_thermal(Q1; K0+K2; V1)
    Att3 A;
    const int qi[3]  = { 0, 2, 1 };
    const int kai[3] = { 2, 0, 0 };
    const int kbi[3] = { 1, 1, 2 };
    for (int a = 0; a < 3; a++) {
        A.Q[a]  = Q[qi[a]];
        A.Ka[a] = K[kai[a]];
        A.Kb[a] = K[kbi[a]];
        A.V[a]  = V[qi[a]];
        A.O[a]  = Wout[a];
    }

    dim3 blk(256);
    proj_mma9 <<<dim3(Ndim / BN, Cdim / BM, 36), blk>>>(P, s);
    scores_mma3<<<dim3(Ndim / BN, Ndim / BM, 12), blk>>>(A);
    softmax_kernel<<<dim3(3 * Bdim * Ndim), blk>>>();
    av_mma3   <<<dim3(Ndim / BN, Cdim / BM, 12), blk>>>(A);
    gate_mma3 <<<dim3(Ndim / BN, Cdim / BM, 12), blk>>>(wg, bg);
    final_mma <<<dim3(Ndim / BN, Cdim / BM, 4), blk>>>(wo, bo, out);
}

// round 9
// speedup vs baseline: 1.6112x; 1.4460x over previous
#include <cuda_runtime.h>
#include <cstdint>
#include <math.h>

#define Bdim 4
#define Cdim 256
#define Ndim 2304      // 48*48
#define PLANE (Bdim*Cdim*Ndim)
#define CN   (Cdim*Ndim)
#define NN   ((size_t)Ndim*Ndim)

#define BM 128
#define BN 128
#define BK 16
#define BMP 136        // [k][*] layout stride
#define AKP 36         // [row][k] layout stride for BK=32 tiles (36 mod 32 = 4)

// ---- scratch ----
__device__ float g_P[9][PLANE];                      // Q0..2, K0..2, V0..2
__device__ float g_S3[(size_t)3 * Bdim * NN];        // scores / probs
__device__ float g_W[3][PLANE];                      // attention outputs
__device__ float g_F3[3][PLANE];                     // Ksums (early) then gated outputs

// ---- tf32 helpers ----
__device__ __forceinline__ float f2tf32f(float x) {
    uint32_t u;
    asm("cvt.rna.tf32.f32 %0, %1;" : "=r"(u) : "f"(x));
    return __uint_as_float(u);
}
__device__ __forceinline__ float4 cvt4(float4 v) {
    v.x = f2tf32f(v.x); v.y = f2tf32f(v.y);
    v.z = f2tf32f(v.z); v.w = f2tf32f(v.w);
    return v;
}

__device__ __forceinline__ void mma_tf32(float c[4], const uint32_t a[4], const uint32_t b[2]) {
    asm volatile(
        "mma.sync.aligned.m16n8k8.row.col.f32.tf32.tf32.f32 "
        "{%0,%1,%2,%3}, {%4,%5,%6,%7}, {%8,%9}, {%0,%1,%2,%3};"
        : "+f"(c[0]), "+f"(c[1]), "+f"(c[2]), "+f"(c[3])
        : "r"(a[0]), "r"(a[1]), "r"(a[2]), "r"(a[3]), "r"(b[0]), "r"(b[1]));
}

// ---- cp.async ----
__device__ __forceinline__ uint32_t smem_cast(const void* p) {
    return (uint32_t)__cvta_generic_to_shared(p);
}
#define CP_ASYNC16(dst_u32, gptr) \
    asm volatile("cp.async.cg.shared.global [%0], [%1], 16;" :: "r"(dst_u32), "l"(gptr))
#define CP_COMMIT() asm volatile("cp.async.commit_group;" ::: "memory")
#define CP_WAIT1()  asm volatile("cp.async.wait_group 1;" ::: "memory")
#define CP_WAIT0()  asm volatile("cp.async.wait_group 0;" ::: "memory")

// ---- MMA tile cores ----
// BK=16, A [k][m]136, B [k][n]136 (proj/gate/final B-side; also their A via variant below)
__device__ __forceinline__ void tile_mma_kk16(
    const float (*As)[BMP], const float (*Bs)[BMP],
    int wm, int wn, int g, int t, float acc[4][4][4])
{
#pragma unroll
    for (int ks = 0; ks < BK; ks += 8) {
        uint32_t af[4][4], bf[4][2];
#pragma unroll
        for (int mi = 0; mi < 4; mi++) {
            int m = wm + mi * 16 + g;
            af[mi][0] = __float_as_uint(As[ks + t][m]);
            af[mi][1] = __float_as_uint(As[ks + t][m + 8]);
            af[mi][2] = __float_as_uint(As[ks + t + 4][m]);
            af[mi][3] = __float_as_uint(As[ks + t + 4][m + 8]);
        }
#pragma unroll
        for (int ni = 0; ni < 4; ni++) {
            int n = wn + ni * 8 + g;
            bf[ni][0] = __float_as_uint(Bs[ks + t][n]);
            bf[ni][1] = __float_as_uint(Bs[ks + t + 4][n]);
        }
#pragma unroll
        for (int mi = 0; mi < 4; mi++)
#pragma unroll
            for (int ni = 0; ni < 4; ni++)
                mma_tf32(acc[mi][ni], af[mi], bf[ni]);
    }
}

// BK=32, A [k][m]136, B [k][n]136 (scores)
__device__ __forceinline__ void tile_mma_kk32(
    const float (*As)[BMP], const float (*Bs)[BMP],
    int wm, int wn, int g, int t, float acc[4][4][4])
{
#pragma unroll
    for (int ks = 0; ks < 32; ks += 8) {
        uint32_t af[4][4], bf[4][2];
#pragma unroll
        for (int mi = 0; mi < 4; mi++) {
            int m = wm + mi * 16 + g;
            af[mi][0] = __float_as_uint(As[ks + t][m]);
            af[mi][1] = __float_as_uint(As[ks + t][m + 8]);
            af[mi][2] = __float_as_uint(As[ks + t + 4][m]);
            af[mi][3] = __float_as_uint(As[ks + t + 4][m + 8]);
        }
#pragma unroll
        for (int ni = 0; ni < 4; ni++) {
            int n = wn + ni * 8 + g;
            bf[ni][0] = __float_as_uint(Bs[ks + t][n]);
            bf[ni][1] = __float_as_uint(Bs[ks + t + 4][n]);
        }
#pragma unroll
        for (int mi = 0; mi < 4; mi++)
#pragma unroll
            for (int ni = 0; ni < 4; ni++)
                mma_tf32(acc[mi][ni], af[mi], bf[ni]);
    }
}

// BK=32, A [m][k]36, B [n][k]36 (av)
__device__ __forceinline__ void tile_mma_rk32(
    const float (*As)[AKP], const float (*Bs)[AKP],
    int wm, int wn, int g, int t, float acc[4][4][4])
{
#pragma unroll
    for (int ks = 0; ks < 32; ks += 8) {
        uint32_t af[4][4], bf[4][2];
#pragma unroll
        for (int mi = 0; mi < 4; mi++) {
            int m = wm + mi * 16 + g;
            af[mi][0] = __float_as_uint(As[m][ks + t]);
            af[mi][1] = __float_as_uint(As[m + 8][ks + t]);
            af[mi][2] = __float_as_uint(As[m][ks + t + 4]);
            af[mi][3] = __float_as_uint(As[m + 8][ks + t + 4]);
        }
#pragma unroll
        for (int ni = 0; ni < 4; ni++) {
            int n = wn + ni * 8 + g;
            bf[ni][0] = __float_as_uint(Bs[n][ks + t]);
            bf[ni][1] = __float_as_uint(Bs[n][ks + t + 4]);
        }
#pragma unroll
        for (int mi = 0; mi < 4; mi++)
#pragma unroll
            for (int ni = 0; ni < 4; ni++)
                mma_tf32(acc[mi][ni], af[mi], bf[ni]);
    }
}

#define DECL_ACC float acc[4][4][4]; \
    _Pragma("unroll") for (int mi = 0; mi < 4; mi++) \
    _Pragma("unroll") for (int ni = 0; ni < 4; ni++) \
    _Pragma("unroll") for (int r = 0; r < 4; r++) acc[mi][ni][r] = 0.f;

// ---- batched arg structs ----
struct Proj9 {
    const float* X[9]; const float* W[9]; const float* B[9];
    float* D[9]; int sidx[9]; int rnd[9];
};
struct Att3 {
    const float* Q[3]; const float* KS[3]; const float* V[3]; float* O[3];
};

// =====================================================================
// batched proj (R4 form + optional tf32 rounding of output)
// z = job*4 + b (grid z = 36)
// =====================================================================
__global__ void __launch_bounds__(256, 2) proj_mma9(Proj9 P, const float* __restrict__ s)
{
    __shared__ float As[2][BK][BMP];
    __shared__ float Bs[2][BK][BMP];
    const int z = blockIdx.z, job = z >> 2, b = z & 3;
    const int o0 = blockIdx.y * BM;
    const int n0 = blockIdx.x * BN;
    const int tid = threadIdx.x;
    const int warp = tid >> 5, lane = tid & 31;
    const int g = lane >> 2, t = lane & 3;
    const int wm = (warp & 1) * 64, wn = (warp >> 1) * 32;

    const float* Xb   = P.X[job] + (size_t)b * CN;
    const float* Wt   = P.W[job];
    const float* bias = P.B[job];
    float*       dst  = P.D[job] + (size_t)b * CN;
    const int   sidx  = P.sidx[job];
    const int   rnd   = P.rnd[job];

    const int arow = tid >> 1;
    const int akk0 = (tid & 1) * 8;
    const int bn4 = (tid & 31) * 4;
    const int bk0 = tid >> 5;

    DECL_ACC;

    float4 a_st[2], b_st[2];
    auto loadg = [&](int k0) {
#pragma unroll
        for (int r = 0; r < 2; r++)
            a_st[r] = *(const float4*)(Wt + (size_t)(o0 + arow) * Cdim + k0 + akk0 + r * 4);
#pragma unroll
        for (int r = 0; r < 2; r++)
            b_st[r] = *(const float4*)(Xb + (size_t)(k0 + bk0 + r * 8) * Ndim + n0 + bn4);
    };
    auto storeg = [&](int buf) {
#pragma unroll
        for (int r = 0; r < 2; r++) {
            int kk = akk0 + r * 4;
            As[buf][kk + 0][arow] = f2tf32f(a_st[r].x);
            As[buf][kk + 1][arow] = f2tf32f(a_st[r].y);
            As[buf][kk + 2][arow] = f2tf32f(a_st[r].z);
            As[buf][kk + 3][arow] = f2tf32f(a_st[r].w);
        }
#pragma unroll
        for (int r = 0; r < 2; r++)
            *(float4*)(&Bs[buf][bk0 + r * 8][bn4]) = cvt4(b_st[r]);
    };

    loadg(0); storeg(0); __syncthreads();
    int buf = 0;
    for (int k0 = 0; k0 < Cdim; k0 += BK) {
        bool more = (k0 + BK) < Cdim;
        if (more) loadg(k0 + BK);
        tile_mma_kk16(As[buf], Bs[buf], wm, wn, g, t, acc);
        if (more) storeg(buf ^ 1);
        __syncthreads();
        buf ^= 1;
    }

    const float scale = (sidx >= 0) ? s[sidx] : 1.f;
#pragma unroll
    for (int mi = 0; mi < 4; mi++)
#pragma unroll
        for (int r2 = 0; r2 < 2; r2++) {
            int m = o0 + wm + mi * 16 + g + r2 * 8;
            float bi = bias[m];
#pragma unroll
            for (int ni = 0; ni < 4; ni++) {
                int n = n0 + wn + ni * 8 + t * 2;
                size_t idx = (size_t)m * Ndim + n;
                float v0 = (acc[mi][ni][r2 * 2 + 0] + bi) * scale;
                float v1 = (acc[mi][ni][r2 * 2 + 1] + bi) * scale;
                if (rnd) { v0 = f2tf32f(v0); v1 = f2tf32f(v1); }
                dst[idx]     = v0;
                dst[idx + 1] = v1;
            }
        }
}

// =====================================================================
// ksum3: KS[a] = cvt(Ka + Kb) elementwise; PLANE divisible by 1024
// =====================================================================
__global__ void __launch_bounds__(256) ksum3_kernel(
    const float* __restrict__ K0, const float* __restrict__ K1,
    const float* __restrict__ K2,
    float* __restrict__ S0, float* __restrict__ S1, float* __restrict__ S2)
{
    size_t i = ((size_t)blockIdx.x * 256 + threadIdx.x) * 4;
    float4 a = *(const float4*)(K0 + i);
    float4 b = *(const float4*)(K1 + i);
    float4 c = *(const float4*)(K2 + i);
    float4 r;
    // S0 = K2+K1, S1 = K0+K1, S2 = K0+K2
    r.x = c.x + b.x; r.y = c.y + b.y; r.z = c.z + b.z; r.w = c.w + b.w;
    *(float4*)(S0 + i) = cvt4(r);
    r.x = a.x + b.x; r.y = a.y + b.y; r.z = a.z + b.z; r.w = a.w + b.w;
    *(float4*)(S1 + i) = cvt4(r);
    r.x = a.x + c.x; r.y = a.y + c.y; r.z = a.z + c.z; r.w = a.w + c.w;
    *(float4*)(S2 + i) = cvt4(r);
}

// =====================================================================
// batched scores via cp.async, BK=32: S3[z][y][m] = (1/16) Qᵀ Ksum
// z = attend*4 + b (grid z = 12). Inputs pre-rounded tf32.
// =====================================================================
__global__ void __launch_bounds__(256, 2) scores_cp(Att3 A)
{
    extern __shared__ float dyn[];
    float (*As)[32][BMP] = (float(*)[32][BMP])dyn;
    float (*Bs)[32][BMP] = (float(*)[32][BMP])(dyn + 2 * 32 * BMP);

    const int z = blockIdx.z, a = z >> 2, b = z & 3;
    const int y0 = blockIdx.y * BM;
    const int z0 = blockIdx.x * BN;
    const int tid = threadIdx.x;
    const int warp = tid >> 5, lane = tid & 31;
    const int g = lane >> 2, t = lane & 3;
    const int wm = (warp & 1) * 64, wn = (warp >> 1) * 32;
    const float* Qb = A.Q[a]  + (size_t)b * CN;
    const float* Kb = A.KS[a] + (size_t)b * CN;

    // loader: 128 threads per tile; r0 = base k-row, cc = 16B chunk in row
    const int u = tid & 127;
    const int r0 = u >> 3;        // 0..15
    const int cc = u & 7;         // 0..7
    const bool isB = (tid >= 128);
    const float* gsrc = isB ? (Kb + z0) : (Qb + y0);

    auto prefetch = [&](int buf, int k0) {
#pragma unroll
        for (int r = 0; r < 2; r++) {
            int krow = r0 + 16 * r;
            const float* gp = gsrc + (size_t)(k0 + krow) * Ndim + cc * 4;
            float* sp = isB ? &Bs[buf][krow][cc * 4] : &As[buf][krow][cc * 4];
#pragma unroll
            for (int j = 0; j < 4; j++)
                CP_ASYNC16(smem_cast(sp + j * 32), gp + j * 32);
        }
        CP_COMMIT();
    };

    DECL_ACC;

    prefetch(0, 0);
    prefetch(1, 32);
    const int NIT = Cdim / 32;   // 8
    for (int it = 0; it < NIT; it++) {
        int buf = it & 1;
        if (it == NIT - 1) CP_WAIT0(); else CP_WAIT1();
        __syncthreads();
        tile_mma_kk32(As[buf], Bs[buf], wm, wn, g, t, acc);
        __syncthreads();
        if (it + 2 < NIT) prefetch(buf, (it + 2) * 32);
    }

    float* Sb = g_S3 + (size_t)z * NN;
#pragma unroll
    for (int mi = 0; mi < 4; mi++)
#pragma unroll
        for (int r2 = 0; r2 < 2; r2++) {
            int y = y0 + wm + mi * 16 + g + r2 * 8;
#pragma unroll
            for (int ni = 0; ni < 4; ni++) {
                int zz = z0 + wn + ni * 8 + t * 2;
                size_t idx = (size_t)y * Ndim + zz;
                Sb[idx]     = acc[mi][ni][r2 * 2 + 0] * 0.0625f;
                Sb[idx + 1] = acc[mi][ni][r2 * 2 + 1] * 0.0625f;
            }
        }
}

// =====================================================================
// softmax (one block per row); writes tf32-rounded probabilities
// =====================================================================
__global__ void __launch_bounds__(256) softmax_kernel()
{
    const size_t row = blockIdx.x;
    float* p = g_S3 + row * Ndim;
    const int tid = threadIdx.x;
    const int warp = tid >> 5, lane = tid & 31;
    __shared__ float red[8];

    float v[9];
#pragma unroll
    for (int i = 0; i < 9; i++) v[i] = p[tid + i * 256];

    float mx = v[0];
#pragma unroll
    for (int i = 1; i < 9; i++) mx = fmaxf(mx, v[i]);
#pragma unroll
    for (int off = 16; off > 0; off >>= 1)
        mx = fmaxf(mx, __shfl_xor_sync(0xffffffffu, mx, off));
    if (lane == 0) red[warp] = mx;
    __syncthreads();
    if (warp == 0) {
        float m2 = red[lane & 7];
#pragma unroll
        for (int off = 4; off > 0; off >>= 1)
            m2 = fmaxf(m2, __shfl_xor_sync(0xffffffffu, m2, off));
        if (lane == 0) red[0] = m2;
    }
    __syncthreads();
    mx = red[0];

    float sum = 0.f;
#pragma unroll
    for (int i = 0; i < 9; i++) { v[i] = __expf(v[i] - mx); sum += v[i]; }
#pragma unroll
    for (int off = 16; off > 0; off >>= 1)
        sum += __shfl_xor_sync(0xffffffffu, sum, off);
    __syncthreads();
    if (lane == 0) red[warp] = sum;
    __syncthreads();
    if (warp == 0) {
        float s2 = red[lane & 7];
#pragma unroll
        for (int off = 4; off > 0; off >>= 1)
            s2 += __shfl_xor_sync(0xffffffffu, s2, off);
        if (lane == 0) red[0] = s2;
    }
    __syncthreads();
    const float inv = 1.f / red[0];
#pragma unroll
    for (int i = 0; i < 9; i++) p[tid + i * 256] = f2tf32f(v[i] * inv);
}

// =====================================================================
// batched AV via cp.async, BK=32: dst[c][n] = sum_m V[c][m] P[n][m]
// A=V [c][k]36, B=P [n][k]36. z = attend*4 + b (grid z = 12)
// =====================================================================
__global__ void __launch_bounds__(256, 2) av_cp(Att3 A)
{
    extern __shared__ float dyn[];
    float (*As)[BM][AKP] = (float(*)[BM][AKP])dyn;
    float (*Bs)[BN][AKP] = (float(*)[BN][AKP])(dyn + 2 * BM * AKP);

    const int z = blockIdx.z, a = z >> 2, b = z & 3;
    const int c0 = blockIdx.y * BM;
    const int n0 = blockIdx.x * BN;
    const int tid = threadIdx.x;
    const int warp = tid >> 5, lane = tid & 31;
    const int g = lane >> 2, t = lane & 3;
    const int wm = (warp & 1) * 64, wn = (warp >> 1) * 32;
    const float* Vb = A.V[a] + (size_t)b * CN;
    const float* Pb = g_S3 + (size_t)z * NN;
    float*      dst = A.O[a] + (size_t)b * CN;

    // loader: r0 = base row, cc = 16B chunk within 128B k-span
    const int u = tid & 127;
    const int r0 = u >> 3;        // 0..15
    const int cc = u & 7;         // 0..7
    const bool isB = (tid >= 128);
    const float* gbase = isB
        ? Pb + (size_t)(n0 + r0) * Ndim + cc * 4
        : Vb + (size_t)(c0 + r0) * Ndim + cc * 4;

    auto prefetch = [&](int buf, int k0) {
        const float* gp = gbase + k0;
        float* sp = isB ? &Bs[buf][r0][cc * 4] : &As[buf][r0][cc * 4];
#pragma unroll
        for (int r = 0; r < 8; r++)
            CP_ASYNC16(smem_cast(sp + (size_t)r * 16 * AKP),
                       gp + (size_t)r * 16 * Ndim);
        CP_COMMIT();
    };

    DECL_ACC;

    prefetch(0, 0);
    prefetch(1, 32);
    const int NIT = Ndim / 32;   // 72
    for (int it = 0; it < NIT; it++) {
        int buf = it & 1;
        if (it == NIT - 1) CP_WAIT0(); else CP_WAIT1();
        __syncthreads();
        tile_mma_rk32(As[buf], Bs[buf], wm, wn, g, t, acc);
        __syncthreads();
        if (it + 2 < NIT) prefetch(buf, (it + 2) * 32);
    }

#pragma unroll
    for (int mi = 0; mi < 4; mi++)
#pragma unroll
        for (int r2 = 0; r2 < 2; r2++) {
            int c = c0 + wm + mi * 16 + g + r2 * 8;
#pragma unroll
            for (int ni = 0; ni < 4; ni++) {
                int n = n0 + wn + ni * 8 + t * 2;
                size_t idx = (size_t)c * Ndim + n;
                dst[idx]     = acc[mi][ni][r2 * 2 + 0];
                dst[idx + 1] = acc[mi][ni][r2 * 2 + 1];
            }
        }
}

// =====================================================================
// batched gate (R4 form), z = m*4 + b (grid z = 12)
// =====================================================================
__global__ void __launch_bounds__(256, 2) gate_mma3(
    const float* __restrict__ Wg, const float* __restrict__ bg)
{
    __shared__ float As[2][BK][BMP];
    __shared__ float Bs[2][BK][BMP];
    const int z = blockIdx.z, a = z >> 2, b = z & 3;
    const int o0 = blockIdx.y * BM;
    const int n0 = blockIdx.x * BN;
    const int tid = threadIdx.x;
    const int warp = tid >> 5, lane = tid & 31;
    const int g = lane >> 2, t = lane & 3;
    const int wm = (warp & 1) * 64, wn = (warp >> 1) * 32;
    const float* Xb = g_W[a] + (size_t)b * CN;
    float*       F  = g_F3[a] + (size_t)b * CN;

    const int arow = tid >> 1;
    const int akk0 = (tid & 1) * 8;
    const int bn4 = (tid & 31) * 4;
    const int bk0 = tid >> 5;

    DECL_ACC;

    float4 a_st[2], b_st[2];
    auto loadg = [&](int k0) {
#pragma unroll
        for (int r = 0; r < 2; r++)
            a_st[r] = *(const float4*)(Wg + (size_t)(o0 + arow) * Cdim + k0 + akk0 + r * 4);
#pragma unroll
        for (int r = 0; r < 2; r++)
            b_st[r] = *(const float4*)(Xb + (size_t)(k0 + bk0 + r * 8) * Ndim + n0 + bn4);
    };
    auto storeg = [&](int buf) {
#pragma unroll
        for (int r = 0; r < 2; r++) {
            int kk = akk0 + r * 4;
            As[buf][kk + 0][arow] = f2tf32f(a_st[r].x);
            As[buf][kk + 1][arow] = f2tf32f(a_st[r].y);
            As[buf][kk + 2][arow] = f2tf32f(a_st[r].z);
            As[buf][kk + 3][arow] = f2tf32f(a_st[r].w);
        }
#pragma unroll
        for (int r = 0; r < 2; r++)
            *(float4*)(&Bs[buf][bk0 + r * 8][bn4]) = cvt4(b_st[r]);
    };

    loadg(0); storeg(0); __syncthreads();
    int buf = 0;
    for (int k0 = 0; k0 < Cdim; k0 += BK) {
        bool more = (k0 + BK) < Cdim;
        if (more) loadg(k0 + BK);
        tile_mma_kk16(As[buf], Bs[buf], wm, wn, g, t, acc);
        if (more) storeg(buf ^ 1);
        __syncthreads();
        buf ^= 1;
    }

#pragma unroll
    for (int mi = 0; mi < 4; mi++)
#pragma unroll
        for (int r2 = 0; r2 < 2; r2++) {
            int o = o0 + wm + mi * 16 + g + r2 * 8;
            float bi = bg[o];
#pragma unroll
            for (int ni = 0; ni < 4; ni++) {
                int n = n0 + wn + ni * 8 + t * 2;
                size_t idx = (size_t)o * Ndim + n;
#pragma unroll
                for (int e = 0; e < 2; e++) {
                    float gv  = acc[mi][ni][r2 * 2 + e] + bi;
                    float sig = 1.f / (1.f + __expf(-gv));
                    F[idx + e] = sig * Xb[idx + e];
                }
            }
        }
}

// =====================================================================
// final conv (R4 form): out = Wo @ (F0+F1+F2) + bo (grid z = 4)
// =====================================================================
__global__ void __launch_bounds__(256, 2) final_mma(
    const float* __restrict__ Wo, const float* __restrict__ bo,
    float* __restrict__ out)
{
    __shared__ float As[2][BK][BMP];
    __shared__ float Bs[2][BK][BMP];
    const int b  = blockIdx.z;
    const int o0 = blockIdx.y * BM;
    const int n0 = blockIdx.x * BN;
    const int tid = threadIdx.x;
    const int warp = tid >> 5, lane = tid & 31;
    const int g = lane >> 2, t = lane & 3;
    const int wm = (warp & 1) * 64, wn = (warp >> 1) * 32;
    const float* F0 = g_F3[0] + (size_t)b * CN;
    const float* F1 = g_F3[1] + (size_t)b * CN;
    const float* F2 = g_F3[2] + (size_t)b * CN;
    float* dst = out + (size_t)b * CN;

    const int arow = tid >> 1;
    const int akk0 = (tid & 1) * 8;
    const int bn4 = (tid & 31) * 4;
    const int bk0 = tid >> 5;

    DECL_ACC;

    float4 a_st[2], b_st[2];
    auto loadg = [&](int k0) {
#pragma unroll
        for (int r = 0; r < 2; r++)
            a_st[r] = *(const float4*)(Wo + (size_t)(o0 + arow) * Cdim + k0 + akk0 + r * 4);
#pragma unroll
        for (int r = 0; r < 2; r++) {
            size_t off = (size_t)(k0 + bk0 + r * 8) * Ndim + n0 + bn4;
            float4 v0 = *(const float4*)(F0 + off);
            float4 v1 = *(const float4*)(F1 + off);
            float4 v2 = *(const float4*)(F2 + off);
            v0.x += v1.x + v2.x; v0.y += v1.y + v2.y;
            v0.z += v1.z + v2.z; v0.w += v1.w + v2.w;
            b_st[r] = v0;
        }
    };
    auto storeg = [&](int buf) {
#pragma unroll
        for (int r = 0; r < 2; r++) {
            int kk = akk0 + r * 4;
            As[buf][kk + 0][arow] = f2tf32f(a_st[r].x);
            As[buf][kk + 1][arow] = f2tf32f(a_st[r].y);
            As[buf][kk + 2][arow] = f2tf32f(a_st[r].z);
            As[buf][kk + 3][arow] = f2tf32f(a_st[r].w);
        }
#pragma unroll
        for (int r = 0; r < 2; r++)
            *(float4*)(&Bs[buf][bk0 + r * 8][bn4]) = cvt4(b_st[r]);
    };

    loadg(0); storeg(0); __syncthreads();
    int buf = 0;
    for (int k0 = 0; k0 < Cdim; k0 += BK) {
        bool more = (k0 + BK) < Cdim;
        if (more) loadg(k0 + BK);
        tile_mma_kk16(As[buf], Bs[buf], wm, wn, g, t, acc);
        if (more) storeg(buf ^ 1);
        __syncthreads();
        buf ^= 1;
    }

#pragma unroll
    for (int mi = 0; mi < 4; mi++)
#pragma unroll
        for (int r2 = 0; r2 < 2; r2++) {
            int o = o0 + wm + mi * 16 + g + r2 * 8;
            float bi = bo[o];
#pragma unroll
            for (int ni = 0; ni < 4; ni++) {
                int n = n0 + wn + ni * 8 + t * 2;
                size_t idx = (size_t)o * Ndim + n;
                dst[idx]     = acc[mi][ni][r2 * 2 + 0] + bi;
                dst[idx + 1] = acc[mi][ni][r2 * 2 + 1] + bi;
            }
        }
}

// =====================================================================
// launch
// =====================================================================
#define SCORES_SMEM (2 * 2 * 32 * BMP * 4)   // 69632 B
#define AV_SMEM     (2 * 2 * BM * AKP * 4)   // 73728 B

extern "C" void kernel_launch(void* const* d_in, const int* in_sizes, int n_in,
                              void* d_out, int out_size)
{
    const float* x[3] = { (const float*)d_in[0], (const float*)d_in[1], (const float*)d_in[2] };
    const float* s = (const float*)d_in[3];
    const float *wq[3], *bq[3], *wk[3], *bk[3], *wv[3], *bv[3];
    for (int m = 0; m < 3; m++) {
        wq[m] = (const float*)d_in[4 + 6 * m];
        bq[m] = (const float*)d_in[5 + 6 * m];
        wk[m] = (const float*)d_in[6 + 6 * m];
        bk[m] = (const float*)d_in[7 + 6 * m];
        wv[m] = (const float*)d_in[8 + 6 * m];
        bv[m] = (const float*)d_in[9 + 6 * m];
    }
    const float* wg = (const float*)d_in[22];
    const float* bg = (const float*)d_in[23];
    const float* wo = (const float*)d_in[24];
    const float* bo = (const float*)d_in[25];
    float* out = (float*)d_out;

    float *gP, *gW, *gF;
    cudaGetSymbolAddress((void**)&gP, g_P);
    cudaGetSymbolAddress((void**)&gW, g_W);
    cudaGetSymbolAddress((void**)&gF, g_F3);

    float* Q[3]; float* K[3]; float* V[3]; float* Wout[3]; float* KS[3];
    for (int m = 0; m < 3; m++) {
        Q[m]    = gP + (size_t)(0 + m) * PLANE;
        K[m]    = gP + (size_t)(3 + m) * PLANE;
        V[m]    = gP + (size_t)(6 + m) * PLANE;
        Wout[m] = gW + (size_t)m * PLANE;
        KS[m]   = gF + (size_t)m * PLANE;   // g_F3 reused as Ksum scratch pre-gate
    }

    Proj9 P;
    for (int m = 0; m < 3; m++) {
        P.X[3 * m + 0] = x[m]; P.W[3 * m + 0] = wq[m]; P.B[3 * m + 0] = bq[m];
        P.D[3 * m + 0] = Q[m]; P.sidx[3 * m + 0] = m;  P.rnd[3 * m + 0] = 1;  // Q: round
        P.X[3 * m + 1] = x[m]; P.W[3 * m + 1] = wk[m]; P.B[3 * m + 1] = bk[m];
        P.D[3 * m + 1] = K[m]; P.sidx[3 * m + 1] = m;  P.rnd[3 * m + 1] = 0;  // K: raw (summed later)
        P.X[3 * m + 2] = x[m]; P.W[3 * m + 2] = wv[m]; P.B[3 * m + 2] = bv[m];
        P.D[3 * m + 2] = V[m]; P.sidx[3 * m + 2] = -1; P.rnd[3 * m + 2] = 1;  // V: round
    }

    // attends: w_rgb(Q0; K2+K1; V0), w_depth(Q2; K0+K1; V2), w_thermal(Q1; K0+K2; V1)
    Att3 A;
    const int qi[3] = { 0, 2, 1 };
    for (int a = 0; a < 3; a++) {
        A.Q[a]  = Q[qi[a]];
        A.KS[a] = KS[a];
        A.V[a]  = V[qi[a]];
        A.O[a]  = Wout[a];
    }

    cudaFuncSetAttribute(scores_cp, cudaFuncAttributeMaxDynamicSharedMemorySize, SCORES_SMEM);
    cudaFuncSetAttribute(av_cp,     cudaFuncAttributeMaxDynamicSharedMemorySize, AV_SMEM);

    dim3 blk(256);
    proj_mma9 <<<dim3(Ndim / BN, Cdim / BM, 36), blk>>>(P, s);
    ksum3_kernel<<<dim3(PLANE / 1024), blk>>>(K[0], K[1], K[2], KS[0], KS[1], KS[2]);
    scores_cp <<<dim3(Ndim / BN, Ndim / BM, 12), blk, SCORES_SMEM>>>(A);
    softmax_kernel<<<dim3(3 * Bdim * Ndim), blk>>>();
    av_cp     <<<dim3(Ndim / BN, Cdim / BM, 12), blk, AV_SMEM>>>(A);
    gate_mma3 <<<dim3(Ndim / BN, Cdim / BM, 12), blk>>>(wg, bg);
    final_mma <<<dim3(Ndim / BN, Cdim / BM, 4), blk>>>(wo, bo, out);
}

// round 10
// speedup vs baseline: 2.5113x; 1.5586x over previous
#include <cuda_runtime.h>
#include <cuda_fp16.h>
#include <cstdint>
#include <math.h>

#define Bdim 4
#define Cdim 256
#define Ndim 2304      // 48*48
#define PLANE (Bdim*Cdim*Ndim)
#define CN   (Cdim*Ndim)
#define NN   ((size_t)Ndim*Ndim)

#define BM 128
#define BN 128
#define BK 16
#define BMP 136        // fp32 [k][*] stride (proj/gate/final)
#define SKP 136        // fp16 [k][*] stride, scores tiles (272B = 17*16)
#define VKP 72         // fp16 [row][k] stride, av tiles (144B = 9*16)

// ---- scratch ----
__device__ float  g_K[3][PLANE];                     // raw fp32 K
__device__ __half g_H[9][PLANE];                     // Q0..2, KS0..2, V0..2
__device__ __half g_S3h[(size_t)3 * Bdim * NN];      // scores / probs (fp16)
__device__ float  g_W[3][PLANE];                     // attention outputs
__device__ float  g_F3[3][PLANE];                    // gated outputs

// ---- tf32 helpers (proj/gate/final path) ----
__device__ __forceinline__ float f2tf32f(float x) {
    uint32_t u;
    asm("cvt.rna.tf32.f32 %0, %1;" : "=r"(u) : "f"(x));
    return __uint_as_float(u);
}
__device__ __forceinline__ float4 cvt4(float4 v) {
    v.x = f2tf32f(v.x); v.y = f2tf32f(v.y);
    v.z = f2tf32f(v.z); v.w = f2tf32f(v.w);
    return v;
}

__device__ __forceinline__ void mma_tf32(float c[4], const uint32_t a[4], const uint32_t b[2]) {
    asm volatile(
        "mma.sync.aligned.m16n8k8.row.col.f32.tf32.tf32.f32 "
        "{%0,%1,%2,%3}, {%4,%5,%6,%7}, {%8,%9}, {%0,%1,%2,%3};"
        : "+f"(c[0]), "+f"(c[1]), "+f"(c[2]), "+f"(c[3])
        : "r"(a[0]), "r"(a[1]), "r"(a[2]), "r"(a[3]), "r"(b[0]), "r"(b[1]));
}

// ---- fp16 mma + ldmatrix ----
__device__ __forceinline__ void mma_f16(float c[4], const uint32_t a[4], const uint32_t b[2]) {
    asm volatile(
        "mma.sync.aligned.m16n8k16.row.col.f32.f16.f16.f32 "
        "{%0,%1,%2,%3}, {%4,%5,%6,%7}, {%8,%9}, {%0,%1,%2,%3};"
        : "+f"(c[0]), "+f"(c[1]), "+f"(c[2]), "+f"(c[3])
        : "r"(a[0]), "r"(a[1]), "r"(a[2]), "r"(a[3]), "r"(b[0]), "r"(b[1]));
}
__device__ __forceinline__ void ldsm4(uint32_t& r0, uint32_t& r1, uint32_t& r2, uint32_t& r3, uint32_t a) {
    asm volatile("ldmatrix.sync.aligned.m8n8.x4.shared.b16 {%0,%1,%2,%3}, [%4];"
        : "=r"(r0), "=r"(r1), "=r"(r2), "=r"(r3) : "r"(a));
}
__device__ __forceinline__ void ldsm4t(uint32_t& r0, uint32_t& r1, uint32_t& r2, uint32_t& r3, uint32_t a) {
    asm volatile("ldmatrix.sync.aligned.m8n8.x4.trans.shared.b16 {%0,%1,%2,%3}, [%4];"
        : "=r"(r0), "=r"(r1), "=r"(r2), "=r"(r3) : "r"(a));
}

// ---- cp.async ----
__device__ __forceinline__ uint32_t smem_cast(const void* p) {
    return (uint32_t)__cvta_generic_to_shared(p);
}
#define CP_ASYNC16(dst_u32, gptr) \
    asm volatile("cp.async.cg.shared.global [%0], [%1], 16;" :: "r"(dst_u32), "l"(gptr))
#define CP_COMMIT() asm volatile("cp.async.commit_group;" ::: "memory")
#define CP_WAIT1()  asm volatile("cp.async.wait_group 1;" ::: "memory")
#define CP_WAIT0()  asm volatile("cp.async.wait_group 0;" ::: "memory")

// ---- fp32 tile core (proj/gate/final) ----
__device__ __forceinline__ void tile_mma_kk16(
    const float (*As)[BMP], const float (*Bs)[BMP],
    int wm, int wn, int g, int t, float acc[4][4][4])
{
#pragma unroll
    for (int ks = 0; ks < BK; ks += 8) {
        uint32_t af[4][4], bf[4][2];
#pragma unroll
        for (int mi = 0; mi < 4; mi++) {
            int m = wm + mi * 16 + g;
            af[mi][0] = __float_as_uint(As[ks + t][m]);
            af[mi][1] = __float_as_uint(As[ks + t][m + 8]);
            af[mi][2] = __float_as_uint(As[ks + t + 4][m]);
            af[mi][3] = __float_as_uint(As[ks + t + 4][m + 8]);
        }
#pragma unroll
        for (int ni = 0; ni < 4; ni++) {
            int n = wn + ni * 8 + g;
            bf[ni][0] = __float_as_uint(Bs[ks + t][n]);
            bf[ni][1] = __float_as_uint(Bs[ks + t + 4][n]);
        }
#pragma unroll
        for (int mi = 0; mi < 4; mi++)
#pragma unroll
            for (int ni = 0; ni < 4; ni++)
                mma_tf32(acc[mi][ni], af[mi], bf[ni]);
    }
}

#define DECL_ACC float acc[4][4][4]; \
    _Pragma("unroll") for (int mi = 0; mi < 4; mi++) \
    _Pragma("unroll") for (int ni = 0; ni < 4; ni++) \
    _Pragma("unroll") for (int r = 0; r < 4; r++) acc[mi][ni][r] = 0.f;

// ---- arg structs ----
struct Proj9 {
    const float* X[9]; const float* W[9]; const float* B[9];
    float* D[9]; __half* DH[9]; int sidx[9];
};
struct Att3h {
    const __half* Q[3]; const __half* KS[3]; const __half* V[3]; float* O[3];
};

// =====================================================================
// batched proj (tf32 core; output fp32 or fp16). z = job*4+b, grid z=36
// =====================================================================
__global__ void __launch_bounds__(256, 2) proj_mma9(Proj9 P, const float* __restrict__ s)
{
    __shared__ float As[2][BK][BMP];
    __shared__ float Bs[2][BK][BMP];
    const int z = blockIdx.z, job = z >> 2, b = z & 3;
    const int o0 = blockIdx.y * BM;
    const int n0 = blockIdx.x * BN;
    const int tid = threadIdx.x;
    const int warp = tid >> 5, lane = tid & 31;
    const int g = lane >> 2, t = lane & 3;
    const int wm = (warp & 1) * 64, wn = (warp >> 1) * 32;

    const float* Xb   = P.X[job] + (size_t)b * CN;
    const float* Wt   = P.W[job];
    const float* bias = P.B[job];
    float*  dstf = P.D[job]  ? P.D[job]  + (size_t)b * CN : nullptr;
    __half* dsth = P.DH[job] ? P.DH[job] + (size_t)b * CN : nullptr;
    const int sidx = P.sidx[job];

    const int arow = tid >> 1;
    const int akk0 = (tid & 1) * 8;
    const int bn4 = (tid & 31) * 4;
    const int bk0 = tid >> 5;

    DECL_ACC;

    float4 a_st[2], b_st[2];
    auto loadg = [&](int k0) {
#pragma unroll
        for (int r = 0; r < 2; r++)
            a_st[r] = *(const float4*)(Wt + (size_t)(o0 + arow) * Cdim + k0 + akk0 + r * 4);
#pragma unroll
        for (int r = 0; r < 2; r++)
            b_st[r] = *(const float4*)(Xb + (size_t)(k0 + bk0 + r * 8) * Ndim + n0 + bn4);
    };
    auto storeg = [&](int buf) {
#pragma unroll
        for (int r = 0; r < 2; r++) {
            int kk = akk0 + r * 4;
            As[buf][kk + 0][arow] = f2tf32f(a_st[r].x);
            As[buf][kk + 1][arow] = f2tf32f(a_st[r].y);
            As[buf][kk + 2][arow] = f2tf32f(a_st[r].z);
            As[buf][kk + 3][arow] = f2tf32f(a_st[r].w);
        }
#pragma unroll
        for (int r = 0; r < 2; r++)
            *(float4*)(&Bs[buf][bk0 + r * 8][bn4]) = cvt4(b_st[r]);
    };

    loadg(0); storeg(0); __syncthreads();
    int buf = 0;
    for (int k0 = 0; k0 < Cdim; k0 += BK) {
        bool more = (k0 + BK) < Cdim;
        if (more) loadg(k0 + BK);
        tile_mma_kk16(As[buf], Bs[buf], wm, wn, g, t, acc);
        if (more) storeg(buf ^ 1);
        __syncthreads();
        buf ^= 1;
    }

    const float scale = (sidx >= 0) ? s[sidx] : 1.f;
#pragma unroll
    for (int mi = 0; mi < 4; mi++)
#pragma unroll
        for (int r2 = 0; r2 < 2; r2++) {
            int m = o0 + wm + mi * 16 + g + r2 * 8;
            float bi = bias[m];
#pragma unroll
            for (int ni = 0; ni < 4; ni++) {
                int n = n0 + wn + ni * 8 + t * 2;
                size_t idx = (size_t)m * Ndim + n;
                float v0 = (acc[mi][ni][r2 * 2 + 0] + bi) * scale;
                float v1 = (acc[mi][ni][r2 * 2 + 1] + bi) * scale;
                if (dsth) {
                    *(__half2*)(dsth + idx) = __floats2half2_rn(v0, v1);
                } else {
                    dstf[idx]     = v0;
                    dstf[idx + 1] = v1;
                }
            }
        }
}

// =====================================================================
// ksum3: KS[a] = fp16(Ka + Kb); fp32 in, fp16 out
// =====================================================================
__global__ void __launch_bounds__(256) ksum3_kernel(
    const float* __restrict__ K0, const float* __restrict__ K1,
    const float* __restrict__ K2,
    __half* __restrict__ S0, __half* __restrict__ S1, __half* __restrict__ S2)
{
    size_t i = ((size_t)blockIdx.x * 256 + threadIdx.x) * 4;
    float4 a = *(const float4*)(K0 + i);
    float4 b = *(const float4*)(K1 + i);
    float4 c = *(const float4*)(K2 + i);
    // S0 = K2+K1, S1 = K0+K1, S2 = K0+K2
    *(__half2*)(S0 + i)     = __floats2half2_rn(c.x + b.x, c.y + b.y);
    *(__half2*)(S0 + i + 2) = __floats2half2_rn(c.z + b.z, c.w + b.w);
    *(__half2*)(S1 + i)     = __floats2half2_rn(a.x + b.x, a.y + b.y);
    *(__half2*)(S1 + i + 2) = __floats2half2_rn(a.z + b.z, a.w + b.w);
    *(__half2*)(S2 + i)     = __floats2half2_rn(a.x + c.x, a.y + c.y);
    *(__half2*)(S2 + i + 2) = __floats2half2_rn(a.z + c.z, a.w + c.w);
}

// =====================================================================
// scores fp16: S[z][y][m] = (1/16) sum_c Q[c][y] KS[c][m]
// cp.async BK=64, smem [k][*] fp16 stride SKP, ldmatrix.trans frags
// z = attend*4 + b (grid z = 12)
// =====================================================================
#define SC_SMEM (2 * 2 * 64 * SKP * 2)   // 69632 B

__global__ void __launch_bounds__(256, 2) scores_h(Att3h A)
{
    extern __shared__ __half hsm[];
    __half* Ab = hsm;                    // [2][64][SKP]
    __half* Bb = hsm + 2 * 64 * SKP;

    const int z = blockIdx.z, a = z >> 2, b = z & 3;
    const int y0 = blockIdx.y * BM;
    const int z0 = blockIdx.x * BN;
    const int tid = threadIdx.x;
    const int warp = tid >> 5, lane = tid & 31;
    const int t = lane & 3;
    const int wm = (warp & 1) * 64, wn = (warp >> 1) * 32;
    const __half* Qb = A.Q[a]  + (size_t)b * CN;
    const __half* Kb = A.KS[a] + (size_t)b * CN;

    // loaders: 128 threads per operand; 16 threads/row (16B each), 8 rows/loop
    const int u  = tid & 127;
    const int r0 = u >> 4;        // 0..7
    const int cc = u & 15;        // 16B chunk
    const bool isB = (tid >= 128);
    const __half* gsrc = isB ? (Kb + z0) : (Qb + y0);
    __half* sbase = isB ? Bb : Ab;

    auto prefetch = [&](int bufp, int k0) {
#pragma unroll
        for (int j = 0; j < 8; j++) {
            int row = r0 + 8 * j;
            const __half* gp = gsrc + (size_t)(k0 + row) * Ndim + cc * 8;
            __half* sp = sbase + ((size_t)bufp * 64 + row) * SKP + cc * 8;
            CP_ASYNC16(smem_cast(sp), gp);
        }
        CP_COMMIT();
    };

    DECL_ACC;

    prefetch(0, 0);
    prefetch(1, 64);
    const int NIT = Cdim / 64;   // 4
    for (int it = 0; it < NIT; it++) {
        int buf = it & 1;
        if (it == NIT - 1) CP_WAIT0(); else CP_WAIT1();
        __syncthreads();
        const __half* At = Ab + (size_t)buf * 64 * SKP;
        const __half* Bt = Bb + (size_t)buf * 64 * SKP;
        const int j = lane >> 3, r = lane & 7;
#pragma unroll
        for (int ks = 0; ks < 64; ks += 16) {
            uint32_t af[4][4];
#pragma unroll
            for (int mi = 0; mi < 4; mi++) {
                int krow = ks + ((j & 2) ? 8 : 0) + r;
                int mo = wm + mi * 16 + ((j & 1) ? 8 : 0);
                ldsm4t(af[mi][0], af[mi][1], af[mi][2], af[mi][3],
                       smem_cast(At + (size_t)krow * SKP + mo));
            }
#pragma unroll
            for (int np = 0; np < 2; np++) {
                int krow = ks + ((j & 1) ? 8 : 0) + r;
                int no = wn + np * 16 + ((j & 2) ? 8 : 0);
                uint32_t b0, b1, b2, b3;
                ldsm4t(b0, b1, b2, b3, smem_cast(Bt + (size_t)krow * SKP + no));
                uint32_t bl[2] = { b0, b1 }, bh[2] = { b2, b3 };
#pragma unroll
                for (int mi = 0; mi < 4; mi++) {
                    mma_f16(acc[mi][np * 2 + 0], af[mi], bl);
                    mma_f16(acc[mi][np * 2 + 1], af[mi], bh);
                }
            }
        }
        __syncthreads();
        if (it + 2 < NIT) prefetch(buf, (it + 2) * 64);
    }

    __half* Sb = g_S3h + (size_t)z * NN;
    const int g = lane >> 2;
#pragma unroll
    for (int mi = 0; mi < 4; mi++)
#pragma unroll
        for (int r2 = 0; r2 < 2; r2++) {
            int y = y0 + wm + mi * 16 + g + r2 * 8;
#pragma unroll
            for (int ni = 0; ni < 4; ni++) {
                int zz = z0 + wn + ni * 8 + t * 2;
                size_t idx = (size_t)y * Ndim + zz;
                *(__half2*)(Sb + idx) = __floats2half2_rn(
                    acc[mi][ni][r2 * 2 + 0] * 0.0625f,
                    acc[mi][ni][r2 * 2 + 1] * 0.0625f);
            }
        }
}

// =====================================================================
// softmax fp16 in/out (one block per row)
// =====================================================================
__global__ void __launch_bounds__(256) softmax_kernel()
{
    const size_t row = blockIdx.x;
    __half* p = g_S3h + row * Ndim;
    const int tid = threadIdx.x;
    const int warp = tid >> 5, lane = tid & 31;
    __shared__ float red[8];

    float v[9];
#pragma unroll
    for (int i = 0; i < 9; i++) v[i] = __half2float(p[tid + i * 256]);

    float mx = v[0];
#pragma unroll
    for (int i = 1; i < 9; i++) mx = fmaxf(mx, v[i]);
#pragma unroll
    for (int off = 16; off > 0; off >>= 1)
        mx = fmaxf(mx, __shfl_xor_sync(0xffffffffu, mx, off));
    if (lane == 0) red[warp] = mx;
    __syncthreads();
    if (warp == 0) {
        float m2 = red[lane & 7];
#pragma unroll
        for (int off = 4; off > 0; off >>= 1)
            m2 = fmaxf(m2, __shfl_xor_sync(0xffffffffu, m2, off));
        if (lane == 0) red[0] = m2;
    }
    __syncthreads();
    mx = red[0];

    float sum = 0.f;
#pragma unroll
    for (int i = 0; i < 9; i++) { v[i] = __expf(v[i] - mx); sum += v[i]; }
#pragma unroll
    for (int off = 16; off > 0; off >>= 1)
        sum += __shfl_xor_sync(0xffffffffu, sum, off);
    __syncthreads();
    if (lane == 0) red[warp] = sum;
    __syncthreads();
    if (warp == 0) {
        float s2 = red[lane & 7];
#pragma unroll
        for (int off = 4; off > 0; off >>= 1)
            s2 += __shfl_xor_sync(0xffffffffu, s2, off);
        if (lane == 0) red[0] = s2;
    }
    __syncthreads();
    const float inv = 1.f / red[0];
#pragma unroll
    for (int i = 0; i < 9; i++) p[tid + i * 256] = __float2half_rn(v[i] * inv);
}

// =====================================================================
// AV fp16: dst[c][n] = sum_m V[c][m] P[n][m]
// cp.async BK=64, smem [row][k] fp16 stride VKP, ldmatrix (no trans)
// z = attend*4 + b (grid z = 12)
// =====================================================================
#define AV_SMEM (2 * 2 * 128 * VKP * 2)  // 73728 B

__global__ void __launch_bounds__(256, 2) av_h(Att3h A)
{
    extern __shared__ __half hsm[];
    __half* Ab = hsm;                    // [2][128][VKP]
    __half* Bb = hsm + 2 * 128 * VKP;

    const int z = blockIdx.z, a = z >> 2, b = z & 3;
    const int c0 = blockIdx.y * BM;
    const int n0 = blockIdx.x * BN;
    const int tid = threadIdx.x;
    const int warp = tid >> 5, lane = tid & 31;
    const int t = lane & 3;
    const int wm = (warp & 1) * 64, wn = (warp >> 1) * 32;
    const __half* Vb = A.V[a] + (size_t)b * CN;
    const __half* Pb = g_S3h + (size_t)z * NN;
    float*       dst = A.O[a] + (size_t)b * CN;

    // loaders: 8 threads/row (16B each), 8 row-groups of 16
    const int u  = tid & 127;
    const int r0 = u >> 3;        // 0..15
    const int cc = u & 7;
    const bool isB = (tid >= 128);
    const __half* gsrc = isB ? (Pb + (size_t)n0 * Ndim) : (Vb + (size_t)c0 * Ndim);
    __half* sbase = isB ? Bb : Ab;

    auto prefetch = [&](int bufp, int k0) {
#pragma unroll
        for (int j = 0; j < 8; j++) {
            int row = r0 + 16 * j;
            const __half* gp = gsrc + (size_t)row * Ndim + k0 + cc * 8;
            __half* sp = sbase + ((size_t)bufp * 128 + row) * VKP + cc * 8;
            CP_ASYNC16(smem_cast(sp), gp);
        }
        CP_COMMIT();
    };

    DECL_ACC;

    prefetch(0, 0);
    prefetch(1, 64);
    const int NIT = Ndim / 64;   // 36
    for (int it = 0; it < NIT; it++) {
        int buf = it & 1;
        if (it == NIT - 1) CP_WAIT0(); else CP_WAIT1();
        __syncthreads();
        const __half* At = Ab + (size_t)buf * 128 * VKP;
        const __half* Bt = Bb + (size_t)buf * 128 * VKP;
        const int j = lane >> 3, r = lane & 7;
#pragma unroll
        for (int ks = 0; ks < 64; ks += 16) {
            uint32_t af[4][4];
#pragma unroll
            for (int mi = 0; mi < 4; mi++) {
                int mrow = wm + mi * 16 + ((j & 1) ? 8 : 0) + r;
                int ko = ks + ((j & 2) ? 8 : 0);
                ldsm4(af[mi][0], af[mi][1], af[mi][2], af[mi][3],
                      smem_cast(At + (size_t)mrow * VKP + ko));
            }
#pragma unroll
            for (int np = 0; np < 2; np++) {
                int nrow = wn + np * 16 + ((j & 2) ? 8 : 0) + r;
                int ko = ks + ((j & 1) ? 8 : 0);
                uint32_t b0, b1, b2, b3;
                ldsm4(b0, b1, b2, b3, smem_cast(Bt + (size_t)nrow * VKP + ko));
                uint32_t bl[2] = { b0, b1 }, bh[2] = { b2, b3 };
#pragma unroll
                for (int mi = 0; mi < 4; mi++) {
                    mma_f16(acc[mi][np * 2 + 0], af[mi], bl);
                    mma_f16(acc[mi][np * 2 + 1], af[mi], bh);
                }
            }
        }
        __syncthreads();
        if (it + 2 < NIT) prefetch(buf, (it + 2) * 64);
    }

    const int g = lane >> 2;
#pragma unroll
    for (int mi = 0; mi < 4; mi++)
#pragma unroll
        for (int r2 = 0; r2 < 2; r2++) {
            int c = c0 + wm + mi * 16 + g + r2 * 8;
#pragma unroll
            for (int ni = 0; ni < 4; ni++) {
                int n = n0 + wn + ni * 8 + t * 2;
                float2 v = { acc[mi][ni][r2 * 2 + 0], acc[mi][ni][r2 * 2 + 1] };
                *(float2*)(dst + (size_t)c * Ndim + n) = v;
            }
        }
}

// =====================================================================
// batched gate (tf32, R9 form), z = m*4 + b (grid z = 12)
// =====================================================================
__global__ void __launch_bounds__(256, 2) gate_mma3(
    const float* __restrict__ Wg, const float* __restrict__ bg)
{
    __shared__ float As[2][BK][BMP];
    __shared__ float Bs[2][BK][BMP];
    const int z = blockIdx.z, a = z >> 2, b = z & 3;
    const int o0 = blockIdx.y * BM;
    const int n0 = blockIdx.x * BN;
    const int tid = threadIdx.x;
    const int warp = tid >> 5, lane = tid & 31;
    const int g = lane >> 2, t = lane & 3;
    const int wm = (warp & 1) * 64, wn = (warp >> 1) * 32;
    const float* Xb = g_W[a] + (size_t)b * CN;
    float*       F  = g_F3[a] + (size_t)b * CN;

    const int arow = tid >> 1;
    const int akk0 = (tid & 1) * 8;
    const int bn4 = (tid & 31) * 4;
    const int bk0 = tid >> 5;

    DECL_ACC;

    float4 a_st[2], b_st[2];
    auto loadg = [&](int k0) {
#pragma unroll
        for (int r = 0; r < 2; r++)
            a_st[r] = *(const float4*)(Wg + (size_t)(o0 + arow) * Cdim + k0 + akk0 + r * 4);
#pragma unroll
        for (int r = 0; r < 2; r++)
            b_st[r] = *(const float4*)(Xb + (size_t)(k0 + bk0 + r * 8) * Ndim + n0 + bn4);
    };
    auto storeg = [&](int buf) {
#pragma unroll
        for (int r = 0; r < 2; r++) {
            int kk = akk0 + r * 4;
            As[buf][kk + 0][arow] = f2tf32f(a_st[r].x);
            As[buf][kk + 1][arow] = f2tf32f(a_st[r].y);
            As[buf][kk + 2][arow] = f2tf32f(a_st[r].z);
            As[buf][kk + 3][arow] = f2tf32f(a_st[r].w);
        }
#pragma unroll
        for (int r = 0; r < 2; r++)
            *(float4*)(&Bs[buf][bk0 + r * 8][bn4]) = cvt4(b_st[r]);
    };

    loadg(0); storeg(0); __syncthreads();
    int buf = 0;
    for (int k0 = 0; k0 < Cdim; k0 += BK) {
        bool more = (k0 + BK) < Cdim;
        if (more) loadg(k0 + BK);
        tile_mma_kk16(As[buf], Bs[buf], wm, wn, g, t, acc);
        if (more) storeg(buf ^ 1);
        __syncthreads();
        buf ^= 1;
    }

#pragma unroll
    for (int mi = 0; mi < 4; mi++)
#pragma unroll
        for (int r2 = 0; r2 < 2; r2++) {
            int o = o0 + wm + mi * 16 + g + r2 * 8;
            float bi = bg[o];
#pragma unroll
            for (int ni = 0; ni < 4; ni++) {
                int n = n0 + wn + ni * 8 + t * 2;
                size_t idx = (size_t)o * Ndim + n;
#pragma unroll
                for (int e = 0; e < 2; e++) {
                    float gv  = acc[mi][ni][r2 * 2 + e] + bi;
                    float sig = 1.f / (1.f + __expf(-gv));
                    F[idx + e] = sig * Xb[idx + e];
                }
            }
        }
}

// =====================================================================
// final conv (tf32, R9 form): out = Wo @ (F0+F1+F2) + bo (grid z = 4)
// =====================================================================
__global__ void __launch_bounds__(256, 2) final_mma(
    const float* __restrict__ Wo, const float* __restrict__ bo,
    float* __restrict__ out)
{
    __shared__ float As[2][BK][BMP];
    __shared__ float Bs[2][BK][BMP];
    const int b  = blockIdx.z;
    const int o0 = blockIdx.y * BM;
    const int n0 = blockIdx.x * BN;
    const int tid = threadIdx.x;
    const int warp = tid >> 5, lane = tid & 31;
    const int g = lane >> 2, t = lane & 3;
    const int wm = (warp & 1) * 64, wn = (warp >> 1) * 32;
    const float* F0 = g_F3[0] + (size_t)b * CN;
    const float* F1 = g_F3[1] + (size_t)b * CN;
    const float* F2 = g_F3[2] + (size_t)b * CN;
    float* dst = out + (size_t)b * CN;

    const int arow = tid >> 1;
    const int akk0 = (tid & 1) * 8;
    const int bn4 = (tid & 31) * 4;
    const int bk0 = tid >> 5;

    DECL_ACC;

    float4 a_st[2], b_st[2];
    auto loadg = [&](int k0) {
#pragma unroll
        for (int r = 0; r < 2; r++)
            a_st[r] = *(const float4*)(Wo + (size_t)(o0 + arow) * Cdim + k0 + akk0 + r * 4);
#pragma unroll
        for (int r = 0; r < 2; r++) {
            size_t off = (size_t)(k0 + bk0 + r * 8) * Ndim + n0 + bn4;
            float4 v0 = *(const float4*)(F0 + off);
            float4 v1 = *(const float4*)(F1 + off);
            float4 v2 = *(const float4*)(F2 + off);
            v0.x += v1.x + v2.x; v0.y += v1.y + v2.y;
            v0.z += v1.z + v2.z; v0.w += v1.w + v2.w;
            b_st[r] = v0;
        }
    };
    auto storeg = [&](int buf) {
#pragma unroll
        for (int r = 0; r < 2; r++) {
            int kk = akk0 + r * 4;
            As[buf][kk + 0][arow] = f2tf32f(a_st[r].x);
            As[buf][kk + 1][arow] = f2tf32f(a_st[r].y);
            As[buf][kk + 2][arow] = f2tf32f(a_st[r].z);
            As[buf][kk + 3][arow] = f2tf32f(a_st[r].w);
        }
#pragma unroll
        for (int r = 0; r < 2; r++)
            *(float4*)(&Bs[buf][bk0 + r * 8][bn4]) = cvt4(b_st[r]);
    };

    loadg(0); storeg(0); __syncthreads();
    int buf = 0;
    for (int k0 = 0; k0 < Cdim; k0 += BK) {
        bool more = (k0 + BK) < Cdim;
        if (more) loadg(k0 + BK);
        tile_mma_kk16(As[buf], Bs[buf], wm, wn, g, t, acc);
        if (more) storeg(buf ^ 1);
        __syncthreads();
        buf ^= 1;
    }

#pragma unroll
    for (int mi = 0; mi < 4; mi++)
#pragma unroll
        for (int r2 = 0; r2 < 2; r2++) {
            int o = o0 + wm + mi * 16 + g + r2 * 8;
            float bi = bo[o];
#pragma unroll
            for (int ni = 0; ni < 4; ni++) {
                int n = n0 + wn + ni * 8 + t * 2;
                size_t idx = (size_t)o * Ndim + n;
                dst[idx]     = acc[mi][ni][r2 * 2 + 0] + bi;
                dst[idx + 1] = acc[mi][ni][r2 * 2 + 1] + bi;
            }
        }
}

// =====================================================================
// launch
// =====================================================================
extern "C" void kernel_launch(void* const* d_in, const int* in_sizes, int n_in,
                              void* d_out, int out_size)
{
    const float* x[3] = { (const float*)d_in[0], (const float*)d_in[1], (const float*)d_in[2] };
    const float* s = (const float*)d_in[3];
    const float *wq[3], *bq[3], *wk[3], *bk[3], *wv[3], *bv[3];
    for (int m = 0; m < 3; m++) {
        wq[m] = (const float*)d_in[4 + 6 * m];
        bq[m] = (const float*)d_in[5 + 6 * m];
        wk[m] = (const float*)d_in[6 + 6 * m];
        bk[m] = (const float*)d_in[7 + 6 * m];
        wv[m] = (const float*)d_in[8 + 6 * m];
        bv[m] = (const float*)d_in[9 + 6 * m];
    }
    const float* wg = (const float*)d_in[22];
    const float* bg = (const float*)d_in[23];
    const float* wo = (const float*)d_in[24];
    const float* bo = (const float*)d_in[25];
    float* out = (float*)d_out;

    float *gK, *gW;
    __half* gH;
    cudaGetSymbolAddress((void**)&gK, g_K);
    cudaGetSymbolAddress((void**)&gH, g_H);
    cudaGetSymbolAddress((void**)&gW, g_W);

    float* Kf[3]; __half* Qh[3]; __half* KSh[3]; __half* Vh[3]; float* Wout[3];
    for (int m = 0; m < 3; m++) {
        Kf[m]  = gK + (size_t)m * PLANE;
        Qh[m]  = gH + (size_t)(0 + m) * PLANE;
        KSh[m] = gH + (size_t)(3 + m) * PLANE;
        Vh[m]  = gH + (size_t)(6 + m) * PLANE;
        Wout[m] = gW + (size_t)m * PLANE;
    }

    Proj9 P;
    for (int m = 0; m < 3; m++) {
        // Q: fp16 out, scaled
        P.X[3 * m + 0] = x[m]; P.W[3 * m + 0] = wq[m]; P.B[3 * m + 0] = bq[m];
        P.D[3 * m + 0] = nullptr; P.DH[3 * m + 0] = Qh[m]; P.sidx[3 * m + 0] = m;
        // K: fp32 raw, scaled
        P.X[3 * m + 1] = x[m]; P.W[3 * m + 1] = wk[m]; P.B[3 * m + 1] = bk[m];
        P.D[3 * m + 1] = Kf[m]; P.DH[3 * m + 1] = nullptr; P.sidx[3 * m + 1] = m;
        // V: fp16 out, unscaled
        P.X[3 * m + 2] = x[m]; P.W[3 * m + 2] = wv[m]; P.B[3 * m + 2] = bv[m];
        P.D[3 * m + 2] = nullptr; P.DH[3 * m + 2] = Vh[m]; P.sidx[3 * m + 2] = -1;
    }

    // attends: w_rgb(Q0; K2+K1; V0), w_depth(Q2; K0+K1; V2), w_thermal(Q1; K0+K2; V1)
    Att3h A;
    const int qi[3] = { 0, 2, 1 };
    for (int a = 0; a < 3; a++) {
        A.Q[a]  = Qh[qi[a]];
        A.KS[a] = KSh[a];
        A.V[a]  = Vh[qi[a]];
        A.O[a]  = Wout[a];
    }

    cudaFuncSetAttribute(scores_h, cudaFuncAttributeMaxDynamicSharedMemorySize, SC_SMEM);
    cudaFuncSetAttribute(av_h,     cudaFuncAttributeMaxDynamicSharedMemorySize, AV_SMEM);

    dim3 blk(256);
    proj_mma9 <<<dim3(Ndim / BN, Cdim / BM, 36), blk>>>(P, s);
    ksum3_kernel<<<dim3(PLANE / 1024), blk>>>(Kf[0], Kf[1], Kf[2], KSh[0], KSh[1], KSh[2]);
    scores_h  <<<dim3(Ndim / BN, Ndim / BM, 12), blk, SC_SMEM>>>(A);
    softmax_kernel<<<dim3(3 * Bdim * Ndim), blk>>>();
    av_h      <<<dim3(Ndim / BN, Cdim / BM, 12), blk, AV_SMEM>>>(A);
    gate_mma3 <<<dim3(Ndim / BN, Cdim / BM, 12), blk>>>(wg, bg);
    final_mma <<<dim3(Ndim / BN, Cdim / BM, 4), blk>>>(wo, bo, out);
}

// round 11
// speedup vs baseline: 2.9492x; 1.1744x over previous
#include <cuda_runtime.h>
#include <cuda_fp16.h>
#include <cstdint>
#include <math.h>

#define Bdim 4
#define Cdim 256
#define Ndim 2304      // 48*48
#define PLANE (Bdim*Cdim*Ndim)
#define CN   (Cdim*Ndim)
#define NN   ((size_t)Ndim*Ndim)

#define BM 128
#define BN 128
#define BK 16
#define BMP 136        // fp32 [k][*] stride (final)
#define SKP 136        // fp16 [k][*] stride (272B)
#define VKP 72         // fp16 [row][k] stride (144B)

// ---- scratch ----
__device__ __half g_Xh[3][PLANE];                    // fp16 inputs
__device__ __half g_WT[10][Cdim * Cdim];             // fp16 weights: wq0..2,wk0..2,wv0..2,wg
__device__ float  g_K[3][PLANE];                     // raw fp32 K
__device__ __half g_H[9][PLANE];                     // Q0..2, KS0..2, V0..2
__device__ __half g_S3h[(size_t)3 * Bdim * NN];      // scores / probs (fp16)
__device__ __half g_Wh[3][PLANE];                    // attention outputs (fp16)
__device__ float  g_F3[3][PLANE];                    // gated outputs (fp32)

// ---- tf32 helpers (final conv path) ----
__device__ __forceinline__ float f2tf32f(float x) {
    uint32_t u;
    asm("cvt.rna.tf32.f32 %0, %1;" : "=r"(u) : "f"(x));
    return __uint_as_float(u);
}
__device__ __forceinline__ float4 cvt4(float4 v) {
    v.x = f2tf32f(v.x); v.y = f2tf32f(v.y);
    v.z = f2tf32f(v.z); v.w = f2tf32f(v.w);
    return v;
}

__device__ __forceinline__ void mma_tf32(float c[4], const uint32_t a[4], const uint32_t b[2]) {
    asm volatile(
        "mma.sync.aligned.m16n8k8.row.col.f32.tf32.tf32.f32 "
        "{%0,%1,%2,%3}, {%4,%5,%6,%7}, {%8,%9}, {%0,%1,%2,%3};"
        : "+f"(c[0]), "+f"(c[1]), "+f"(c[2]), "+f"(c[3])
        : "r"(a[0]), "r"(a[1]), "r"(a[2]), "r"(a[3]), "r"(b[0]), "r"(b[1]));
}

// ---- fp16 mma + ldmatrix ----
__device__ __forceinline__ void mma_f16(float c[4], const uint32_t a[4], const uint32_t b[2]) {
    asm volatile(
        "mma.sync.aligned.m16n8k16.row.col.f32.f16.f16.f32 "
        "{%0,%1,%2,%3}, {%4,%5,%6,%7}, {%8,%9}, {%0,%1,%2,%3};"
        : "+f"(c[0]), "+f"(c[1]), "+f"(c[2]), "+f"(c[3])
        : "r"(a[0]), "r"(a[1]), "r"(a[2]), "r"(a[3]), "r"(b[0]), "r"(b[1]));
}
__device__ __forceinline__ void ldsm4(uint32_t& r0, uint32_t& r1, uint32_t& r2, uint32_t& r3, uint32_t a) {
    asm volatile("ldmatrix.sync.aligned.m8n8.x4.shared.b16 {%0,%1,%2,%3}, [%4];"
        : "=r"(r0), "=r"(r1), "=r"(r2), "=r"(r3) : "r"(a));
}
__device__ __forceinline__ void ldsm4t(uint32_t& r0, uint32_t& r1, uint32_t& r2, uint32_t& r3, uint32_t a) {
    asm volatile("ldmatrix.sync.aligned.m8n8.x4.trans.shared.b16 {%0,%1,%2,%3}, [%4];"
        : "=r"(r0), "=r"(r1), "=r"(r2), "=r"(r3) : "r"(a));
}

// ---- cp.async ----
__device__ __forceinline__ uint32_t smem_cast(const void* p) {
    return (uint32_t)__cvta_generic_to_shared(p);
}
#define CP_ASYNC16(dst_u32, gptr) \
    asm volatile("cp.async.cg.shared.global [%0], [%1], 16;" :: "r"(dst_u32), "l"(gptr))
#define CP_COMMIT() asm volatile("cp.async.commit_group;" ::: "memory")
#define CP_WAIT1()  asm volatile("cp.async.wait_group 1;" ::: "memory")
#define CP_WAIT0()  asm volatile("cp.async.wait_group 0;" ::: "memory")

#define DECL_ACC float acc[4][4][4]; \
    _Pragma("unroll") for (int mi = 0; mi < 4; mi++) \
    _Pragma("unroll") for (int ni = 0; ni < 4; ni++) \
    _Pragma("unroll") for (int r = 0; r < 4; r++) acc[mi][ni][r] = 0.f;

// fp16 GEMM inner step: A [m][k] stride VKP (ldsm), B [k][n] stride SKP (ldsm.trans)
#define F16_STEP_MKKN(At, Bt, wm, wn, j, r) \
    _Pragma("unroll") \
    for (int ks = 0; ks < 64; ks += 16) { \
        uint32_t af[4][4]; \
        _Pragma("unroll") \
        for (int mi = 0; mi < 4; mi++) { \
            int mrow = (wm) + mi * 16 + (((j) & 1) ? 8 : 0) + (r); \
            int ko = ks + (((j) & 2) ? 8 : 0); \
            ldsm4(af[mi][0], af[mi][1], af[mi][2], af[mi][3], \
                  smem_cast((At) + (size_t)mrow * VKP + ko)); \
        } \
        _Pragma("unroll") \
        for (int np = 0; np < 2; np++) { \
            int krow = ks + (((j) & 1) ? 8 : 0) + (r); \
            int no = (wn) + np * 16 + (((j) & 2) ? 8 : 0); \
            uint32_t b0, b1, b2, b3; \
            ldsm4t(b0, b1, b2, b3, smem_cast((Bt) + (size_t)krow * SKP + no)); \
            uint32_t bl[2] = { b0, b1 }, bh[2] = { b2, b3 }; \
            _Pragma("unroll") \
            for (int mi = 0; mi < 4; mi++) { \
                mma_f16(acc[mi][np * 2 + 0], af[mi], bl); \
                mma_f16(acc[mi][np * 2 + 1], af[mi], bh); \
            } \
        } \
    }

// ---- arg structs ----
struct Proj9 {
    const __half* X[9]; const __half* W[9]; const float* B[9];
    float* D[9]; __half* DH[9]; int sidx[9];
};
struct Att3h {
    const __half* Q[3]; const __half* KS[3]; const __half* V[3]; __half* O[3];
};

// =====================================================================
// cvt kernels
// =====================================================================
__global__ void __launch_bounds__(256) cvt_x3(
    const float* __restrict__ x0, const float* __restrict__ x1,
    const float* __restrict__ x2,
    __half* __restrict__ d0, __half* __restrict__ d1, __half* __restrict__ d2)
{
    const float* src = (blockIdx.y == 0) ? x0 : (blockIdx.y == 1) ? x1 : x2;
    __half* dst      = (blockIdx.y == 0) ? d0 : (blockIdx.y == 1) ? d1 : d2;
    size_t i = ((size_t)blockIdx.x * 256 + threadIdx.x) * 4;
    float4 v = *(const float4*)(src + i);
    *(__half2*)(dst + i)     = __floats2half2_rn(v.x, v.y);
    *(__half2*)(dst + i + 2) = __floats2half2_rn(v.z, v.w);
}

struct W10 { const float* src[10]; };
__global__ void __launch_bounds__(256) cvt_w10(W10 W, __half* __restrict__ base)
{
    const float* src = W.src[blockIdx.y];
    __half* dst = base + (size_t)blockIdx.y * Cdim * Cdim;
    size_t i = ((size_t)blockIdx.x * 256 + threadIdx.x) * 4;
    float4 v = *(const float4*)(src + i);
    *(__half2*)(dst + i)     = __floats2half2_rn(v.x, v.y);
    *(__half2*)(dst + i + 2) = __floats2half2_rn(v.z, v.w);
}

// =====================================================================
// proj fp16: dst[o][n] = scale*(sum_c W[o][c] X[c][n] + bias[o])
// A = W [m][k] (ldsm), B = X [k][n] (ldsm.trans), BK=64, z = job*4+b
// =====================================================================
#define PJ_SMEM (2*128*VKP*2 + 2*64*SKP*2)   // 71680 B

__global__ void __launch_bounds__(256, 2) proj_h9(Proj9 P, const float* __restrict__ s)
{
    extern __shared__ __half hsm[];
    __half* Ab = hsm;                     // [2][128][VKP]
    __half* Bb = hsm + 2 * 128 * VKP;     // [2][64][SKP]

    const int z = blockIdx.z, job = z >> 2, b = z & 3;
    const int o0 = blockIdx.y * BM;
    const int n0 = blockIdx.x * BN;
    const int tid = threadIdx.x;
    const int warp = tid >> 5, lane = tid & 31;
    const int g = lane >> 2, t = lane & 3;
    const int j = lane >> 3, r = lane & 7;
    const int wm = (warp & 1) * 64, wn = (warp >> 1) * 32;

    const __half* Xb   = P.X[job] + (size_t)b * CN;
    const __half* Wt   = P.W[job];
    const float*  bias = P.B[job];
    float*  dstf = P.D[job]  ? P.D[job]  + (size_t)b * CN : nullptr;
    __half* dsth = P.DH[job] ? P.DH[job] + (size_t)b * CN : nullptr;
    const int sidx = P.sidx[job];

    const int u = tid & 127;
    const bool isB = (tid >= 128);
    const int r0a = u >> 3, cca = u & 7;     // A: 16 rows/pass x 8 passes
    const int r0b = u >> 4, ccb = u & 15;    // B: 8 k-rows/pass x 8 passes

    auto prefetch = [&](int bufp, int k0) {
        if (!isB) {
#pragma unroll
            for (int p = 0; p < 8; p++) {
                int row = r0a + 16 * p;
                const __half* gp = Wt + (size_t)(o0 + row) * Cdim + k0 + cca * 8;
                __half* sp = Ab + ((size_t)bufp * 128 + row) * VKP + cca * 8;
                CP_ASYNC16(smem_cast(sp), gp);
            }
        } else {
#pragma unroll
            for (int p = 0; p < 8; p++) {
                int row = r0b + 8 * p;
                const __half* gp = Xb + (size_t)(k0 + row) * Ndim + n0 + ccb * 8;
                __half* sp = Bb + ((size_t)bufp * 64 + row) * SKP + ccb * 8;
                CP_ASYNC16(smem_cast(sp), gp);
            }
        }
        CP_COMMIT();
    };

    DECL_ACC;

    prefetch(0, 0);
    prefetch(1, 64);
    const int NIT = Cdim / 64;   // 4
    for (int it = 0; it < NIT; it++) {
        int buf = it & 1;
        if (it == NIT - 1) CP_WAIT0(); else CP_WAIT1();
        __syncthreads();
        const __half* At = Ab + (size_t)buf * 128 * VKP;
        const __half* Bt = Bb + (size_t)buf * 64 * SKP;
        F16_STEP_MKKN(At, Bt, wm, wn, j, r);
        __syncthreads();
        if (it + 2 < NIT) prefetch(buf, (it + 2) * 64);
    }

    const float scale = (sidx >= 0) ? s[sidx] : 1.f;
#pragma unroll
    for (int mi = 0; mi < 4; mi++)
#pragma unroll
        for (int r2 = 0; r2 < 2; r2++) {
            int m = o0 + wm + mi * 16 + g + r2 * 8;
            float bi = bias[m];
#pragma unroll
            for (int ni = 0; ni < 4; ni++) {
                int n = n0 + wn + ni * 8 + t * 2;
                size_t idx = (size_t)m * Ndim + n;
                float v0 = (acc[mi][ni][r2 * 2 + 0] + bi) * scale;
                float v1 = (acc[mi][ni][r2 * 2 + 1] + bi) * scale;
                if (dsth) {
                    *(__half2*)(dsth + idx) = __floats2half2_rn(v0, v1);
                } else {
                    dstf[idx]     = v0;
                    dstf[idx + 1] = v1;
                }
            }
        }
}

// =====================================================================
// ksum3: KS[a] = fp16(Ka + Kb)
// =====================================================================
__global__ void __launch_bounds__(256) ksum3_kernel(
    const float* __restrict__ K0, const float* __restrict__ K1,
    const float* __restrict__ K2,
    __half* __restrict__ S0, __half* __restrict__ S1, __half* __restrict__ S2)
{
    size_t i = ((size_t)blockIdx.x * 256 + threadIdx.x) * 4;
    float4 a = *(const float4*)(K0 + i);
    float4 b = *(const float4*)(K1 + i);
    float4 c = *(const float4*)(K2 + i);
    *(__half2*)(S0 + i)     = __floats2half2_rn(c.x + b.x, c.y + b.y);
    *(__half2*)(S0 + i + 2) = __floats2half2_rn(c.z + b.z, c.w + b.w);
    *(__half2*)(S1 + i)     = __floats2half2_rn(a.x + b.x, a.y + b.y);
    *(__half2*)(S1 + i + 2) = __floats2half2_rn(a.z + b.z, a.w + b.w);
    *(__half2*)(S2 + i)     = __floats2half2_rn(a.x + c.x, a.y + c.y);
    *(__half2*)(S2 + i + 2) = __floats2half2_rn(a.z + c.z, a.w + c.w);
}

// =====================================================================
// scores fp16 (R10 form): S = (1/16) Q^T KS. z = attend*4+b
// =====================================================================
#define SC_SMEM (2 * 2 * 64 * SKP * 2)   // 69632 B

__global__ void __launch_bounds__(256, 2) scores_h(Att3h A)
{
    extern __shared__ __half hsm[];
    __half* Ab = hsm;
    __half* Bb = hsm + 2 * 64 * SKP;

    const int z = blockIdx.z, a = z >> 2, b = z & 3;
    const int y0 = blockIdx.y * BM;
    const int z0 = blockIdx.x * BN;
    const int tid = threadIdx.x;
    const int warp = tid >> 5, lane = tid & 31;
    const int t = lane & 3;
    const int wm = (warp & 1) * 64, wn = (warp >> 1) * 32;
    const __half* Qb = A.Q[a]  + (size_t)b * CN;
    const __half* Kb = A.KS[a] + (size_t)b * CN;

    const int u  = tid & 127;
    const int r0 = u >> 4;
    const int cc = u & 15;
    const bool isB = (tid >= 128);
    const __half* gsrc = isB ? (Kb + z0) : (Qb + y0);
    __half* sbase = isB ? Bb : Ab;

    auto prefetch = [&](int bufp, int k0) {
#pragma unroll
        for (int p = 0; p < 8; p++) {
            int row = r0 + 8 * p;
            const __half* gp = gsrc + (size_t)(k0 + row) * Ndim + cc * 8;
            __half* sp = sbase + ((size_t)bufp * 64 + row) * SKP + cc * 8;
            CP_ASYNC16(smem_cast(sp), gp);
        }
        CP_COMMIT();
    };

    DECL_ACC;

    prefetch(0, 0);
    prefetch(1, 64);
    const int NIT = Cdim / 64;   // 4
    for (int it = 0; it < NIT; it++) {
        int buf = it & 1;
        if (it == NIT - 1) CP_WAIT0(); else CP_WAIT1();
        __syncthreads();
        const __half* At = Ab + (size_t)buf * 64 * SKP;
        const __half* Bt = Bb + (size_t)buf * 64 * SKP;
        const int j = lane >> 3, r = lane & 7;
#pragma unroll
        for (int ks = 0; ks < 64; ks += 16) {
            uint32_t af[4][4];
#pragma unroll
            for (int mi = 0; mi < 4; mi++) {
                int krow = ks + ((j & 2) ? 8 : 0) + r;
                int mo = wm + mi * 16 + ((j & 1) ? 8 : 0);
                ldsm4t(af[mi][0], af[mi][1], af[mi][2], af[mi][3],
                       smem_cast(At + (size_t)krow * SKP + mo));
            }
#pragma unroll
            for (int np = 0; np < 2; np++) {
                int krow = ks + ((j & 1) ? 8 : 0) + r;
                int no = wn + np * 16 + ((j & 2) ? 8 : 0);
                uint32_t b0, b1, b2, b3;
                ldsm4t(b0, b1, b2, b3, smem_cast(Bt + (size_t)krow * SKP + no));
                uint32_t bl[2] = { b0, b1 }, bh[2] = { b2, b3 };
#pragma unroll
                for (int mi = 0; mi < 4; mi++) {
                    mma_f16(acc[mi][np * 2 + 0], af[mi], bl);
                    mma_f16(acc[mi][np * 2 + 1], af[mi], bh);
                }
            }
        }
        __syncthreads();
        if (it + 2 < NIT) prefetch(buf, (it + 2) * 64);
    }

    __half* Sb = g_S3h + (size_t)z * NN;
    const int g = lane >> 2;
#pragma unroll
    for (int mi = 0; mi < 4; mi++)
#pragma unroll
        for (int r2 = 0; r2 < 2; r2++) {
            int y = y0 + wm + mi * 16 + g + r2 * 8;
#pragma unroll
            for (int ni = 0; ni < 4; ni++) {
                int zz = z0 + wn + ni * 8 + t * 2;
                size_t idx = (size_t)y * Ndim + zz;
                *(__half2*)(Sb + idx) = __floats2half2_rn(
                    acc[mi][ni][r2 * 2 + 0] * 0.0625f,
                    acc[mi][ni][r2 * 2 + 1] * 0.0625f);
            }
        }
}

// =====================================================================
// softmax fp16 in/out (one block per row)
// =====================================================================
__global__ void __launch_bounds__(256) softmax_kernel()
{
    const size_t row = blockIdx.x;
    __half* p = g_S3h + row * Ndim;
    const int tid = threadIdx.x;
    const int warp = tid >> 5, lane = tid & 31;
    __shared__ float red[8];

    float v[9];
#pragma unroll
    for (int i = 0; i < 9; i++) v[i] = __half2float(p[tid + i * 256]);

    float mx = v[0];
#pragma unroll
    for (int i = 1; i < 9; i++) mx = fmaxf(mx, v[i]);
#pragma unroll
    for (int off = 16; off > 0; off >>= 1)
        mx = fmaxf(mx, __shfl_xor_sync(0xffffffffu, mx, off));
    if (lane == 0) red[warp] = mx;
    __syncthreads();
    if (warp == 0) {
        float m2 = red[lane & 7];
#pragma unroll
        for (int off = 4; off > 0; off >>= 1)
            m2 = fmaxf(m2, __shfl_xor_sync(0xffffffffu, m2, off));
        if (lane == 0) red[0] = m2;
    }
    __syncthreads();
    mx = red[0];

    float sum = 0.f;
#pragma unroll
    for (int i = 0; i < 9; i++) { v[i] = __expf(v[i] - mx); sum += v[i]; }
#pragma unroll
    for (int off = 16; off > 0; off >>= 1)
        sum += __shfl_xor_sync(0xffffffffu, sum, off);
    __syncthreads();
    if (lane == 0) red[warp] = sum;
    __syncthreads();
    if (warp == 0) {
        float s2 = red[lane & 7];
#pragma unroll
        for (int off = 4; off > 0; off >>= 1)
            s2 += __shfl_xor_sync(0xffffffffu, s2, off);
        if (lane == 0) red[0] = s2;
    }
    __syncthreads();
    const float inv = 1.f / red[0];
#pragma unroll
    for (int i = 0; i < 9; i++) p[tid + i * 256] = __float2half_rn(v[i] * inv);
}

// =====================================================================
// AV fp16 (R10 form), now writes fp16 Wout. z = attend*4+b
// =====================================================================
#define AV_SMEM (2 * 2 * 128 * VKP * 2)  // 73728 B

__global__ void __launch_bounds__(256, 2) av_h(Att3h A)
{
    extern __shared__ __half hsm[];
    __half* Ab = hsm;
    __half* Bb = hsm + 2 * 128 * VKP;

    const int z = blockIdx.z, a = z >> 2, b = z & 3;
    const int c0 = blockIdx.y * BM;
    const int n0 = blockIdx.x * BN;
    const int tid = threadIdx.x;
    const int warp = tid >> 5, lane = tid & 31;
    const int t = lane & 3;
    const int wm = (warp & 1) * 64, wn = (warp >> 1) * 32;
    const __half* Vb = A.V[a] + (size_t)b * CN;
    const __half* Pb = g_S3h + (size_t)z * NN;
    __half*      dst = A.O[a] + (size_t)b * CN;

    const int u  = tid & 127;
    const int r0 = u >> 3;
    const int cc = u & 7;
    const bool isB = (tid >= 128);
    const __half* gsrc = isB ? (Pb + (size_t)n0 * Ndim) : (Vb + (size_t)c0 * Ndim);
    __half* sbase = isB ? Bb : Ab;

    auto prefetch = [&](int bufp, int k0) {
#pragma unroll
        for (int p = 0; p < 8; p++) {
            int row = r0 + 16 * p;
            const __half* gp = gsrc + (size_t)row * Ndim + k0 + cc * 8;
            __half* sp = sbase + ((size_t)bufp * 128 + row) * VKP + cc * 8;
            CP_ASYNC16(smem_cast(sp), gp);
        }
        CP_COMMIT();
    };

    DECL_ACC;

    prefetch(0, 0);
    prefetch(1, 64);
    const int NIT = Ndim / 64;   // 36
    for (int it = 0; it < NIT; it++) {
        int buf = it & 1;
        if (it == NIT - 1) CP_WAIT0(); else CP_WAIT1();
        __syncthreads();
        const __half* At = Ab + (size_t)buf * 128 * VKP;
        const __half* Bt = Bb + (size_t)buf * 128 * VKP;
        const int j = lane >> 3, r = lane & 7;
#pragma unroll
        for (int ks = 0; ks < 64; ks += 16) {
            uint32_t af[4][4];
#pragma unroll
            for (int mi = 0; mi < 4; mi++) {
                int mrow = wm + mi * 16 + ((j & 1) ? 8 : 0) + r;
                int ko = ks + ((j & 2) ? 8 : 0);
                ldsm4(af[mi][0], af[mi][1], af[mi][2], af[mi][3],
                      smem_cast(At + (size_t)mrow * VKP + ko));
            }
#pragma unroll
            for (int np = 0; np < 2; np++) {
                int nrow = wn + np * 16 + ((j & 2) ? 8 : 0) + r;
                int ko = ks + ((j & 1) ? 8 : 0);
                uint32_t b0, b1, b2, b3;
                ldsm4(b0, b1, b2, b3, smem_cast(Bt + (size_t)nrow * VKP + ko));
                uint32_t bl[2] = { b0, b1 }, bh[2] = { b2, b3 };
#pragma unroll
                for (int mi = 0; mi < 4; mi++) {
                    mma_f16(acc[mi][np * 2 + 0], af[mi], bl);
                    mma_f16(acc[mi][np * 2 + 1], af[mi], bh);
                }
            }
        }
        __syncthreads();
        if (it + 2 < NIT) prefetch(buf, (it + 2) * 64);
    }

    const int g = lane >> 2;
#pragma unroll
    for (int mi = 0; mi < 4; mi++)
#pragma unroll
        for (int r2 = 0; r2 < 2; r2++) {
            int c = c0 + wm + mi * 16 + g + r2 * 8;
#pragma unroll
            for (int ni = 0; ni < 4; ni++) {
                int n = n0 + wn + ni * 8 + t * 2;
                *(__half2*)(dst + (size_t)c * Ndim + n) = __floats2half2_rn(
                    acc[mi][ni][r2 * 2 + 0], acc[mi][ni][r2 * 2 + 1]);
            }
        }
}

// =====================================================================
// gate fp16: F[o][n] = sigmoid(sum_c Wg[o][c] X[c][n] + bg[o]) * X[o][n]
// A = Wg fp16 [m][k], B = X = Wout fp16 [k][n]. F fp32. z = m*4+b
// =====================================================================
__global__ void __launch_bounds__(256, 2) gate_h3(
    const __half* __restrict__ WgH, const float* __restrict__ bg)
{
    extern __shared__ __half hsm[];
    __half* Ab = hsm;                     // [2][128][VKP]
    __half* Bb = hsm + 2 * 128 * VKP;     // [2][64][SKP]

    const int z = blockIdx.z, a = z >> 2, b = z & 3;
    const int o0 = blockIdx.y * BM;
    const int n0 = blockIdx.x * BN;
    const int tid = threadIdx.x;
    const int warp = tid >> 5, lane = tid & 31;
    const int g = lane >> 2, t = lane & 3;
    const int jj = lane >> 3, rr = lane & 7;
    const int wm = (warp & 1) * 64, wn = (warp >> 1) * 32;
    const __half* Xb = g_Wh[a] + (size_t)b * CN;
    float*       F  = g_F3[a] + (size_t)b * CN;

    const int u = tid & 127;
    const bool isB = (tid >= 128);
    const int r0a = u >> 3, cca = u & 7;
    const int r0b = u >> 4, ccb = u & 15;

    auto prefetch = [&](int bufp, int k0) {
        if (!isB) {
#pragma unroll
            for (int p = 0; p < 8; p++) {
                int row = r0a + 16 * p;
                const __half* gp = WgH + (size_t)(o0 + row) * Cdim + k0 + cca * 8;
                __half* sp = Ab + ((size_t)bufp * 128 + row) * VKP + cca * 8;
                CP_ASYNC16(smem_cast(sp), gp);
            }
        } else {
#pragma unroll
            for (int p = 0; p < 8; p++) {
                int row = r0b + 8 * p;
                const __half* gp = Xb + (size_t)(k0 + row) * Ndim + n0 + ccb * 8;
                __half* sp = Bb + ((size_t)bufp * 64 + row) * SKP + ccb * 8;
                CP_ASYNC16(smem_cast(sp), gp);
            }
        }
        CP_COMMIT();
    };

    DECL_ACC;

    prefetch(0, 0);
    prefetch(1, 64);
    const int NIT = Cdim / 64;   // 4
    for (int it = 0; it < NIT; it++) {
        int buf = it & 1;
        if (it == NIT - 1) CP_WAIT0(); else CP_WAIT1();
        __syncthreads();
        const __half* At = Ab + (size_t)buf * 128 * VKP;
        const __half* Bt = Bb + (size_t)buf * 64 * SKP;
        F16_STEP_MKKN(At, Bt, wm, wn, jj, rr);
        __syncthreads();
        if (it + 2 < NIT) prefetch(buf, (it + 2) * 64);
    }

#pragma unroll
    for (int mi = 0; mi < 4; mi++)
#pragma unroll
        for (int r2 = 0; r2 < 2; r2++) {
            int o = o0 + wm + mi * 16 + g + r2 * 8;
            float bi = bg[o];
#pragma unroll
            for (int ni = 0; ni < 4; ni++) {
                int n = n0 + wn + ni * 8 + t * 2;
                size_t idx = (size_t)o * Ndim + n;
                __half2 xh = *(const __half2*)(Xb + idx);
                float x0 = __low2float(xh), x1 = __high2float(xh);
                float g0 = acc[mi][ni][r2 * 2 + 0] + bi;
                float g1 = acc[mi][ni][r2 * 2 + 1] + bi;
                F[idx]     = x0 / (1.f + __expf(-g0));
                F[idx + 1] = x1 / (1.f + __expf(-g1));
            }
        }
}

// =====================================================================
// final conv (tf32): out = Wo @ (F0+F1+F2) + bo (grid z = 4)
// =====================================================================
__device__ __forceinline__ void tile_mma_kk16(
    const float (*As)[BMP], const float (*Bs)[BMP],
    int wm, int wn, int g, int t, float acc[4][4][4])
{
#pragma unroll
    for (int ks = 0; ks < BK; ks += 8) {
        uint32_t af[4][4], bf[4][2];
#pragma unroll
        for (int mi = 0; mi < 4; mi++) {
            int m = wm + mi * 16 + g;
            af[mi][0] = __float_as_uint(As[ks + t][m]);
            af[mi][1] = __float_as_uint(As[ks + t][m + 8]);
            af[mi][2] = __float_as_uint(As[ks + t + 4][m]);
            af[mi][3] = __float_as_uint(As[ks + t + 4][m + 8]);
        }
#pragma unroll
        for (int ni = 0; ni < 4; ni++) {
            int n = wn + ni * 8 + g;
            bf[ni][0] = __float_as_uint(Bs[ks + t][n]);
            bf[ni][1] = __float_as_uint(Bs[ks + t + 4][n]);
        }
#pragma unroll
        for (int mi = 0; mi < 4; mi++)
#pragma unroll
            for (int ni = 0; ni < 4; ni++)
                mma_tf32(acc[mi][ni], af[mi], bf[ni]);
    }
}

__global__ void __launch_bounds__(256, 2) final_mma(
    const float* __restrict__ Wo, const float* __restrict__ bo,
    float* __restrict__ out)
{
    __shared__ float As[2][BK][BMP];
    __shared__ float Bs[2][BK][BMP];
    const int b  = blockIdx.z;
    const int o0 = blockIdx.y * BM;
    const int n0 = blockIdx.x * BN;
    const int tid = threadIdx.x;
    const int warp = tid >> 5, lane = tid & 31;
    const int g = lane >> 2, t = lane & 3;
    const int wm = (warp & 1) * 64, wn = (warp >> 1) * 32;
    const float* F0 = g_F3[0] + (size_t)b * CN;
    const float* F1 = g_F3[1] + (size_t)b * CN;
    const float* F2 = g_F3[2] + (size_t)b * CN;
    float* dst = out + (size_t)b * CN;

    const int arow = tid >> 1;
    const int akk0 = (tid & 1) * 8;
    const int bn4 = (tid & 31) * 4;
    const int bk0 = tid >> 5;

    DECL_ACC;

    float4 a_st[2], b_st[2];
    auto loadg = [&](int k0) {
#pragma unroll
        for (int r = 0; r < 2; r++)
            a_st[r] = *(const float4*)(Wo + (size_t)(o0 + arow) * Cdim + k0 + akk0 + r * 4);
#pragma unroll
        for (int r = 0; r < 2; r++) {
            size_t off = (size_t)(k0 + bk0 + r * 8) * Ndim + n0 + bn4;
            float4 v0 = *(const float4*)(F0 + off);
            float4 v1 = *(const float4*)(F1 + off);
            float4 v2 = *(const float4*)(F2 + off);
            v0.x += v1.x + v2.x; v0.y += v1.y + v2.y;
            v0.z += v1.z + v2.z; v0.w += v1.w + v2.w;
            b_st[r] = v0;
        }
    };
    auto storeg = [&](int buf) {
#pragma unroll
        for (int r = 0; r < 2; r++) {
            int kk = akk0 + r * 4;
            As[buf][kk + 0][arow] = f2tf32f(a_st[r].x);
            As[buf][kk + 1][arow] = f2tf32f(a_st[r].y);
            As[buf][kk + 2][arow] = f2tf32f(a_st[r].z);
            As[buf][kk + 3][arow] = f2tf32f(a_st[r].w);
        }
#pragma unroll
        for (int r = 0; r < 2; r++)
            *(float4*)(&Bs[buf][bk0 + r * 8][bn4]) = cvt4(b_st[r]);
    };

    loadg(0); storeg(0); __syncthreads();
    int buf = 0;
    for (int k0 = 0; k0 < Cdim; k0 += BK) {
        bool more = (k0 + BK) < Cdim;
        if (more) loadg(k0 + BK);
        tile_mma_kk16(As[buf], Bs[buf], wm, wn, g, t, acc);
        if (more) storeg(buf ^ 1);
        __syncthreads();
        buf ^= 1;
    }

#pragma unroll
    for (int mi = 0; mi < 4; mi++)
#pragma unroll
        for (int r2 = 0; r2 < 2; r2++) {
            int o = o0 + wm + mi * 16 + g + r2 * 8;
            float bi = bo[o];
#pragma unroll
            for (int ni = 0; ni < 4; ni++) {
                int n = n0 + wn + ni * 8 + t * 2;
                size_t idx = (size_t)o * Ndim + n;
                dst[idx]     = acc[mi][ni][r2 * 2 + 0] + bi;
                dst[idx + 1] = acc[mi][ni][r2 * 2 + 1] + bi;
            }
        }
}

// =====================================================================
// launch
// =====================================================================
extern "C" void kernel_launch(void* const* d_in, const int* in_sizes, int n_in,
                              void* d_out, int out_size)
{
    const float* x[3] = { (const float*)d_in[0], (const float*)d_in[1], (const float*)d_in[2] };
    const float* s = (const float*)d_in[3];
    const float *wq[3], *bq[3], *wk[3], *bk[3], *wv[3], *bv[3];
    for (int m = 0; m < 3; m++) {
        wq[m] = (const float*)d_in[4 + 6 * m];
        bq[m] = (const float*)d_in[5 + 6 * m];
        wk[m] = (const float*)d_in[6 + 6 * m];
        bk[m] = (const float*)d_in[7 + 6 * m];
        wv[m] = (const float*)d_in[8 + 6 * m];
        bv[m] = (const float*)d_in[9 + 6 * m];
    }
    const float* wg = (const float*)d_in[22];
    const float* bg = (const float*)d_in[23];
    const float* wo = (const float*)d_in[24];
    const float* bo = (const float*)d_in[25];
    float* out = (float*)d_out;

    float *gK;
    __half *gH, *gXh, *gWT, *gWh;
    cudaGetSymbolAddress((void**)&gK,  g_K);
    cudaGetSymbolAddress((void**)&gH,  g_H);
    cudaGetSymbolAddress((void**)&gXh, g_Xh);
    cudaGetSymbolAddress((void**)&gWT, g_WT);
    cudaGetSymbolAddress((void**)&gWh, g_Wh);

    float* Kf[3]; __half *Qh[3], *KSh[3], *Vh[3], *Xh[3], *Wout[3];
    for (int m = 0; m < 3; m++) {
        Kf[m]  = gK + (size_t)m * PLANE;
        Qh[m]  = gH + (size_t)(0 + m) * PLANE;
        KSh[m] = gH + (size_t)(3 + m) * PLANE;
        Vh[m]  = gH + (size_t)(6 + m) * PLANE;
        Xh[m]  = gXh + (size_t)m * PLANE;
        Wout[m] = gWh + (size_t)m * PLANE;
    }
    __half* WqH[3]; __half* WkH[3]; __half* WvH[3]; __half* WgH;
    for (int m = 0; m < 3; m++) {
        WqH[m] = gWT + (size_t)(3 * m + 0) * Cdim * Cdim;
        WkH[m] = gWT + (size_t)(3 * m + 1) * Cdim * Cdim;
        WvH[m] = gWT + (size_t)(3 * m + 2) * Cdim * Cdim;
    }
    WgH = gWT + (size_t)9 * Cdim * Cdim;

    W10 WC;
    for (int m = 0; m < 3; m++) {
        WC.src[3 * m + 0] = wq[m];
        WC.src[3 * m + 1] = wk[m];
        WC.src[3 * m + 2] = wv[m];
    }
    WC.src[9] = wg;

    Proj9 P;
    for (int m = 0; m < 3; m++) {
        P.X[3 * m + 0] = Xh[m]; P.W[3 * m + 0] = WqH[m]; P.B[3 * m + 0] = bq[m];
        P.D[3 * m + 0] = nullptr; P.DH[3 * m + 0] = Qh[m]; P.sidx[3 * m + 0] = m;
        P.X[3 * m + 1] = Xh[m]; P.W[3 * m + 1] = WkH[m]; P.B[3 * m + 1] = bk[m];
        P.D[3 * m + 1] = Kf[m]; P.DH[3 * m + 1] = nullptr; P.sidx[3 * m + 1] = m;
        P.X[3 * m + 2] = Xh[m]; P.W[3 * m + 2] = WvH[m]; P.B[3 * m + 2] = bv[m];
        P.D[3 * m + 2] = nullptr; P.DH[3 * m + 2] = Vh[m]; P.sidx[3 * m + 2] = -1;
    }

    // attends: w_rgb(Q0; K2+K1; V0), w_depth(Q2; K0+K1; V2), w_thermal(Q1; K0+K2; V1)
    Att3h A;
    const int qi[3] = { 0, 2, 1 };
    for (int a = 0; a < 3; a++) {
        A.Q[a]  = Qh[qi[a]];
        A.KS[a] = KSh[a];
        A.V[a]  = Vh[qi[a]];
        A.O[a]  = Wout[a];
    }

    cudaFuncSetAttribute(proj_h9,  cudaFuncAttributeMaxDynamicSharedMemorySize, PJ_SMEM);
    cudaFuncSetAttribute(scores_h, cudaFuncAttributeMaxDynamicSharedMemorySize, SC_SMEM);
    cudaFuncSetAttribute(av_h,     cudaFuncAttributeMaxDynamicSharedMemorySize, AV_SMEM);
    cudaFuncSetAttribute(gate_h3,  cudaFuncAttributeMaxDynamicSharedMemorySize, PJ_SMEM);

    dim3 blk(256);
    cvt_x3 <<<dim3(PLANE / 1024, 3), blk>>>(x[0], x[1], x[2], Xh[0], Xh[1], Xh[2]);
    cvt_w10<<<dim3(Cdim * Cdim / 1024, 10), blk>>>(WC, gWT);
    proj_h9<<<dim3(Ndim / BN, Cdim / BM, 36), blk, PJ_SMEM>>>(P, s);
    ksum3_kernel<<<dim3(PLANE / 1024), blk>>>(Kf[0], Kf[1], Kf[2], KSh[0], KSh[1], KSh[2]);
    scores_h<<<dim3(Ndim / BN, Ndim / BM, 12), blk, SC_SMEM>>>(A);
    softmax_kernel<<<dim3(3 * Bdim * Ndim), blk>>>();
    av_h   <<<dim3(Ndim / BN, Cdim / BM, 12), blk, AV_SMEM>>>(A);
    gate_h3<<<dim3(Ndim / BN, Cdim / BM, 12), blk, PJ_SMEM>>>(WgH, bg);
    final_mma<<<dim3(Ndim / BN, Cdim / BM, 4), blk>>>(wo, bo, out);
}

// round 12
// speedup vs baseline: 3.1033x; 1.0523x over previous
#include <cuda_runtime.h>
#include <cuda_fp16.h>
#include <cstdint>
#include <math.h>

#define Bdim 4
#define Cdim 256
#define Ndim 2304      // 48*48
#define PLANE (Bdim*Cdim*Ndim)
#define CN   (Cdim*Ndim)
#define NN   ((size_t)Ndim*Ndim)

#define BM 128
#define BN 128
#define SKP 136        // fp16 [k][*] stride (272B)
#define VKP 72         // fp16 [row][k] stride (144B)

// ---- scratch ----
__device__ __half g_Xh[3][PLANE];                    // fp16 inputs
__device__ __half g_WT[11][Cdim * Cdim];             // fp16 weights: wq0..2,wk0..2,wv0..2,wg,wo
__device__ float  g_K[3][PLANE];                     // raw fp32 K
__device__ __half g_H[9][PLANE];                     // Q0..2, KS0..2, V0..2
__device__ __half g_S3h[(size_t)3 * Bdim * NN];      // scores / probs (fp16)
__device__ __half g_Wh[3][PLANE];                    // attention outputs (fp16)
__device__ __half g_F3h[3][PLANE];                   // gated outputs (fp16)

// ---- fp16 mma + ldmatrix ----
__device__ __forceinline__ void mma_f16(float c[4], const uint32_t a[4], const uint32_t b[2]) {
    asm volatile(
        "mma.sync.aligned.m16n8k16.row.col.f32.f16.f16.f32 "
        "{%0,%1,%2,%3}, {%4,%5,%6,%7}, {%8,%9}, {%0,%1,%2,%3};"
        : "+f"(c[0]), "+f"(c[1]), "+f"(c[2]), "+f"(c[3])
        : "r"(a[0]), "r"(a[1]), "r"(a[2]), "r"(a[3]), "r"(b[0]), "r"(b[1]));
}
__device__ __forceinline__ void ldsm4(uint32_t& r0, uint32_t& r1, uint32_t& r2, uint32_t& r3, uint32_t a) {
    asm volatile("ldmatrix.sync.aligned.m8n8.x4.shared.b16 {%0,%1,%2,%3}, [%4];"
        : "=r"(r0), "=r"(r1), "=r"(r2), "=r"(r3) : "r"(a));
}
__device__ __forceinline__ void ldsm4t(uint32_t& r0, uint32_t& r1, uint32_t& r2, uint32_t& r3, uint32_t a) {
    asm volatile("ldmatrix.sync.aligned.m8n8.x4.trans.shared.b16 {%0,%1,%2,%3}, [%4];"
        : "=r"(r0), "=r"(r1), "=r"(r2), "=r"(r3) : "r"(a));
}

// ---- cp.async ----
__device__ __forceinline__ uint32_t smem_cast(const void* p) {
    return (uint32_t)__cvta_generic_to_shared(p);
}
#define CP_ASYNC16(dst_u32, gptr) \
    asm volatile("cp.async.cg.shared.global [%0], [%1], 16;" :: "r"(dst_u32), "l"(gptr))
#define CP_COMMIT() asm volatile("cp.async.commit_group;" ::: "memory")
#define CP_WAIT1()  asm volatile("cp.async.wait_group 1;" ::: "memory")
#define CP_WAIT0()  asm volatile("cp.async.wait_group 0;" ::: "memory")

#define DECL_ACC float acc[4][4][4]; \
    _Pragma("unroll") for (int mi = 0; mi < 4; mi++) \
    _Pragma("unroll") for (int ni = 0; ni < 4; ni++) \
    _Pragma("unroll") for (int r = 0; r < 4; r++) acc[mi][ni][r] = 0.f;

// fp16 GEMM inner step: A [m][k] stride VKP (ldsm), B [k][n] stride SKP (ldsm.trans)
#define F16_STEP_MKKN(At, Bt, wm, wn, j, r) \
    _Pragma("unroll") \
    for (int ks = 0; ks < 64; ks += 16) { \
        uint32_t af[4][4]; \
        _Pragma("unroll") \
        for (int mi = 0; mi < 4; mi++) { \
            int mrow = (wm) + mi * 16 + (((j) & 1) ? 8 : 0) + (r); \
            int ko = ks + (((j) & 2) ? 8 : 0); \
            ldsm4(af[mi][0], af[mi][1], af[mi][2], af[mi][3], \
                  smem_cast((At) + (size_t)mrow * VKP + ko)); \
        } \
        _Pragma("unroll") \
        for (int np = 0; np < 2; np++) { \
            int krow = ks + (((j) & 1) ? 8 : 0) + (r); \
            int no = (wn) + np * 16 + (((j) & 2) ? 8 : 0); \
            uint32_t b0, b1, b2, b3; \
            ldsm4t(b0, b1, b2, b3, smem_cast((Bt) + (size_t)krow * SKP + no)); \
            uint32_t bl[2] = { b0, b1 }, bh[2] = { b2, b3 }; \
            _Pragma("unroll") \
            for (int mi = 0; mi < 4; mi++) { \
                mma_f16(acc[mi][np * 2 + 0], af[mi], bl); \
                mma_f16(acc[mi][np * 2 + 1], af[mi], bh); \
            } \
        } \
    }

// ---- arg structs ----
struct Proj9 {
    const __half* X[9]; const __half* W[9]; const float* B[9];
    float* D[9]; __half* DH[9]; int sidx[9];
};
struct Att3h {
    const __half* Q[3]; const __half* KS[3]; const __half* V[3]; __half* O[3];
};

// =====================================================================
// cvt kernels
// =====================================================================
__global__ void __launch_bounds__(256) cvt_x3(
    const float* __restrict__ x0, const float* __restrict__ x1,
    const float* __restrict__ x2,
    __half* __restrict__ d0, __half* __restrict__ d1, __half* __restrict__ d2)
{
    const float* src = (blockIdx.y == 0) ? x0 : (blockIdx.y == 1) ? x1 : x2;
    __half* dst      = (blockIdx.y == 0) ? d0 : (blockIdx.y == 1) ? d1 : d2;
    size_t i = ((size_t)blockIdx.x * 256 + threadIdx.x) * 4;
    float4 v = *(const float4*)(src + i);
    *(__half2*)(dst + i)     = __floats2half2_rn(v.x, v.y);
    *(__half2*)(dst + i + 2) = __floats2half2_rn(v.z, v.w);
}

struct W11 { const float* src[11]; };
__global__ void __launch_bounds__(256) cvt_w11(W11 W, __half* __restrict__ base)
{
    const float* src = W.src[blockIdx.y];
    __half* dst = base + (size_t)blockIdx.y * Cdim * Cdim;
    size_t i = ((size_t)blockIdx.x * 256 + threadIdx.x) * 4;
    float4 v = *(const float4*)(src + i);
    *(__half2*)(dst + i)     = __floats2half2_rn(v.x, v.y);
    *(__half2*)(dst + i + 2) = __floats2half2_rn(v.z, v.w);
}

// =====================================================================
// proj fp16: dst[o][n] = scale*(sum_c W[o][c] X[c][n] + bias[o])
// =====================================================================
#define PJ_SMEM (2*128*VKP*2 + 2*64*SKP*2)   // 71680 B

__global__ void __launch_bounds__(256, 2) proj_h9(Proj9 P, const float* __restrict__ s)
{
    extern __shared__ __half hsm[];
    __half* Ab = hsm;                     // [2][128][VKP]
    __half* Bb = hsm + 2 * 128 * VKP;     // [2][64][SKP]

    const int z = blockIdx.z, job = z >> 2, b = z & 3;
    const int o0 = blockIdx.y * BM;
    const int n0 = blockIdx.x * BN;
    const int tid = threadIdx.x;
    const int warp = tid >> 5, lane = tid & 31;
    const int g = lane >> 2, t = lane & 3;
    const int j = lane >> 3, r = lane & 7;
    const int wm = (warp & 1) * 64, wn = (warp >> 1) * 32;

    const __half* Xb   = P.X[job] + (size_t)b * CN;
    const __half* Wt   = P.W[job];
    const float*  bias = P.B[job];
    float*  dstf = P.D[job]  ? P.D[job]  + (size_t)b * CN : nullptr;
    __half* dsth = P.DH[job] ? P.DH[job] + (size_t)b * CN : nullptr;
    const int sidx = P.sidx[job];

    const int u = tid & 127;
    const bool isB = (tid >= 128);
    const int r0a = u >> 3, cca = u & 7;
    const int r0b = u >> 4, ccb = u & 15;

    auto prefetch = [&](int bufp, int k0) {
        if (!isB) {
#pragma unroll
            for (int p = 0; p < 8; p++) {
                int row = r0a + 16 * p;
                const __half* gp = Wt + (size_t)(o0 + row) * Cdim + k0 + cca * 8;
                __half* sp = Ab + ((size_t)bufp * 128 + row) * VKP + cca * 8;
                CP_ASYNC16(smem_cast(sp), gp);
            }
        } else {
#pragma unroll
            for (int p = 0; p < 8; p++) {
                int row = r0b + 8 * p;
                const __half* gp = Xb + (size_t)(k0 + row) * Ndim + n0 + ccb * 8;
                __half* sp = Bb + ((size_t)bufp * 64 + row) * SKP + ccb * 8;
                CP_ASYNC16(smem_cast(sp), gp);
            }
        }
        CP_COMMIT();
    };

    DECL_ACC;

    prefetch(0, 0);
    prefetch(1, 64);
    const int NIT = Cdim / 64;   // 4
    for (int it = 0; it < NIT; it++) {
        int buf = it & 1;
        if (it == NIT - 1) CP_WAIT0(); else CP_WAIT1();
        __syncthreads();
        const __half* At = Ab + (size_t)buf * 128 * VKP;
        const __half* Bt = Bb + (size_t)buf * 64 * SKP;
        F16_STEP_MKKN(At, Bt, wm, wn, j, r);
        __syncthreads();
        if (it + 2 < NIT) prefetch(buf, (it + 2) * 64);
    }

    const float scale = (sidx >= 0) ? s[sidx] : 1.f;
#pragma unroll
    for (int mi = 0; mi < 4; mi++)
#pragma unroll
        for (int r2 = 0; r2 < 2; r2++) {
            int m = o0 + wm + mi * 16 + g + r2 * 8;
            float bi = bias[m];
#pragma unroll
            for (int ni = 0; ni < 4; ni++) {
                int n = n0 + wn + ni * 8 + t * 2;
                size_t idx = (size_t)m * Ndim + n;
                float v0 = (acc[mi][ni][r2 * 2 + 0] + bi) * scale;
                float v1 = (acc[mi][ni][r2 * 2 + 1] + bi) * scale;
                if (dsth) {
                    *(__half2*)(dsth + idx) = __floats2half2_rn(v0, v1);
                } else {
                    dstf[idx]     = v0;
                    dstf[idx + 1] = v1;
                }
            }
        }
}

// =====================================================================
// ksum3: KS[a] = fp16(Ka + Kb)
// =====================================================================
__global__ void __launch_bounds__(256) ksum3_kernel(
    const float* __restrict__ K0, const float* __restrict__ K1,
    const float* __restrict__ K2,
    __half* __restrict__ S0, __half* __restrict__ S1, __half* __restrict__ S2)
{
    size_t i = ((size_t)blockIdx.x * 256 + threadIdx.x) * 4;
    float4 a = *(const float4*)(K0 + i);
    float4 b = *(const float4*)(K1 + i);
    float4 c = *(const float4*)(K2 + i);
    *(__half2*)(S0 + i)     = __floats2half2_rn(c.x + b.x, c.y + b.y);
    *(__half2*)(S0 + i + 2) = __floats2half2_rn(c.z + b.z, c.w + b.w);
    *(__half2*)(S1 + i)     = __floats2half2_rn(a.x + b.x, a.y + b.y);
    *(__half2*)(S1 + i + 2) = __floats2half2_rn(a.z + b.z, a.w + b.w);
    *(__half2*)(S2 + i)     = __floats2half2_rn(a.x + c.x, a.y + c.y);
    *(__half2*)(S2 + i + 2) = __floats2half2_rn(a.z + c.z, a.w + c.w);
}

// =====================================================================
// scores fp16: S = (1/16) Q^T KS. z = attend*4+b
// =====================================================================
#define SC_SMEM (2 * 2 * 64 * SKP * 2)   // 69632 B

__global__ void __launch_bounds__(256, 2) scores_h(Att3h A)
{
    extern __shared__ __half hsm[];
    __half* Ab = hsm;
    __half* Bb = hsm + 2 * 64 * SKP;

    const int z = blockIdx.z, a = z >> 2, b = z & 3;
    const int y0 = blockIdx.y * BM;
    const int z0 = blockIdx.x * BN;
    const int tid = threadIdx.x;
    const int warp = tid >> 5, lane = tid & 31;
    const int t = lane & 3;
    const int wm = (warp & 1) * 64, wn = (warp >> 1) * 32;
    const __half* Qb = A.Q[a]  + (size_t)b * CN;
    const __half* Kb = A.KS[a] + (size_t)b * CN;

    const int u  = tid & 127;
    const int r0 = u >> 4;
    const int cc = u & 15;
    const bool isB = (tid >= 128);
    const __half* gsrc = isB ? (Kb + z0) : (Qb + y0);
    __half* sbase = isB ? Bb : Ab;

    auto prefetch = [&](int bufp, int k0) {
#pragma unroll
        for (int p = 0; p < 8; p++) {
            int row = r0 + 8 * p;
            const __half* gp = gsrc + (size_t)(k0 + row) * Ndim + cc * 8;
            __half* sp = sbase + ((size_t)bufp * 64 + row) * SKP + cc * 8;
            CP_ASYNC16(smem_cast(sp), gp);
        }
        CP_COMMIT();
    };

    DECL_ACC;

    prefetch(0, 0);
    prefetch(1, 64);
    const int NIT = Cdim / 64;   // 4
    for (int it = 0; it < NIT; it++) {
        int buf = it & 1;
        if (it == NIT - 1) CP_WAIT0(); else CP_WAIT1();
        __syncthreads();
        const __half* At = Ab + (size_t)buf * 64 * SKP;
        const __half* Bt = Bb + (size_t)buf * 64 * SKP;
        const int j = lane >> 3, r = lane & 7;
#pragma unroll
        for (int ks = 0; ks < 64; ks += 16) {
            uint32_t af[4][4];
#pragma unroll
            for (int mi = 0; mi < 4; mi++) {
                int krow = ks + ((j & 2) ? 8 : 0) + r;
                int mo = wm + mi * 16 + ((j & 1) ? 8 : 0);
                ldsm4t(af[mi][0], af[mi][1], af[mi][2], af[mi][3],
                       smem_cast(At + (size_t)krow * SKP + mo));
            }
#pragma unroll
            for (int np = 0; np < 2; np++) {
                int krow = ks + ((j & 1) ? 8 : 0) + r;
                int no = wn + np * 16 + ((j & 2) ? 8 : 0);
                uint32_t b0, b1, b2, b3;
                ldsm4t(b0, b1, b2, b3, smem_cast(Bt + (size_t)krow * SKP + no));
                uint32_t bl[2] = { b0, b1 }, bh[2] = { b2, b3 };
#pragma unroll
                for (int mi = 0; mi < 4; mi++) {
                    mma_f16(acc[mi][np * 2 + 0], af[mi], bl);
                    mma_f16(acc[mi][np * 2 + 1], af[mi], bh);
                }
            }
        }
        __syncthreads();
        if (it + 2 < NIT) prefetch(buf, (it + 2) * 64);
    }

    __half* Sb = g_S3h + (size_t)z * NN;
    const int g = lane >> 2;
#pragma unroll
    for (int mi = 0; mi < 4; mi++)
#pragma unroll
        for (int r2 = 0; r2 < 2; r2++) {
            int y = y0 + wm + mi * 16 + g + r2 * 8;
#pragma unroll
            for (int ni = 0; ni < 4; ni++) {
                int zz = z0 + wn + ni * 8 + t * 2;
                size_t idx = (size_t)y * Ndim + zz;
                *(__half2*)(Sb + idx) = __floats2half2_rn(
                    acc[mi][ni][r2 * 2 + 0] * 0.0625f,
                    acc[mi][ni][r2 * 2 + 1] * 0.0625f);
            }
        }
}

// =====================================================================
// softmax: 2 rows per 256-thread block, half2 I/O
// =====================================================================
__global__ void __launch_bounds__(256) softmax_kernel()
{
    const int sub = threadIdx.x >> 7;          // 0/1: which row
    const size_t row = (size_t)blockIdx.x * 2 + sub;
    __half2* p = (__half2*)(g_S3h + row * Ndim);
    const int t = threadIdx.x & 127;
    const int warp = threadIdx.x >> 5, lane = threadIdx.x & 31;
    __shared__ float redm[8], reds[8];

    float2 v[9];
#pragma unroll
    for (int i = 0; i < 9; i++) v[i] = __half22float2(p[t + i * 128]);

    float mx = fmaxf(v[0].x, v[0].y);
#pragma unroll
    for (int i = 1; i < 9; i++) mx = fmaxf(mx, fmaxf(v[i].x, v[i].y));
#pragma unroll
    for (int off = 16; off > 0; off >>= 1)
        mx = fmaxf(mx, __shfl_xor_sync(0xffffffffu, mx, off));
    if (lane == 0) redm[warp] = mx;
    __syncthreads();
    {
        int base = sub * 4;
        mx = fmaxf(fmaxf(redm[base], redm[base + 1]),
                   fmaxf(redm[base + 2], redm[base + 3]));
    }

    float sum = 0.f;
#pragma unroll
    for (int i = 0; i < 9; i++) {
        v[i].x = __expf(v[i].x - mx);
        v[i].y = __expf(v[i].y - mx);
        sum += v[i].x + v[i].y;
    }
#pragma unroll
    for (int off = 16; off > 0; off >>= 1)
        sum += __shfl_xor_sync(0xffffffffu, sum, off);
    if (lane == 0) reds[warp] = sum;
    __syncthreads();
    float inv;
    {
        int base = sub * 4;
        inv = 1.f / (reds[base] + reds[base + 1] + reds[base + 2] + reds[base + 3]);
    }
#pragma unroll
    for (int i = 0; i < 9; i++)
        p[t + i * 128] = __floats2half2_rn(v[i].x * inv, v[i].y * inv);
}

// =====================================================================
// AV fp16: dst[c][n] = sum_m V[c][m] P[n][m], writes fp16 Wout
// =====================================================================
#define AV_SMEM (2 * 2 * 128 * VKP * 2)  // 73728 B

__global__ void __launch_bounds__(256, 2) av_h(Att3h A)
{
    extern __shared__ __half hsm[];
    __half* Ab = hsm;
    __half* Bb = hsm + 2 * 128 * VKP;

    const int z = blockIdx.z, a = z >> 2, b = z & 3;
    const int c0 = blockIdx.y * BM;
    const int n0 = blockIdx.x * BN;
    const int tid = threadIdx.x;
    const int warp = tid >> 5, lane = tid & 31;
    const int t = lane & 3;
    const int wm = (warp & 1) * 64, wn = (warp >> 1) * 32;
    const __half* Vb = A.V[a] + (size_t)b * CN;
    const __half* Pb = g_S3h + (size_t)z * NN;
    __half*      dst = A.O[a] + (size_t)b * CN;

    const int u  = tid & 127;
    const int r0 = u >> 3;
    const int cc = u & 7;
    const bool isB = (tid >= 128);
    const __half* gsrc = isB ? (Pb + (size_t)n0 * Ndim) : (Vb + (size_t)c0 * Ndim);
    __half* sbase = isB ? Bb : Ab;

    auto prefetch = [&](int bufp, int k0) {
#pragma unroll
        for (int p = 0; p < 8; p++) {
            int row = r0 + 16 * p;
            const __half* gp = gsrc + (size_t)row * Ndim + k0 + cc * 8;
            __half* sp = sbase + ((size_t)bufp * 128 + row) * VKP + cc * 8;
            CP_ASYNC16(smem_cast(sp), gp);
        }
        CP_COMMIT();
    };

    DECL_ACC;

    prefetch(0, 0);
    prefetch(1, 64);
    const int NIT = Ndim / 64;   // 36
    for (int it = 0; it < NIT; it++) {
        int buf = it & 1;
        if (it == NIT - 1) CP_WAIT0(); else CP_WAIT1();
        __syncthreads();
        const __half* At = Ab + (size_t)buf * 128 * VKP;
        const __half* Bt = Bb + (size_t)buf * 128 * VKP;
        const int j = lane >> 3, r = lane & 7;
#pragma unroll
        for (int ks = 0; ks < 64; ks += 16) {
            uint32_t af[4][4];
#pragma unroll
            for (int mi = 0; mi < 4; mi++) {
                int mrow = wm + mi * 16 + ((j & 1) ? 8 : 0) + r;
                int ko = ks + ((j & 2) ? 8 : 0);
                ldsm4(af[mi][0], af[mi][1], af[mi][2], af[mi][3],
                      smem_cast(At + (size_t)mrow * VKP + ko));
            }
#pragma unroll
            for (int np = 0; np < 2; np++) {
                int nrow = wn + np * 16 + ((j & 2) ? 8 : 0) + r;
                int ko = ks + ((j & 1) ? 8 : 0);
                uint32_t b0, b1, b2, b3;
                ldsm4(b0, b1, b2, b3, smem_cast(Bt + (size_t)nrow * VKP + ko));
                uint32_t bl[2] = { b0, b1 }, bh[2] = { b2, b3 };
#pragma unroll
                for (int mi = 0; mi < 4; mi++) {
                    mma_f16(acc[mi][np * 2 + 0], af[mi], bl);
                    mma_f16(acc[mi][np * 2 + 1], af[mi], bh);
                }
            }
        }
        __syncthreads();
        if (it + 2 < NIT) prefetch(buf, (it + 2) * 64);
    }

    const int g = lane >> 2;
#pragma unroll
    for (int mi = 0; mi < 4; mi++)
#pragma unroll
        for (int r2 = 0; r2 < 2; r2++) {
            int c = c0 + wm + mi * 16 + g + r2 * 8;
#pragma unroll
            for (int ni = 0; ni < 4; ni++) {
                int n = n0 + wn + ni * 8 + t * 2;
                *(__half2*)(dst + (size_t)c * Ndim + n) = __floats2half2_rn(
                    acc[mi][ni][r2 * 2 + 0], acc[mi][ni][r2 * 2 + 1]);
            }
        }
}

// =====================================================================
// gate fp16: F[o][n] = sigmoid(conv) * X[o][n], F stored fp16
// =====================================================================
__global__ void __launch_bounds__(256, 2) gate_h3(
    const __half* __restrict__ WgH, const float* __restrict__ bg)
{
    extern __shared__ __half hsm[];
    __half* Ab = hsm;                     // [2][128][VKP]
    __half* Bb = hsm + 2 * 128 * VKP;     // [2][64][SKP]

    const int z = blockIdx.z, a = z >> 2, b = z & 3;
    const int o0 = blockIdx.y * BM;
    const int n0 = blockIdx.x * BN;
    const int tid = threadIdx.x;
    const int warp = tid >> 5, lane = tid & 31;
    const int g = lane >> 2, t = lane & 3;
    const int jj = lane >> 3, rr = lane & 7;
    const int wm = (warp & 1) * 64, wn = (warp >> 1) * 32;
    const __half* Xb = g_Wh[a] + (size_t)b * CN;
    __half*      F  = g_F3h[a] + (size_t)b * CN;

    const int u = tid & 127;
    const bool isB = (tid >= 128);
    const int r0a = u >> 3, cca = u & 7;
    const int r0b = u >> 4, ccb = u & 15;

    auto prefetch = [&](int bufp, int k0) {
        if (!isB) {
#pragma unroll
            for (int p = 0; p < 8; p++) {
                int row = r0a + 16 * p;
                const __half* gp = WgH + (size_t)(o0 + row) * Cdim + k0 + cca * 8;
                __half* sp = Ab + ((size_t)bufp * 128 + row) * VKP + cca * 8;
                CP_ASYNC16(smem_cast(sp), gp);
            }
        } else {
#pragma unroll
            for (int p = 0; p < 8; p++) {
                int row = r0b + 8 * p;
                const __half* gp = Xb + (size_t)(k0 + row) * Ndim + n0 + ccb * 8;
                __half* sp = Bb + ((size_t)bufp * 64 + row) * SKP + ccb * 8;
                CP_ASYNC16(smem_cast(sp), gp);
            }
        }
        CP_COMMIT();
    };

    DECL_ACC;

    prefetch(0, 0);
    prefetch(1, 64);
    const int NIT = Cdim / 64;   // 4
    for (int it = 0; it < NIT; it++) {
        int buf = it & 1;
        if (it == NIT - 1) CP_WAIT0(); else CP_WAIT1();
        __syncthreads();
        const __half* At = Ab + (size_t)buf * 128 * VKP;
        const __half* Bt = Bb + (size_t)buf * 64 * SKP;
        F16_STEP_MKKN(At, Bt, wm, wn, jj, rr);
        __syncthreads();
        if (it + 2 < NIT) prefetch(buf, (it + 2) * 64);
    }

#pragma unroll
    for (int mi = 0; mi < 4; mi++)
#pragma unroll
        for (int r2 = 0; r2 < 2; r2++) {
            int o = o0 + wm + mi * 16 + g + r2 * 8;
            float bi = bg[o];
#pragma unroll
            for (int ni = 0; ni < 4; ni++) {
                int n = n0 + wn + ni * 8 + t * 2;
                size_t idx = (size_t)o * Ndim + n;
                __half2 xh = *(const __half2*)(Xb + idx);
                float x0 = __low2float(xh), x1 = __high2float(xh);
                float g0 = acc[mi][ni][r2 * 2 + 0] + bi;
                float g1 = acc[mi][ni][r2 * 2 + 1] + bi;
                *(__half2*)(F + idx) = __floats2half2_rn(
                    x0 / (1.f + __expf(-g0)),
                    x1 / (1.f + __expf(-g1)));
            }
        }
}

// =====================================================================
// final fp16: out = WoH @ (F0+F1+F2) + bo  (fp32 sum in B loader)
// A via cp.async, B manual double-buffered regs. grid z = 4
// =====================================================================
#define FN_SMEM (2*128*VKP*2 + 2*64*SKP*2)   // 71680 B

__global__ void __launch_bounds__(256, 2) final_h(
    const __half* __restrict__ WoH, const float* __restrict__ bo,
    float* __restrict__ out)
{
    extern __shared__ __half hsm[];
    __half* Ab = hsm;                     // [2][128][VKP]
    __half* Bb = hsm + 2 * 128 * VKP;     // [2][64][SKP]

    const int b  = blockIdx.z;
    const int o0 = blockIdx.y * BM;
    const int n0 = blockIdx.x * BN;
    const int tid = threadIdx.x;
    const int warp = tid >> 5, lane = tid & 31;
    const int g = lane >> 2, t = lane & 3;
    const int jj = lane >> 3, rr = lane & 7;
    const int wm = (warp & 1) * 64, wn = (warp >> 1) * 32;
    const __half* F0 = g_F3h[0] + (size_t)b * CN;
    const __half* F1 = g_F3h[1] + (size_t)b * CN;
    const __half* F2 = g_F3h[2] + (size_t)b * CN;
    float* dst = out + (size_t)b * CN;

    const int u = tid & 127;
    const bool isB = (tid >= 128);
    const int r0a = u >> 3, cca = u & 7;
    const int r0b = u >> 4, ccb = u & 15;

    auto prefetchA = [&](int bufp, int k0) {
        if (!isB) {
#pragma unroll
            for (int p = 0; p < 8; p++) {
                int row = r0a + 16 * p;
                const __half* gp = WoH + (size_t)(o0 + row) * Cdim + k0 + cca * 8;
                __half* sp = Ab + ((size_t)bufp * 128 + row) * VKP + cca * 8;
                CP_ASYNC16(smem_cast(sp), gp);
            }
        }
        CP_COMMIT();
    };

    __half2 breg[8][4];
    auto loadB = [&](int k0) {
        if (isB) {
#pragma unroll
            for (int p = 0; p < 8; p++) {
                int row = r0b + 8 * p;
                size_t off = (size_t)(k0 + row) * Ndim + n0 + ccb * 8;
#pragma unroll
                for (int c = 0; c < 4; c++) {
                    float2 a0 = __half22float2(*(const __half2*)(F0 + off + c * 2));
                    float2 a1 = __half22float2(*(const __half2*)(F1 + off + c * 2));
                    float2 a2 = __half22float2(*(const __half2*)(F2 + off + c * 2));
                    breg[p][c] = __floats2half2_rn(a0.x + a1.x + a2.x,
                                                   a0.y + a1.y + a2.y);
                }
            }
        }
    };
    auto storeB = [&](int bufp) {
        if (isB) {
#pragma unroll
            for (int p = 0; p < 8; p++) {
                int row = r0b + 8 * p;
                __half2* sp = (__half2*)(Bb + ((size_t)bufp * 64 + row) * SKP + ccb * 8);
#pragma unroll
                for (int c = 0; c < 4; c++) sp[c] = breg[p][c];
            }
        }
    };

    DECL_ACC;

    prefetchA(0, 0);
    prefetchA(1, 64);
    loadB(0); storeB(0);
    loadB(64);
    const int NIT = Cdim / 64;   // 4
    for (int it = 0; it < NIT; it++) {
        int buf = it & 1;
        if (it == NIT - 1) CP_WAIT0(); else CP_WAIT1();
        __syncthreads();
        const __half* At = Ab + (size_t)buf * 128 * VKP;
        const __half* Bt = Bb + (size_t)buf * 64 * SKP;
        F16_STEP_MKKN(At, Bt, wm, wn, jj, rr);
        __syncthreads();
        if (it + 2 < NIT) prefetchA(buf, (it + 2) * 64);
        if (it + 1 < NIT) storeB(buf ^ 1);        // regs loaded for iter it+1
        if (it + 2 < NIT) loadB((it + 2) * 64);
    }

#pragma unroll
    for (int mi = 0; mi < 4; mi++)
#pragma unroll
        for (int r2 = 0; r2 < 2; r2++) {
            int o = o0 + wm + mi * 16 + g + r2 * 8;
            float bi = bo[o];
#pragma unroll
            for (int ni = 0; ni < 4; ni++) {
                int n = n0 + wn + ni * 8 + t * 2;
                size_t idx = (size_t)o * Ndim + n;
                float2 v = { acc[mi][ni][r2 * 2 + 0] + bi,
                             acc[mi][ni][r2 * 2 + 1] + bi };
                *(float2*)(dst + idx) = v;
            }
        }
}

// =====================================================================
// launch
// =====================================================================
extern "C" void kernel_launch(void* const* d_in, const int* in_sizes, int n_in,
                              void* d_out, int out_size)
{
    const float* x[3] = { (const float*)d_in[0], (const float*)d_in[1], (const float*)d_in[2] };
    const float* s = (const float*)d_in[3];
    const float *wq[3], *bq[3], *wk[3], *bk[3], *wv[3], *bv[3];
    for (int m = 0; m < 3; m++) {
        wq[m] = (const float*)d_in[4 + 6 * m];
        bq[m] = (const float*)d_in[5 + 6 * m];
        wk[m] = (const float*)d_in[6 + 6 * m];
        bk[m] = (const float*)d_in[7 + 6 * m];
        wv[m] = (const float*)d_in[8 + 6 * m];
        bv[m] = (const float*)d_in[9 + 6 * m];
    }
    const float* wg = (const float*)d_in[22];
    const float* bg = (const float*)d_in[23];
    const float* wo = (const float*)d_in[24];
    const float* bo = (const float*)d_in[25];
    float* out = (float*)d_out;

    float *gK;
    __half *gH, *gXh, *gWT, *gWh;
    cudaGetSymbolAddress((void**)&gK,  g_K);
    cudaGetSymbolAddress((void**)&gH,  g_H);
    cudaGetSymbolAddress((void**)&gXh, g_Xh);
    cudaGetSymbolAddress((void**)&gWT, g_WT);
    cudaGetSymbolAddress((void**)&gWh, g_Wh);

    float* Kf[3]; __half *Qh[3], *KSh[3], *Vh[3], *Xh[3], *Wout[3];
    for (int m = 0; m < 3; m++) {
        Kf[m]  = gK + (size_t)m * PLANE;
        Qh[m]  = gH + (size_t)(0 + m) * PLANE;
        KSh[m] = gH + (size_t)(3 + m) * PLANE;
        Vh[m]  = gH + (size_t)(6 + m) * PLANE;
        Xh[m]  = gXh + (size_t)m * PLANE;
        Wout[m] = gWh + (size_t)m * PLANE;
    }
    __half* WqH[3]; __half* WkH[3]; __half* WvH[3];
    for (int m = 0; m < 3; m++) {
        WqH[m] = gWT + (size_t)(3 * m + 0) * Cdim * Cdim;
        WkH[m] = gWT + (size_t)(3 * m + 1) * Cdim * Cdim;
        WvH[m] = gWT + (size_t)(3 * m + 2) * Cdim * Cdim;
    }
    __half* WgH = gWT + (size_t)9 * Cdim * Cdim;
    __half* WoH = gWT + (size_t)10 * Cdim * Cdim;

    W11 WC;
    for (int m = 0; m < 3; m++) {
        WC.src[3 * m + 0] = wq[m];
        WC.src[3 * m + 1] = wk[m];
        WC.src[3 * m + 2] = wv[m];
    }
    WC.src[9]  = wg;
    WC.src[10] = wo;

    Proj9 P;
    for (int m = 0; m < 3; m++) {
        P.X[3 * m + 0] = Xh[m]; P.W[3 * m + 0] = WqH[m]; P.B[3 * m + 0] = bq[m];
        P.D[3 * m + 0] = nullptr; P.DH[3 * m + 0] = Qh[m]; P.sidx[3 * m + 0] = m;
        P.X[3 * m + 1] = Xh[m]; P.W[3 * m + 1] = WkH[m]; P.B[3 * m + 1] = bk[m];
        P.D[3 * m + 1] = Kf[m]; P.DH[3 * m + 1] = nullptr; P.sidx[3 * m + 1] = m;
        P.X[3 * m + 2] = Xh[m]; P.W[3 * m + 2] = WvH[m]; P.B[3 * m + 2] = bv[m];
        P.D[3 * m + 2] = nullptr; P.DH[3 * m + 2] = Vh[m]; P.sidx[3 * m + 2] = -1;
    }

    // attends: w_rgb(Q0; K2+K1; V0), w_depth(Q2; K0+K1; V2), w_thermal(Q1; K0+K2; V1)
    Att3h A;
    const int qi[3] = { 0, 2, 1 };
    for (int a = 0; a < 3; a++) {
        A.Q[a]  = Qh[qi[a]];
        A.KS[a] = KSh[a];
        A.V[a]  = Vh[qi[a]];
        A.O[a]  = Wout[a];
    }

    cudaFuncSetAttribute(proj_h9,  cudaFuncAttributeMaxDynamicSharedMemorySize, PJ_SMEM);
    cudaFuncSetAttribute(scores_h, cudaFuncAttributeMaxDynamicSharedMemorySize, SC_SMEM);
    cudaFuncSetAttribute(av_h,     cudaFuncAttributeMaxDynamicSharedMemorySize, AV_SMEM);
    cudaFuncSetAttribute(gate_h3,  cudaFuncAttributeMaxDynamicSharedMemorySize, PJ_SMEM);
    cudaFuncSetAttribute(final_h,  cudaFuncAttributeMaxDynamicSharedMemorySize, FN_SMEM);

    dim3 blk(256);
    cvt_x3 <<<dim3(PLANE / 1024, 3), blk>>>(x[0], x[1], x[2], Xh[0], Xh[1], Xh[2]);
    cvt_w11<<<dim3(Cdim * Cdim / 1024, 11), blk>>>(WC, gWT);
    proj_h9<<<dim3(Ndim / BN, Cdim / BM, 36), blk, PJ_SMEM>>>(P, s);
    ksum3_kernel<<<dim3(PLANE / 1024), blk>>>(Kf[0], Kf[1], Kf[2], KSh[0], KSh[1], KSh[2]);
    scores_h<<<dim3(Ndim / BN, Ndim / BM, 12), blk, SC_SMEM>>>(A);
    softmax_kernel<<<dim3(3 * Bdim * Ndim / 2), blk>>>();
    av_h   <<<dim3(Ndim / BN, Cdim / BM, 12), blk, AV_SMEM>>>(A);
    gate_h3<<<dim3(Ndim / BN, Cdim / BM, 12), blk, PJ_SMEM>>>(WgH, bg);
    final_h<<<dim3(Ndim / BN, Cdim / BM, 4), blk, FN_SMEM>>>(WoH, bo, out);
}